// round 1
// baseline (speedup 1.0000x reference)
#include <cuda_runtime.h>
#include <cuda_bf16.h>
#include <math.h>

// ---------------- problem constants ----------------
#define NN   4096
#define INF_ 512
#define DD   256
#define LL   2
#define HH   8
#define DH   32
#define FF_  1024
#define HALF_ 128

// ---------------- scratch (device global, no allocs) ----------------
// h0, h, qkv, attn, tmp, ff, hc
#define OFF_H0   0
#define OFF_H    (OFF_H0 + NN*DD)
#define OFF_QKV  (OFF_H  + NN*DD)
#define OFF_ATTN (OFF_QKV + NN*3*DD)
#define OFF_TMP  (OFF_ATTN + NN*DD)
#define OFF_FF   (OFF_TMP + NN*DD)
#define OFF_HC   (OFF_FF + NN*FF_)
#define SCRATCH_FLOATS (OFF_HC + NN*DD)

__device__ float g_scratch[SCRATCH_FLOATS];

// ---------------- generic SGEMM: C = A@B + bias, optional ReLU ----------------
// BM=128, BN=128, BK=16, TM=TN=8, 256 threads. Requires M%128==0, N%128==0, K%16==0.
__global__ __launch_bounds__(256) void sgemm_kernel(
    int M, int N, int K,
    const float* __restrict__ A, const float* __restrict__ B,
    const float* __restrict__ bias, float* __restrict__ C, int act)
{
    __shared__ float As[16][132];   // padded, transposed [k][m]
    __shared__ float Bs[16][128];

    const int tid = threadIdx.x;
    const int bx = blockIdx.x, by = blockIdx.y;
    const int trow = tid >> 4;      // 0..15
    const int tcol = tid & 15;      // 0..15

    A += (size_t)by * 128 * K;
    B += (size_t)bx * 128;
    C += (size_t)by * 128 * N + (size_t)bx * 128;
    bias += (size_t)bx * 128;

    float acc[8][8];
    #pragma unroll
    for (int i = 0; i < 8; i++)
        #pragma unroll
        for (int j = 0; j < 8; j++) acc[i][j] = 0.f;

    float ra[8], rb[8];

    for (int kt = 0; kt < K; kt += 16) {
        // load A tile 128x16 (transposed into As)
        #pragma unroll
        for (int i = 0; i < 2; i++) {
            int f = tid + i * 256;           // float4 id 0..511
            int r = f >> 2;                  // 0..127
            int c4 = f & 3;                  // 0..3
            float4 v = *reinterpret_cast<const float4*>(A + (size_t)r * K + kt + c4 * 4);
            As[c4*4+0][r] = v.x; As[c4*4+1][r] = v.y;
            As[c4*4+2][r] = v.z; As[c4*4+3][r] = v.w;
        }
        // load B tile 16x128
        #pragma unroll
        for (int i = 0; i < 2; i++) {
            int f = tid + i * 256;
            int r = f >> 5;                  // 0..15
            int c4 = f & 31;                 // 0..31
            *reinterpret_cast<float4*>(&Bs[r][c4*4]) =
                *reinterpret_cast<const float4*>(B + (size_t)(kt + r) * N + c4 * 4);
        }
        __syncthreads();
        #pragma unroll
        for (int k = 0; k < 16; k++) {
            #pragma unroll
            for (int i = 0; i < 8; i++) ra[i] = As[k][trow*8 + i];
            #pragma unroll
            for (int j = 0; j < 8; j++) rb[j] = Bs[k][tcol*8 + j];
            #pragma unroll
            for (int i = 0; i < 8; i++)
                #pragma unroll
                for (int j = 0; j < 8; j++) acc[i][j] += ra[i] * rb[j];
        }
        __syncthreads();
    }

    #pragma unroll
    for (int i = 0; i < 8; i++) {
        int r = trow*8 + i;
        #pragma unroll
        for (int j = 0; j < 8; j += 4) {
            int c = tcol*8 + j;
            float4 v;
            v.x = acc[i][j+0] + bias[c+0];
            v.y = acc[i][j+1] + bias[c+1];
            v.z = acc[i][j+2] + bias[c+2];
            v.w = acc[i][j+3] + bias[c+3];
            if (act == 1) {
                v.x = fmaxf(v.x, 0.f); v.y = fmaxf(v.y, 0.f);
                v.z = fmaxf(v.z, 0.f); v.w = fmaxf(v.w, 0.f);
            }
            *reinterpret_cast<float4*>(C + (size_t)r * N + c) = v;
        }
    }
}

// ---------------- fused flash attention ----------------
// grid (NN/64, HH), 256 threads (16x16). Q block 64 rows, iterate KV in 64-blocks.
// qkv layout [N, 3D]; q at col h*32+d, k at 256+..., v at 512+...
__global__ __launch_bounds__(256) void attn_kernel(
    const float* __restrict__ qkv, float* __restrict__ out)
{
    __shared__ float Qs[64][33];
    __shared__ float Ks[64][33];
    __shared__ float Vs[64][33];
    __shared__ float Ps[64][65];

    const int h = blockIdx.y;
    const int qb = blockIdx.x * 64;
    const int tid = threadIdx.x;
    const int trow = tid >> 4;   // 0..15 : owns rows trow*4..+3
    const int tcol = tid & 15;   // 0..15 : owns S cols tcol*4..+3, O cols tcol*2..+1
    const float scale = 0.17677669529663687f;   // 1/sqrt(32)

    // load Q block
    #pragma unroll
    for (int i = 0; i < 8; i++) {
        int f = tid + i * 256;
        int r = f >> 5, c = f & 31;
        Qs[r][c] = qkv[(size_t)(qb + r) * 768 + h * 32 + c];
    }

    float m[4], l[4], o[4][2];
    #pragma unroll
    for (int i = 0; i < 4; i++) {
        m[i] = -1e30f; l[i] = 0.f;
        o[i][0] = 0.f; o[i][1] = 0.f;
    }

    for (int kb = 0; kb < NN; kb += 64) {
        __syncthreads();  // protect Ks/Vs/Ps from previous iter
        #pragma unroll
        for (int i = 0; i < 8; i++) {
            int f = tid + i * 256;
            int r = f >> 5, c = f & 31;
            Ks[r][c] = qkv[(size_t)(kb + r) * 768 + 256 + h * 32 + c];
            Vs[r][c] = qkv[(size_t)(kb + r) * 768 + 512 + h * 32 + c];
        }
        __syncthreads();

        // S = Q @ K^T (64x64 tile), thread computes 4x4
        float s[4][4];
        #pragma unroll
        for (int i = 0; i < 4; i++)
            #pragma unroll
            for (int j = 0; j < 4; j++) s[i][j] = 0.f;
        #pragma unroll 8
        for (int d = 0; d < 32; d++) {
            float qa[4], kk[4];
            #pragma unroll
            for (int i = 0; i < 4; i++) qa[i] = Qs[trow*4 + i][d];
            #pragma unroll
            for (int j = 0; j < 4; j++) kk[j] = Ks[tcol*4 + j][d];
            #pragma unroll
            for (int i = 0; i < 4; i++)
                #pragma unroll
                for (int j = 0; j < 4; j++) s[i][j] += qa[i] * kk[j];
        }

        // online softmax
        float alpha[4];
        #pragma unroll
        for (int i = 0; i < 4; i++) {
            float rmax = -1e30f;
            #pragma unroll
            for (int j = 0; j < 4; j++) { s[i][j] *= scale; rmax = fmaxf(rmax, s[i][j]); }
            rmax = fmaxf(rmax, __shfl_xor_sync(0xffffffffu, rmax, 1));
            rmax = fmaxf(rmax, __shfl_xor_sync(0xffffffffu, rmax, 2));
            rmax = fmaxf(rmax, __shfl_xor_sync(0xffffffffu, rmax, 4));
            rmax = fmaxf(rmax, __shfl_xor_sync(0xffffffffu, rmax, 8));
            float mnew = fmaxf(m[i], rmax);
            float rsum = 0.f;
            #pragma unroll
            for (int j = 0; j < 4; j++) {
                float p = expf(s[i][j] - mnew);
                Ps[trow*4 + i][tcol*4 + j] = p;
                rsum += p;
            }
            rsum += __shfl_xor_sync(0xffffffffu, rsum, 1);
            rsum += __shfl_xor_sync(0xffffffffu, rsum, 2);
            rsum += __shfl_xor_sync(0xffffffffu, rsum, 4);
            rsum += __shfl_xor_sync(0xffffffffu, rsum, 8);
            alpha[i] = expf(m[i] - mnew);
            l[i] = l[i] * alpha[i] + rsum;
            m[i] = mnew;
            o[i][0] *= alpha[i];
            o[i][1] *= alpha[i];
        }
        __syncthreads();   // Ps fully written

        // O += P @ V  (rows trow*4..+3, cols tcol*2..+1)
        #pragma unroll 8
        for (int j = 0; j < 64; j++) {
            float v0 = Vs[j][tcol*2 + 0];
            float v1 = Vs[j][tcol*2 + 1];
            #pragma unroll
            for (int i = 0; i < 4; i++) {
                float p = Ps[trow*4 + i][j];
                o[i][0] += p * v0;
                o[i][1] += p * v1;
            }
        }
    }

    #pragma unroll
    for (int i = 0; i < 4; i++) {
        float inv = 1.f / l[i];
        int n = qb + trow*4 + i;
        out[(size_t)n * 256 + h * 32 + tcol*2 + 0] = o[i][0] * inv;
        out[(size_t)n * 256 + h * 32 + tcol*2 + 1] = o[i][1] * inv;
    }
}

// ---------------- fused residual-add + LayerNorm ----------------
// one block per row (256 threads, D=256)
__global__ __launch_bounds__(256) void add_ln_kernel(
    const float* __restrict__ x, const float* __restrict__ y,
    const float* __restrict__ g, const float* __restrict__ b,
    float* __restrict__ out)
{
    __shared__ float red[256];
    __shared__ float s_mean, s_rstd;
    int row = blockIdx.x, c = threadIdx.x;
    float v = x[(size_t)row*256 + c] + y[(size_t)row*256 + c];
    red[c] = v; __syncthreads();
    for (int s = 128; s > 0; s >>= 1) { if (c < s) red[c] += red[c + s]; __syncthreads(); }
    if (c == 0) s_mean = red[0] * (1.f/256.f);
    __syncthreads();
    float dv = v - s_mean;
    red[c] = dv * dv; __syncthreads();
    for (int s = 128; s > 0; s >>= 1) { if (c < s) red[c] += red[c + s]; __syncthreads(); }
    if (c == 0) s_rstd = rsqrtf(red[0] * (1.f/256.f) + 1e-5f);
    __syncthreads();
    out[(size_t)row*256 + c] = dv * s_rstd * g[c] + b[c];
}

// ---------------- h_combined = h + h0, also write to d_out tail ----------------
__global__ __launch_bounds__(256) void hc_kernel(
    const float* __restrict__ h, const float* __restrict__ h0,
    float* __restrict__ hc, float* __restrict__ out_tail)
{
    int idx = blockIdx.x * 256 + threadIdx.x;
    float v = h[idx] + h0[idx];
    hc[idx] = v;
    out_tail[idx] = v;
}

// ---------------- fused edge predictor ----------------
// per block: 128 edges. A[e][k] = hc[src[e]][k]*hc[dst[e]][k]*w[e]
// y = leaky(A @ Wp1 + bp1, 0.2);  out[e] = y @ Wp2 + bp2
__global__ __launch_bounds__(256) void edge_kernel(
    const float* __restrict__ hc,
    const int* __restrict__ src, const int* __restrict__ dst,
    const float* __restrict__ w,
    const float* __restrict__ Wp1, const float* __restrict__ bp1,
    const float* __restrict__ Wp2, const float* __restrict__ bp2,
    float* __restrict__ out, int E)
{
    __shared__ float As[128][36];    // [e][k], padded (BK=32 + 4)
    __shared__ float Ws[32][128];    // [k][j]
    __shared__ int   sSrc[128], sDst[128];
    __shared__ float sW[128], sWp2[128];

    const int tid = threadIdx.x;
    const int e0 = blockIdx.x * 128;

    if (tid < 128) {
        int e = e0 + tid;
        if (e < E) { sSrc[tid] = src[e]; sDst[tid] = dst[e]; sW[tid] = w[e]; }
        else       { sSrc[tid] = 0;      sDst[tid] = 0;      sW[tid] = 0.f; }
        sWp2[tid] = Wp2[tid];
    }
    __syncthreads();

    const int trow = tid >> 4;  // 0..15: rows trow*8..+7
    const int tcol = tid & 15;  // 0..15: cols tcol*8..+7

    float acc[8][8];
    #pragma unroll
    for (int i = 0; i < 8; i++)
        #pragma unroll
        for (int j = 0; j < 8; j++) acc[i][j] = 0.f;
    float ra[8], rb[8];

    for (int kt = 0; kt < 256; kt += 32) {
        __syncthreads();  // protect As/Ws from previous compute
        // load A tile: 128 edges x 32 k (gather + multiply), 4 float4 per thread
        #pragma unroll
        for (int i = 0; i < 4; i++) {
            int f = tid + i * 256;           // 0..1023
            int e = f >> 3;                  // 0..127
            int k4 = f & 7;                  // 0..7 -> k = kt + k4*4
            float4 a = *reinterpret_cast<const float4*>(hc + (size_t)sSrc[e]*256 + kt + k4*4);
            float4 b = *reinterpret_cast<const float4*>(hc + (size_t)sDst[e]*256 + kt + k4*4);
            float ww = sW[e];
            float4 r;
            r.x = a.x*b.x*ww; r.y = a.y*b.y*ww; r.z = a.z*b.z*ww; r.w = a.w*b.w*ww;
            *reinterpret_cast<float4*>(&As[e][k4*4]) = r;
        }
        // load Wp1 tile: 32 x 128
        #pragma unroll
        for (int i = 0; i < 4; i++) {
            int f = tid + i * 256;
            int r = f >> 5;                  // 0..31
            int c4 = f & 31;
            *reinterpret_cast<float4*>(&Ws[r][c4*4]) =
                *reinterpret_cast<const float4*>(Wp1 + (size_t)(kt + r) * 128 + c4*4);
        }
        __syncthreads();
        #pragma unroll
        for (int k = 0; k < 32; k++) {
            #pragma unroll
            for (int i = 0; i < 8; i++) ra[i] = As[trow*8 + i][k];
            #pragma unroll
            for (int j = 0; j < 8; j++) rb[j] = Ws[k][tcol*8 + j];
            #pragma unroll
            for (int i = 0; i < 8; i++)
                #pragma unroll
                for (int j = 0; j < 8; j++) acc[i][j] += ra[i] * rb[j];
        }
    }

    // second layer: leaky-relu then dot with Wp2, reduce across tcol group
    float bp2v = bp2[0];
    #pragma unroll
    for (int i = 0; i < 8; i++) {
        float p = 0.f;
        #pragma unroll
        for (int j = 0; j < 8; j++) {
            float y = acc[i][j] + bp1[tcol*8 + j];
            y = (y > 0.f) ? y : 0.2f * y;
            p += y * sWp2[tcol*8 + j];
        }
        p += __shfl_xor_sync(0xffffffffu, p, 1);
        p += __shfl_xor_sync(0xffffffffu, p, 2);
        p += __shfl_xor_sync(0xffffffffu, p, 4);
        p += __shfl_xor_sync(0xffffffffu, p, 8);
        if (tcol == 0) {
            int e = e0 + trow*8 + i;
            if (e < E) out[e] = p + bp2v;
        }
    }
}

// ---------------- host orchestration ----------------
extern "C" void kernel_launch(void* const* d_in, const int* in_sizes, int n_in,
                              void* d_out, int out_size)
{
    const float* x        = (const float*)d_in[0];
    const int*   pos_src  = (const int*)  d_in[1];
    const int*   pos_dst  = (const int*)  d_in[2];
    const float* pos_w    = (const float*)d_in[3];
    const int*   neg_src  = (const int*)  d_in[4];
    const int*   neg_dst  = (const int*)  d_in[5];
    const float* neg_w    = (const float*)d_in[6];
    const float* Wi       = (const float*)d_in[7];
    const float* bi       = (const float*)d_in[8];
    const float* Wqkv     = (const float*)d_in[9];
    const float* bqkv     = (const float*)d_in[10];
    const float* Wo       = (const float*)d_in[11];
    const float* bo       = (const float*)d_in[12];
    const float* g1       = (const float*)d_in[13];
    const float* be1      = (const float*)d_in[14];
    const float* g2       = (const float*)d_in[15];
    const float* be2      = (const float*)d_in[16];
    const float* W1       = (const float*)d_in[17];
    const float* b1       = (const float*)d_in[18];
    const float* W2       = (const float*)d_in[19];
    const float* b2       = (const float*)d_in[20];
    const float* Wp1      = (const float*)d_in[21];
    const float* bp1      = (const float*)d_in[22];
    const float* Wp2      = (const float*)d_in[23];
    const float* bp2      = (const float*)d_in[24];

    const int E = in_sizes[1];   // 500000

    float* S = nullptr;
    cudaGetSymbolAddress((void**)&S, g_scratch);
    float* h0   = S + OFF_H0;
    float* h    = S + OFF_H;
    float* qkv  = S + OFF_QKV;
    float* attn = S + OFF_ATTN;
    float* tmp  = S + OFF_TMP;
    float* ff   = S + OFF_FF;
    float* hc   = S + OFF_HC;
    float* out  = (float*)d_out;

    // h0 = x @ Wi + bi
    sgemm_kernel<<<dim3(DD/128, NN/128), 256>>>(NN, DD, INF_, x, Wi, bi, h0, 0);

    for (int l = 0; l < LL; l++) {
        const float* hin = (l == 0) ? h0 : h;
        // qkv = hin @ Wqkv[l] + bqkv[l]
        sgemm_kernel<<<dim3(768/128, NN/128), 256>>>(NN, 768, DD,
            hin, Wqkv + (size_t)l*DD*768, bqkv + (size_t)l*768, qkv, 0);
        // attention
        attn_kernel<<<dim3(NN/64, HH), 256>>>(qkv, attn);
        // o-proj
        sgemm_kernel<<<dim3(DD/128, NN/128), 256>>>(NN, DD, DD,
            attn, Wo + (size_t)l*DD*DD, bo + (size_t)l*DD, tmp, 0);
        // h = LN(hin + tmp)
        add_ln_kernel<<<NN, 256>>>(hin, tmp, g1 + (size_t)l*DD, be1 + (size_t)l*DD, h);
        // ff = relu(h @ W1 + b1)
        sgemm_kernel<<<dim3(FF_/128, NN/128), 256>>>(NN, FF_, DD,
            h, W1 + (size_t)l*DD*FF_, b1 + (size_t)l*FF_, ff, 1);
        // tmp = ff @ W2 + b2
        sgemm_kernel<<<dim3(DD/128, NN/128), 256>>>(NN, DD, FF_,
            ff, W2 + (size_t)l*FF_*DD, b2 + (size_t)l*DD, tmp, 0);
        // h = LN(h + tmp)
        add_ln_kernel<<<NN, 256>>>(h, tmp, g2 + (size_t)l*DD, be2 + (size_t)l*DD, h);
    }

    // h_combined = h + h0, also write to d_out[2E ..)
    hc_kernel<<<NN*DD/256, 256>>>(h, h0, hc, out + 2*(size_t)E);

    // edge predictions
    int eblocks = (E + 127) / 128;
    edge_kernel<<<eblocks, 256>>>(hc, pos_src, pos_dst, pos_w, Wp1, bp1, Wp2, bp2, out, E);
    edge_kernel<<<eblocks, 256>>>(hc, neg_src, neg_dst, neg_w, Wp1, bp1, Wp2, bp2, out + E, E);
}

// round 2
// speedup vs baseline: 1.4923x; 1.4923x over previous
#include <cuda_runtime.h>
#include <cuda_bf16.h>
#include <math.h>

// ---------------- problem constants ----------------
#define NN   4096
#define INF_ 512
#define DD   256
#define LL   2
#define HH   8
#define DH   32
#define FF_  1024
#define HALF_ 128

// ---------------- scratch (device global, no allocs) ----------------
#define OFF_H0   0
#define OFF_H    (OFF_H0 + NN*DD)
#define OFF_QKV  (OFF_H  + NN*DD)
#define OFF_ATTN (OFF_QKV + NN*3*DD)
#define OFF_TMP  (OFF_ATTN + NN*DD)
#define OFF_FF   (OFF_TMP + NN*DD)
#define OFF_HC   (OFF_FF + NN*FF_)
#define SCRATCH_FLOATS (OFF_HC + NN*DD)

__device__ float g_scratch[SCRATCH_FLOATS];

// ---------------- TF32 helpers ----------------
__device__ __forceinline__ float f2tf32(float x) {
    unsigned r;
    asm("cvt.rna.tf32.f32 %0, %1;" : "=r"(r) : "f"(x));
    return __uint_as_float(r);
}

__device__ __forceinline__ void mma_tf32(float* d, const float* a, const float* b) {
    asm("mma.sync.aligned.m16n8k8.row.col.f32.tf32.tf32.f32 "
        "{%0,%1,%2,%3},{%4,%5,%6,%7},{%8,%9},{%0,%1,%2,%3};"
        : "+f"(d[0]), "+f"(d[1]), "+f"(d[2]), "+f"(d[3])
        : "r"(__float_as_uint(a[0])), "r"(__float_as_uint(a[1])),
          "r"(__float_as_uint(a[2])), "r"(__float_as_uint(a[3])),
          "r"(__float_as_uint(b[0])), "r"(__float_as_uint(b[1])));
}

// ---------------- TF32 tensor-core SGEMM ----------------
// C = A@B + bias, optional ReLU. BM=128, BN=64, BK=32. 256 threads = 8 warps (4m x 2n),
// warp tile 32x32 (2 m-tiles x 4 n-tiles of m16n8k8).
// Requires M%128==0, N%64==0, K%32==0.
__global__ __launch_bounds__(256) void sgemm_tc_kernel(
    int M, int N, int K,
    const float* __restrict__ A, const float* __restrict__ B,
    const float* __restrict__ bias, float* __restrict__ C, int act)
{
    __shared__ float As[128][36];   // [m][k], pad 36 -> conflict-free frag loads
    __shared__ float Bs[32][68];    // [k][n], pad 68

    const int tid  = threadIdx.x;
    const int lane = tid & 31;
    const int wid  = tid >> 5;
    const int wm   = wid >> 1;      // 0..3
    const int wn   = wid & 1;       // 0..1
    const int grp  = lane >> 2;     // 0..7
    const int tig  = lane & 3;      // 0..3

    const int bx = blockIdx.x, by = blockIdx.y;
    A += (size_t)by * 128 * K;
    B += (size_t)bx * 64;
    C += (size_t)by * 128 * N + (size_t)bx * 64;
    bias += (size_t)bx * 64;

    float acc[2][4][4];
    #pragma unroll
    for (int mt = 0; mt < 2; mt++)
        #pragma unroll
        for (int nt = 0; nt < 4; nt++)
            #pragma unroll
            for (int i = 0; i < 4; i++) acc[mt][nt][i] = 0.f;

    for (int kt = 0; kt < K; kt += 32) {
        // A tile 128x32: 4 float4 per thread
        #pragma unroll
        for (int i = 0; i < 4; i++) {
            int f  = tid + i * 256;
            int r  = f >> 3;
            int c4 = f & 7;
            float4 v = *reinterpret_cast<const float4*>(A + (size_t)r * K + kt + c4 * 4);
            As[r][c4*4+0] = f2tf32(v.x); As[r][c4*4+1] = f2tf32(v.y);
            As[r][c4*4+2] = f2tf32(v.z); As[r][c4*4+3] = f2tf32(v.w);
        }
        // B tile 32x64: 2 float4 per thread
        #pragma unroll
        for (int i = 0; i < 2; i++) {
            int f  = tid + i * 256;
            int r  = f >> 4;
            int c4 = f & 15;
            float4 v = *reinterpret_cast<const float4*>(B + (size_t)(kt + r) * N + c4 * 4);
            Bs[r][c4*4+0] = f2tf32(v.x); Bs[r][c4*4+1] = f2tf32(v.y);
            Bs[r][c4*4+2] = f2tf32(v.z); Bs[r][c4*4+3] = f2tf32(v.w);
        }
        __syncthreads();

        #pragma unroll
        for (int ks = 0; ks < 4; ks++) {
            int k0 = ks * 8 + tig;
            float a[2][4], b[4][2];
            #pragma unroll
            for (int mt = 0; mt < 2; mt++) {
                int row = wm * 32 + mt * 16 + grp;
                a[mt][0] = As[row  ][k0  ];
                a[mt][1] = As[row+8][k0  ];
                a[mt][2] = As[row  ][k0+4];
                a[mt][3] = As[row+8][k0+4];
            }
            #pragma unroll
            for (int nt = 0; nt < 4; nt++) {
                int col = wn * 32 + nt * 8 + grp;
                b[nt][0] = Bs[ks*8 + tig    ][col];
                b[nt][1] = Bs[ks*8 + tig + 4][col];
            }
            #pragma unroll
            for (int mt = 0; mt < 2; mt++)
                #pragma unroll
                for (int nt = 0; nt < 4; nt++)
                    mma_tf32(acc[mt][nt], a[mt], b[nt]);
        }
        __syncthreads();
    }

    // epilogue
    #pragma unroll
    for (int mt = 0; mt < 2; mt++) {
        #pragma unroll
        for (int nt = 0; nt < 4; nt++) {
            int row = wm * 32 + mt * 16 + grp;
            int col = wn * 32 + nt * 8 + tig * 2;
            float b0 = bias[col], b1 = bias[col+1];
            float2 v0, v1;
            v0.x = acc[mt][nt][0] + b0; v0.y = acc[mt][nt][1] + b1;
            v1.x = acc[mt][nt][2] + b0; v1.y = acc[mt][nt][3] + b1;
            if (act == 1) {
                v0.x = fmaxf(v0.x, 0.f); v0.y = fmaxf(v0.y, 0.f);
                v1.x = fmaxf(v1.x, 0.f); v1.y = fmaxf(v1.y, 0.f);
            }
            *reinterpret_cast<float2*>(C + (size_t)row * N + col)     = v0;
            *reinterpret_cast<float2*>(C + (size_t)(row+8) * N + col) = v1;
        }
    }
}

// ---------------- fused flash attention (fp32, unchanged) ----------------
__global__ __launch_bounds__(256) void attn_kernel(
    const float* __restrict__ qkv, float* __restrict__ out)
{
    __shared__ float Qs[64][33];
    __shared__ float Ks[64][33];
    __shared__ float Vs[64][33];
    __shared__ float Ps[64][65];

    const int h = blockIdx.y;
    const int qb = blockIdx.x * 64;
    const int tid = threadIdx.x;
    const int trow = tid >> 4;
    const int tcol = tid & 15;
    const float scale = 0.17677669529663687f;

    #pragma unroll
    for (int i = 0; i < 8; i++) {
        int f = tid + i * 256;
        int r = f >> 5, c = f & 31;
        Qs[r][c] = qkv[(size_t)(qb + r) * 768 + h * 32 + c];
    }

    float m[4], l[4], o[4][2];
    #pragma unroll
    for (int i = 0; i < 4; i++) {
        m[i] = -1e30f; l[i] = 0.f;
        o[i][0] = 0.f; o[i][1] = 0.f;
    }

    for (int kb = 0; kb < NN; kb += 64) {
        __syncthreads();
        #pragma unroll
        for (int i = 0; i < 8; i++) {
            int f = tid + i * 256;
            int r = f >> 5, c = f & 31;
            Ks[r][c] = qkv[(size_t)(kb + r) * 768 + 256 + h * 32 + c];
            Vs[r][c] = qkv[(size_t)(kb + r) * 768 + 512 + h * 32 + c];
        }
        __syncthreads();

        float s[4][4];
        #pragma unroll
        for (int i = 0; i < 4; i++)
            #pragma unroll
            for (int j = 0; j < 4; j++) s[i][j] = 0.f;
        #pragma unroll 8
        for (int d = 0; d < 32; d++) {
            float qa[4], kk[4];
            #pragma unroll
            for (int i = 0; i < 4; i++) qa[i] = Qs[trow*4 + i][d];
            #pragma unroll
            for (int j = 0; j < 4; j++) kk[j] = Ks[tcol*4 + j][d];
            #pragma unroll
            for (int i = 0; i < 4; i++)
                #pragma unroll
                for (int j = 0; j < 4; j++) s[i][j] += qa[i] * kk[j];
        }

        float alpha[4];
        #pragma unroll
        for (int i = 0; i < 4; i++) {
            float rmax = -1e30f;
            #pragma unroll
            for (int j = 0; j < 4; j++) { s[i][j] *= scale; rmax = fmaxf(rmax, s[i][j]); }
            rmax = fmaxf(rmax, __shfl_xor_sync(0xffffffffu, rmax, 1));
            rmax = fmaxf(rmax, __shfl_xor_sync(0xffffffffu, rmax, 2));
            rmax = fmaxf(rmax, __shfl_xor_sync(0xffffffffu, rmax, 4));
            rmax = fmaxf(rmax, __shfl_xor_sync(0xffffffffu, rmax, 8));
            float mnew = fmaxf(m[i], rmax);
            float rsum = 0.f;
            #pragma unroll
            for (int j = 0; j < 4; j++) {
                float p = expf(s[i][j] - mnew);
                Ps[trow*4 + i][tcol*4 + j] = p;
                rsum += p;
            }
            rsum += __shfl_xor_sync(0xffffffffu, rsum, 1);
            rsum += __shfl_xor_sync(0xffffffffu, rsum, 2);
            rsum += __shfl_xor_sync(0xffffffffu, rsum, 4);
            rsum += __shfl_xor_sync(0xffffffffu, rsum, 8);
            alpha[i] = expf(m[i] - mnew);
            l[i] = l[i] * alpha[i] + rsum;
            m[i] = mnew;
            o[i][0] *= alpha[i];
            o[i][1] *= alpha[i];
        }
        __syncthreads();

        #pragma unroll 8
        for (int j = 0; j < 64; j++) {
            float v0 = Vs[j][tcol*2 + 0];
            float v1 = Vs[j][tcol*2 + 1];
            #pragma unroll
            for (int i = 0; i < 4; i++) {
                float p = Ps[trow*4 + i][j];
                o[i][0] += p * v0;
                o[i][1] += p * v1;
            }
        }
    }

    #pragma unroll
    for (int i = 0; i < 4; i++) {
        float inv = 1.f / l[i];
        int n = qb + trow*4 + i;
        out[(size_t)n * 256 + h * 32 + tcol*2 + 0] = o[i][0] * inv;
        out[(size_t)n * 256 + h * 32 + tcol*2 + 1] = o[i][1] * inv;
    }
}

// ---------------- fused residual-add + LayerNorm ----------------
__global__ __launch_bounds__(256) void add_ln_kernel(
    const float* __restrict__ x, const float* __restrict__ y,
    const float* __restrict__ g, const float* __restrict__ b,
    float* __restrict__ out)
{
    __shared__ float red[256];
    __shared__ float s_mean, s_rstd;
    int row = blockIdx.x, c = threadIdx.x;
    float v = x[(size_t)row*256 + c] + y[(size_t)row*256 + c];
    red[c] = v; __syncthreads();
    for (int s = 128; s > 0; s >>= 1) { if (c < s) red[c] += red[c + s]; __syncthreads(); }
    if (c == 0) s_mean = red[0] * (1.f/256.f);
    __syncthreads();
    float dv = v - s_mean;
    red[c] = dv * dv; __syncthreads();
    for (int s = 128; s > 0; s >>= 1) { if (c < s) red[c] += red[c + s]; __syncthreads(); }
    if (c == 0) s_rstd = rsqrtf(red[0] * (1.f/256.f) + 1e-5f);
    __syncthreads();
    out[(size_t)row*256 + c] = dv * s_rstd * g[c] + b[c];
}

// ---------------- h_combined = h + h0 ----------------
__global__ __launch_bounds__(256) void hc_kernel(
    const float* __restrict__ h, const float* __restrict__ h0,
    float* __restrict__ hc, float* __restrict__ out_tail)
{
    int idx = blockIdx.x * 256 + threadIdx.x;
    float v = h[idx] + h0[idx];
    hc[idx] = v;
    out_tail[idx] = v;
}

// ---------------- fused edge predictor (TF32 tensor cores) ----------------
// Block: 128 edges x 128 cols x K=256. 8 warps (4m x 2n), warp tile 32x64.
// A[e][k] = hc[src[e]][k] * hc[dst[e]][k] * w[e] (tf32), B = Wp1.
// Epilogue: leaky(acc + bp1) . Wp2 reduced in-register + smem cross-warp.
__global__ __launch_bounds__(256) void edge_tc_kernel(
    const float* __restrict__ hc,
    const int* __restrict__ src, const int* __restrict__ dst,
    const float* __restrict__ w,
    const float* __restrict__ Wp1, const float* __restrict__ bp1,
    const float* __restrict__ Wp2, const float* __restrict__ bp2,
    float* __restrict__ out, int E)
{
    __shared__ float As[128][36];
    __shared__ float Bs[32][132];
    __shared__ int   sSrc[128], sDst[128];
    __shared__ float sW[128], sWp2[128], sBp1[128];
    __shared__ float sred[128][2];

    const int tid  = threadIdx.x;
    const int lane = tid & 31;
    const int wid  = tid >> 5;
    const int wm   = wid >> 1;
    const int wn   = wid & 1;
    const int grp  = lane >> 2;
    const int tig  = lane & 3;
    const int e0   = blockIdx.x * 128;

    if (tid < 128) {
        int e = e0 + tid;
        if (e < E) { sSrc[tid] = src[e]; sDst[tid] = dst[e]; sW[tid] = w[e]; }
        else       { sSrc[tid] = 0;      sDst[tid] = 0;      sW[tid] = 0.f; }
        sWp2[tid] = Wp2[tid];
        sBp1[tid] = bp1[tid];
    }
    __syncthreads();

    float acc[2][8][4];
    #pragma unroll
    for (int mt = 0; mt < 2; mt++)
        #pragma unroll
        for (int nt = 0; nt < 8; nt++)
            #pragma unroll
            for (int i = 0; i < 4; i++) acc[mt][nt][i] = 0.f;

    for (int kt = 0; kt < 256; kt += 32) {
        // A gather tile 128x32
        #pragma unroll
        for (int i = 0; i < 4; i++) {
            int f  = tid + i * 256;
            int e  = f >> 3;
            int c4 = f & 7;
            float4 a = *reinterpret_cast<const float4*>(hc + (size_t)sSrc[e]*256 + kt + c4*4);
            float4 b = *reinterpret_cast<const float4*>(hc + (size_t)sDst[e]*256 + kt + c4*4);
            float ww = sW[e];
            As[e][c4*4+0] = f2tf32(a.x*b.x*ww);
            As[e][c4*4+1] = f2tf32(a.y*b.y*ww);
            As[e][c4*4+2] = f2tf32(a.z*b.z*ww);
            As[e][c4*4+3] = f2tf32(a.w*b.w*ww);
        }
        // B tile 32x128 from Wp1
        #pragma unroll
        for (int i = 0; i < 4; i++) {
            int f  = tid + i * 256;
            int r  = f >> 5;
            int c4 = f & 31;
            float4 v = *reinterpret_cast<const float4*>(Wp1 + (size_t)(kt + r) * 128 + c4 * 4);
            Bs[r][c4*4+0] = f2tf32(v.x); Bs[r][c4*4+1] = f2tf32(v.y);
            Bs[r][c4*4+2] = f2tf32(v.z); Bs[r][c4*4+3] = f2tf32(v.w);
        }
        __syncthreads();

        #pragma unroll
        for (int ks = 0; ks < 4; ks++) {
            int k0 = ks * 8 + tig;
            float a[2][4], b[8][2];
            #pragma unroll
            for (int mt = 0; mt < 2; mt++) {
                int row = wm * 32 + mt * 16 + grp;
                a[mt][0] = As[row  ][k0  ];
                a[mt][1] = As[row+8][k0  ];
                a[mt][2] = As[row  ][k0+4];
                a[mt][3] = As[row+8][k0+4];
            }
            #pragma unroll
            for (int nt = 0; nt < 8; nt++) {
                int col = wn * 64 + nt * 8 + grp;
                b[nt][0] = Bs[k0    ][col];
                b[nt][1] = Bs[k0 + 4][col];
            }
            #pragma unroll
            for (int mt = 0; mt < 2; mt++)
                #pragma unroll
                for (int nt = 0; nt < 8; nt++)
                    mma_tf32(acc[mt][nt], a[mt], b[nt]);
        }
        __syncthreads();
    }

    // epilogue: per-row partial dot with Wp2 over this warp's 64 columns
    #pragma unroll
    for (int mt = 0; mt < 2; mt++) {
        float p0 = 0.f, p1 = 0.f;   // halves: rows grp and grp+8
        #pragma unroll
        for (int nt = 0; nt < 8; nt++) {
            int col = wn * 64 + nt * 8 + tig * 2;
            float bb0 = sBp1[col], bb1 = sBp1[col+1];
            float w0  = sWp2[col], w1  = sWp2[col+1];
            float y;
            y = acc[mt][nt][0] + bb0; y = (y > 0.f) ? y : 0.2f*y; p0 += y * w0;
            y = acc[mt][nt][1] + bb1; y = (y > 0.f) ? y : 0.2f*y; p0 += y * w1;
            y = acc[mt][nt][2] + bb0; y = (y > 0.f) ? y : 0.2f*y; p1 += y * w0;
            y = acc[mt][nt][3] + bb1; y = (y > 0.f) ? y : 0.2f*y; p1 += y * w1;
        }
        // reduce over tig (4 lanes hold same row)
        p0 += __shfl_xor_sync(0xffffffffu, p0, 1);
        p0 += __shfl_xor_sync(0xffffffffu, p0, 2);
        p1 += __shfl_xor_sync(0xffffffffu, p1, 1);
        p1 += __shfl_xor_sync(0xffffffffu, p1, 2);
        if (tig == 0) {
            int r0 = wm * 32 + mt * 16 + grp;
            sred[r0    ][wn] = p0;
            sred[r0 + 8][wn] = p1;
        }
    }
    __syncthreads();

    if (tid < 128) {
        int e = e0 + tid;
        if (e < E) out[e] = sred[tid][0] + sred[tid][1] + bp2[0];
    }
}

// ---------------- host orchestration ----------------
extern "C" void kernel_launch(void* const* d_in, const int* in_sizes, int n_in,
                              void* d_out, int out_size)
{
    const float* x        = (const float*)d_in[0];
    const int*   pos_src  = (const int*)  d_in[1];
    const int*   pos_dst  = (const int*)  d_in[2];
    const float* pos_w    = (const float*)d_in[3];
    const int*   neg_src  = (const int*)  d_in[4];
    const int*   neg_dst  = (const int*)  d_in[5];
    const float* neg_w    = (const float*)d_in[6];
    const float* Wi       = (const float*)d_in[7];
    const float* bi       = (const float*)d_in[8];
    const float* Wqkv     = (const float*)d_in[9];
    const float* bqkv     = (const float*)d_in[10];
    const float* Wo       = (const float*)d_in[11];
    const float* bo       = (const float*)d_in[12];
    const float* g1       = (const float*)d_in[13];
    const float* be1      = (const float*)d_in[14];
    const float* g2       = (const float*)d_in[15];
    const float* be2      = (const float*)d_in[16];
    const float* W1       = (const float*)d_in[17];
    const float* b1       = (const float*)d_in[18];
    const float* W2       = (const float*)d_in[19];
    const float* b2       = (const float*)d_in[20];
    const float* Wp1      = (const float*)d_in[21];
    const float* bp1      = (const float*)d_in[22];
    const float* Wp2      = (const float*)d_in[23];
    const float* bp2      = (const float*)d_in[24];

    const int E = in_sizes[1];   // 500000

    float* S = nullptr;
    cudaGetSymbolAddress((void**)&S, g_scratch);
    float* h0   = S + OFF_H0;
    float* h    = S + OFF_H;
    float* qkv  = S + OFF_QKV;
    float* attn = S + OFF_ATTN;
    float* tmp  = S + OFF_TMP;
    float* ff   = S + OFF_FF;
    float* hc   = S + OFF_HC;
    float* out  = (float*)d_out;

    // h0 = x @ Wi + bi
    sgemm_tc_kernel<<<dim3(DD/64, NN/128), 256>>>(NN, DD, INF_, x, Wi, bi, h0, 0);

    for (int l = 0; l < LL; l++) {
        const float* hin = (l == 0) ? h0 : h;
        sgemm_tc_kernel<<<dim3(768/64, NN/128), 256>>>(NN, 768, DD,
            hin, Wqkv + (size_t)l*DD*768, bqkv + (size_t)l*768, qkv, 0);
        attn_kernel<<<dim3(NN/64, HH), 256>>>(qkv, attn);
        sgemm_tc_kernel<<<dim3(DD/64, NN/128), 256>>>(NN, DD, DD,
            attn, Wo + (size_t)l*DD*DD, bo + (size_t)l*DD, tmp, 0);
        add_ln_kernel<<<NN, 256>>>(hin, tmp, g1 + (size_t)l*DD, be1 + (size_t)l*DD, h);
        sgemm_tc_kernel<<<dim3(FF_/64, NN/128), 256>>>(NN, FF_, DD,
            h, W1 + (size_t)l*DD*FF_, b1 + (size_t)l*FF_, ff, 1);
        sgemm_tc_kernel<<<dim3(DD/64, NN/128), 256>>>(NN, DD, FF_,
            ff, W2 + (size_t)l*FF_*DD, b2 + (size_t)l*DD, tmp, 0);
        add_ln_kernel<<<NN, 256>>>(h, tmp, g2 + (size_t)l*DD, be2 + (size_t)l*DD, h);
    }

    hc_kernel<<<NN*DD/256, 256>>>(h, h0, hc, out + 2*(size_t)E);

    int eblocks = (E + 127) / 128;
    edge_tc_kernel<<<eblocks, 256>>>(hc, pos_src, pos_dst, pos_w, Wp1, bp1, Wp2, bp2, out, E);
    edge_tc_kernel<<<eblocks, 256>>>(hc, neg_src, neg_dst, neg_w, Wp1, bp1, Wp2, bp2, out + E, E);
}

// round 6
// speedup vs baseline: 2.7876x; 1.8681x over previous
#include <cuda_runtime.h>
#include <cuda_bf16.h>
#include <math.h>

// ---------------- problem constants ----------------
#define NN   4096
#define INF_ 512
#define DD   256
#define LL   2
#define HH   8
#define DH   32
#define FF_  1024
#define HALF_ 128

// ---------------- scratch (device global, no allocs) ----------------
#define OFF_H0   0
#define OFF_H    (OFF_H0 + NN*DD)
#define OFF_QKV  (OFF_H  + NN*DD)
#define OFF_ATTN (OFF_QKV + NN*3*DD)
#define OFF_TMP  (OFF_ATTN + NN*DD)
#define OFF_FF   (OFF_TMP + NN*DD)
#define OFF_HC   (OFF_FF + NN*FF_)
#define SCRATCH_FLOATS (OFF_HC + NN*DD)

__device__ float g_scratch[SCRATCH_FLOATS];

// dynamic smem sizes
#define SGEMM_SMEM ((2*128*36 + 2*32*68) * 4)
#define EDGE_SMEM  ((2*128*36 + 2*32*132) * 4)
#define ATTN_SMEM  ((2*64*35 + 2*64*36 + 8*16*68) * 4)   // P tile is 16x64 (stride 68)!

// ---------------- TF32 helpers ----------------
__device__ __forceinline__ float f2tf32(float x) {
    unsigned r;
    asm("cvt.rna.tf32.f32 %0, %1;" : "=r"(r) : "f"(x));
    return __uint_as_float(r);
}

__device__ __forceinline__ void mma_tf32(float* d, const float* a, const float* b) {
    asm("mma.sync.aligned.m16n8k8.row.col.f32.tf32.tf32.f32 "
        "{%0,%1,%2,%3},{%4,%5,%6,%7},{%8,%9},{%0,%1,%2,%3};"
        : "+f"(d[0]), "+f"(d[1]), "+f"(d[2]), "+f"(d[3])
        : "r"(__float_as_uint(a[0])), "r"(__float_as_uint(a[1])),
          "r"(__float_as_uint(a[2])), "r"(__float_as_uint(a[3])),
          "r"(__float_as_uint(b[0])), "r"(__float_as_uint(b[1])));
}

// ---------------- TF32 tensor-core SGEMM, ping-pong prefetch ----------------
// C = A@B + bias, optional ReLU. BM=128, BN=64, BK=32. 256 threads = 8 warps (4m x 2n).
__global__ __launch_bounds__(256) void sgemm_tc_kernel(
    int M, int N, int K,
    const float* __restrict__ A, const float* __restrict__ B,
    const float* __restrict__ bias, float* __restrict__ C, int act)
{
    extern __shared__ float sm[];
    float* As_ = sm;                 // [2][128][36]
    float* Bs_ = sm + 2*128*36;      // [2][32][68]
#define AS(bb,r,c) As_[(bb)*(128*36) + (r)*36 + (c)]
#define BS(bb,r,c) Bs_[(bb)*(32*68) + (r)*68 + (c)]

    const int tid  = threadIdx.x;
    const int lane = tid & 31;
    const int wid  = tid >> 5;
    const int wm   = wid >> 1;
    const int wn   = wid & 1;
    const int grp  = lane >> 2;
    const int tig  = lane & 3;

    const int bx = blockIdx.x, by = blockIdx.y;
    A += (size_t)by * 128 * K;
    B += (size_t)bx * 64;
    C += (size_t)by * 128 * N + (size_t)bx * 64;
    bias += (size_t)bx * 64;

    float acc[2][4][4] = {};
    float4 rA[4], rB[2];

    auto ldT = [&](int kt) {
        #pragma unroll
        for (int i = 0; i < 4; i++) {
            int f = tid + i * 256, r = f >> 3, c4 = f & 7;
            rA[i] = *reinterpret_cast<const float4*>(A + (size_t)r * K + kt + c4 * 4);
        }
        #pragma unroll
        for (int i = 0; i < 2; i++) {
            int f = tid + i * 256, r = f >> 4, c4 = f & 15;
            rB[i] = *reinterpret_cast<const float4*>(B + (size_t)(kt + r) * N + c4 * 4);
        }
    };
    auto stT = [&](int bb) {
        #pragma unroll
        for (int i = 0; i < 4; i++) {
            int f = tid + i * 256, r = f >> 3, c4 = f & 7;
            AS(bb,r,c4*4+0) = f2tf32(rA[i].x); AS(bb,r,c4*4+1) = f2tf32(rA[i].y);
            AS(bb,r,c4*4+2) = f2tf32(rA[i].z); AS(bb,r,c4*4+3) = f2tf32(rA[i].w);
        }
        #pragma unroll
        for (int i = 0; i < 2; i++) {
            int f = tid + i * 256, r = f >> 4, c4 = f & 15;
            BS(bb,r,c4*4+0) = f2tf32(rB[i].x); BS(bb,r,c4*4+1) = f2tf32(rB[i].y);
            BS(bb,r,c4*4+2) = f2tf32(rB[i].z); BS(bb,r,c4*4+3) = f2tf32(rB[i].w);
        }
    };

    const int T = K / 32;
    ldT(0); stT(0); __syncthreads();

    for (int t = 0; t < T; t++) {
        int cur = t & 1;
        if (t + 1 < T) ldT((t + 1) * 32);
        #pragma unroll
        for (int ks = 0; ks < 4; ks++) {
            int k0 = ks * 8 + tig;
            float a[2][4], b[4][2];
            #pragma unroll
            for (int mt = 0; mt < 2; mt++) {
                int row = wm * 32 + mt * 16 + grp;
                a[mt][0] = AS(cur,row,  k0);   a[mt][1] = AS(cur,row+8,k0);
                a[mt][2] = AS(cur,row,  k0+4); a[mt][3] = AS(cur,row+8,k0+4);
            }
            #pragma unroll
            for (int nt = 0; nt < 4; nt++) {
                int col = wn * 32 + nt * 8 + grp;
                b[nt][0] = BS(cur,k0,col); b[nt][1] = BS(cur,k0+4,col);
            }
            #pragma unroll
            for (int mt = 0; mt < 2; mt++)
                #pragma unroll
                for (int nt = 0; nt < 4; nt++)
                    mma_tf32(acc[mt][nt], a[mt], b[nt]);
        }
        if (t + 1 < T) stT((t + 1) & 1);
        __syncthreads();
    }

    #pragma unroll
    for (int mt = 0; mt < 2; mt++) {
        #pragma unroll
        for (int nt = 0; nt < 4; nt++) {
            int row = wm * 32 + mt * 16 + grp;
            int col = wn * 32 + nt * 8 + tig * 2;
            float b0 = bias[col], b1 = bias[col+1];
            float2 v0, v1;
            v0.x = acc[mt][nt][0] + b0; v0.y = acc[mt][nt][1] + b1;
            v1.x = acc[mt][nt][2] + b0; v1.y = acc[mt][nt][3] + b1;
            if (act == 1) {
                v0.x = fmaxf(v0.x, 0.f); v0.y = fmaxf(v0.y, 0.f);
                v1.x = fmaxf(v1.x, 0.f); v1.y = fmaxf(v1.y, 0.f);
            }
            *reinterpret_cast<float2*>(C + (size_t)row * N + col)     = v0;
            *reinterpret_cast<float2*>(C + (size_t)(row+8) * N + col) = v1;
        }
    }
#undef AS
#undef BS
}

// ---------------- TF32 MMA flash attention ----------------
// grid (NN/128, HH), 256 threads = 8 warps, warp owns 16 query rows.
__global__ __launch_bounds__(256) void attn_tc_kernel(
    const float* __restrict__ qkv, float* __restrict__ out)
{
    extern __shared__ float sm[];
    float* Ks_ = sm;                       // [2][64][35]
    float* Vs_ = sm + 2*64*35;             // [2][64][36]
    float* Ps_ = sm + 2*64*35 + 2*64*36;   // [8][16][68]  (16 rows x 64 cols + pad)
#define KS(bb,r,c) Ks_[(bb)*(64*35) + (r)*35 + (c)]
#define VS(bb,r,c) Vs_[(bb)*(64*36) + (r)*36 + (c)]
#define PS(w,r,c)  Ps_[(w)*(16*68) + (r)*68 + (c)]

    const int h  = blockIdx.y;
    const int qb = blockIdx.x * 128;
    const int tid  = threadIdx.x;
    const int lane = tid & 31;
    const int wid  = tid >> 5;
    const int grp  = lane >> 2;
    const int tig  = lane & 3;
    const float scale = 0.17677669529663687f;   // 1/sqrt(32)

    // Q fragments, scale folded in (per-thread, registers; 16 rows per warp)
    float qa[4][4];
    {
        const float* q0 = qkv + (size_t)(qb + wid*16 + grp) * 768 + h * 32;
        const float* q1 = q0 + (size_t)8 * 768;
        #pragma unroll
        for (int ks = 0; ks < 4; ks++) {
            qa[ks][0] = f2tf32(q0[ks*8 + tig]     * scale);
            qa[ks][1] = f2tf32(q1[ks*8 + tig]     * scale);
            qa[ks][2] = f2tf32(q0[ks*8 + tig + 4] * scale);
            qa[ks][3] = f2tf32(q1[ks*8 + tig + 4] * scale);
        }
    }

    float m0 = -1e30f, m1 = -1e30f, l0 = 0.f, l1 = 0.f;
    float o[4][4] = {};
    float4 rk[2], rv[2];

    auto ldKV = [&](int kb) {
        #pragma unroll
        for (int i = 0; i < 2; i++) {
            int f = tid + i * 256, r = f >> 3, c4 = f & 7;
            const float* p = qkv + (size_t)(kb + r) * 768 + 256 + h * 32 + c4 * 4;
            rk[i] = *reinterpret_cast<const float4*>(p);
            rv[i] = *reinterpret_cast<const float4*>(p + 256);
        }
    };
    auto stKV = [&](int bb) {
        #pragma unroll
        for (int i = 0; i < 2; i++) {
            int f = tid + i * 256, r = f >> 3, c4 = f & 7;
            KS(bb,r,c4*4+0) = f2tf32(rk[i].x); KS(bb,r,c4*4+1) = f2tf32(rk[i].y);
            KS(bb,r,c4*4+2) = f2tf32(rk[i].z); KS(bb,r,c4*4+3) = f2tf32(rk[i].w);
            VS(bb,r,c4*4+0) = f2tf32(rv[i].x); VS(bb,r,c4*4+1) = f2tf32(rv[i].y);
            VS(bb,r,c4*4+2) = f2tf32(rv[i].z); VS(bb,r,c4*4+3) = f2tf32(rv[i].w);
        }
    };

    ldKV(0); stKV(0); __syncthreads();

    for (int t = 0; t < NN/64; t++) {
        int cur = t & 1;
        if (t < NN/64 - 1) ldKV((t + 1) * 64);

        // S = Q @ K^T for this warp's 16 rows x 64 kv cols
        float sacc[8][4] = {};
        #pragma unroll
        for (int ks = 0; ks < 4; ks++) {
            #pragma unroll
            for (int nt = 0; nt < 8; nt++) {
                float b[2];
                b[0] = KS(cur, nt*8 + grp, ks*8 + tig);
                b[1] = KS(cur, nt*8 + grp, ks*8 + tig + 4);
                mma_tf32(sacc[nt], qa[ks], b);
            }
        }

        // online softmax (rows grp and grp+8 of warp tile; reduce over tig lanes)
        float rmax0 = -1e30f, rmax1 = -1e30f;
        #pragma unroll
        for (int nt = 0; nt < 8; nt++) {
            rmax0 = fmaxf(rmax0, fmaxf(sacc[nt][0], sacc[nt][1]));
            rmax1 = fmaxf(rmax1, fmaxf(sacc[nt][2], sacc[nt][3]));
        }
        rmax0 = fmaxf(rmax0, __shfl_xor_sync(0xffffffffu, rmax0, 1));
        rmax0 = fmaxf(rmax0, __shfl_xor_sync(0xffffffffu, rmax0, 2));
        rmax1 = fmaxf(rmax1, __shfl_xor_sync(0xffffffffu, rmax1, 1));
        rmax1 = fmaxf(rmax1, __shfl_xor_sync(0xffffffffu, rmax1, 2));
        float mn0 = fmaxf(m0, rmax0), mn1 = fmaxf(m1, rmax1);
        float a0 = __expf(m0 - mn0), a1 = __expf(m1 - mn1);
        float ps0 = 0.f, ps1 = 0.f;
        #pragma unroll
        for (int nt = 0; nt < 8; nt++) {
            float p00 = __expf(sacc[nt][0] - mn0);
            float p01 = __expf(sacc[nt][1] - mn0);
            float p10 = __expf(sacc[nt][2] - mn1);
            float p11 = __expf(sacc[nt][3] - mn1);
            ps0 += p00 + p01; ps1 += p10 + p11;
            PS(wid, grp,   nt*8 + tig*2    ) = p00;
            PS(wid, grp,   nt*8 + tig*2 + 1) = p01;
            PS(wid, grp+8, nt*8 + tig*2    ) = p10;
            PS(wid, grp+8, nt*8 + tig*2 + 1) = p11;
        }
        ps0 += __shfl_xor_sync(0xffffffffu, ps0, 1);
        ps0 += __shfl_xor_sync(0xffffffffu, ps0, 2);
        ps1 += __shfl_xor_sync(0xffffffffu, ps1, 1);
        ps1 += __shfl_xor_sync(0xffffffffu, ps1, 2);
        l0 = l0 * a0 + ps0; l1 = l1 * a1 + ps1;
        m0 = mn0; m1 = mn1;
        #pragma unroll
        for (int nt = 0; nt < 4; nt++) {
            o[nt][0] *= a0; o[nt][1] *= a0;
            o[nt][2] *= a1; o[nt][3] *= a1;
        }
        __syncwarp();

        // O += P @ V
        #pragma unroll
        for (int ks = 0; ks < 8; ks++) {
            float a[4];
            a[0] = PS(wid, grp,   ks*8 + tig);
            a[1] = PS(wid, grp+8, ks*8 + tig);
            a[2] = PS(wid, grp,   ks*8 + tig + 4);
            a[3] = PS(wid, grp+8, ks*8 + tig + 4);
            #pragma unroll
            for (int nt = 0; nt < 4; nt++) {
                float b[2];
                b[0] = VS(cur, ks*8 + tig,     nt*8 + grp);
                b[1] = VS(cur, ks*8 + tig + 4, nt*8 + grp);
                mma_tf32(o[nt], a, b);
            }
        }
        __syncwarp();   // P reads done before next iteration's P writes

        if (t < NN/64 - 1) stKV((t + 1) & 1);
        __syncthreads();
    }

    float inv0 = 1.f / l0, inv1 = 1.f / l1;
    int r0 = qb + wid*16 + grp;
    #pragma unroll
    for (int nt = 0; nt < 4; nt++) {
        int col = h * 32 + nt * 8 + tig * 2;
        *reinterpret_cast<float2*>(out + (size_t)r0 * 256 + col) =
            make_float2(o[nt][0] * inv0, o[nt][1] * inv0);
        *reinterpret_cast<float2*>(out + (size_t)(r0 + 8) * 256 + col) =
            make_float2(o[nt][2] * inv1, o[nt][3] * inv1);
    }
#undef KS
#undef VS
#undef PS
}

// ---------------- fused residual-add + LayerNorm ----------------
__global__ __launch_bounds__(256) void add_ln_kernel(
    const float* __restrict__ x, const float* __restrict__ y,
    const float* __restrict__ g, const float* __restrict__ b,
    float* __restrict__ out)
{
    __shared__ float red[256];
    __shared__ float s_mean, s_rstd;
    int row = blockIdx.x, c = threadIdx.x;
    float v = x[(size_t)row*256 + c] + y[(size_t)row*256 + c];
    red[c] = v; __syncthreads();
    for (int s = 128; s > 0; s >>= 1) { if (c < s) red[c] += red[c + s]; __syncthreads(); }
    if (c == 0) s_mean = red[0] * (1.f/256.f);
    __syncthreads();
    float dv = v - s_mean;
    red[c] = dv * dv; __syncthreads();
    for (int s = 128; s > 0; s >>= 1) { if (c < s) red[c] += red[c + s]; __syncthreads(); }
    if (c == 0) s_rstd = rsqrtf(red[0] * (1.f/256.f) + 1e-5f);
    __syncthreads();
    out[(size_t)row*256 + c] = dv * s_rstd * g[c] + b[c];
}

// ---------------- h_combined = h + h0 ----------------
__global__ __launch_bounds__(256) void hc_kernel(
    const float* __restrict__ h, const float* __restrict__ h0,
    float* __restrict__ hc, float* __restrict__ out_tail)
{
    int idx = blockIdx.x * 256 + threadIdx.x;
    float v = h[idx] + h0[idx];
    hc[idx] = v;
    out_tail[idx] = v;
}

// ---------------- fused edge predictor, ping-pong prefetch ----------------
__global__ __launch_bounds__(256) void edge_tc_kernel(
    const float* __restrict__ hc,
    const int* __restrict__ src, const int* __restrict__ dst,
    const float* __restrict__ w,
    const float* __restrict__ Wp1, const float* __restrict__ bp1,
    const float* __restrict__ Wp2, const float* __restrict__ bp2,
    float* __restrict__ out, int E)
{
    extern __shared__ float sm[];
    float* As_ = sm;                  // [2][128][36]
    float* Bs_ = sm + 2*128*36;       // [2][32][132]
#define EAS(bb,r,c) As_[(bb)*(128*36) + (r)*36 + (c)]
#define EBS(bb,r,c) Bs_[(bb)*(32*132) + (r)*132 + (c)]
    __shared__ int   sSrc[128], sDst[128];
    __shared__ float sW[128], sWp2[128], sBp1[128];
    __shared__ float sred[128][2];

    const int tid  = threadIdx.x;
    const int lane = tid & 31;
    const int wid  = tid >> 5;
    const int wm   = wid >> 1;
    const int wn   = wid & 1;
    const int grp  = lane >> 2;
    const int tig  = lane & 3;
    const int e0   = blockIdx.x * 128;

    if (tid < 128) {
        int e = e0 + tid;
        if (e < E) { sSrc[tid] = src[e]; sDst[tid] = dst[e]; sW[tid] = w[e]; }
        else       { sSrc[tid] = 0;      sDst[tid] = 0;      sW[tid] = 0.f; }
        sWp2[tid] = Wp2[tid];
        sBp1[tid] = bp1[tid];
    }
    __syncthreads();

    float acc[2][8][4] = {};
    float4 ga[4], gb[4], rB[4];

    auto ldT = [&](int kt) {
        #pragma unroll
        for (int i = 0; i < 4; i++) {
            int f = tid + i * 256, e = f >> 3, c4 = f & 7;
            ga[i] = *reinterpret_cast<const float4*>(hc + (size_t)sSrc[e]*256 + kt + c4*4);
            gb[i] = *reinterpret_cast<const float4*>(hc + (size_t)sDst[e]*256 + kt + c4*4);
        }
        #pragma unroll
        for (int i = 0; i < 4; i++) {
            int f = tid + i * 256, r = f >> 5, c4 = f & 31;
            rB[i] = *reinterpret_cast<const float4*>(Wp1 + (size_t)(kt + r) * 128 + c4 * 4);
        }
    };
    auto stT = [&](int bb) {
        #pragma unroll
        for (int i = 0; i < 4; i++) {
            int f = tid + i * 256, e = f >> 3, c4 = f & 7;
            float ww = sW[e];
            EAS(bb,e,c4*4+0) = f2tf32(ga[i].x * gb[i].x * ww);
            EAS(bb,e,c4*4+1) = f2tf32(ga[i].y * gb[i].y * ww);
            EAS(bb,e,c4*4+2) = f2tf32(ga[i].z * gb[i].z * ww);
            EAS(bb,e,c4*4+3) = f2tf32(ga[i].w * gb[i].w * ww);
        }
        #pragma unroll
        for (int i = 0; i < 4; i++) {
            int f = tid + i * 256, r = f >> 5, c4 = f & 31;
            EBS(bb,r,c4*4+0) = f2tf32(rB[i].x); EBS(bb,r,c4*4+1) = f2tf32(rB[i].y);
            EBS(bb,r,c4*4+2) = f2tf32(rB[i].z); EBS(bb,r,c4*4+3) = f2tf32(rB[i].w);
        }
    };

    ldT(0); stT(0); __syncthreads();

    for (int t = 0; t < 8; t++) {
        int cur = t & 1;
        if (t < 7) ldT((t + 1) * 32);
        #pragma unroll
        for (int ks = 0; ks < 4; ks++) {
            int k0 = ks * 8 + tig;
            float a[2][4], b[8][2];
            #pragma unroll
            for (int mt = 0; mt < 2; mt++) {
                int row = wm * 32 + mt * 16 + grp;
                a[mt][0] = EAS(cur,row,  k0);   a[mt][1] = EAS(cur,row+8,k0);
                a[mt][2] = EAS(cur,row,  k0+4); a[mt][3] = EAS(cur,row+8,k0+4);
            }
            #pragma unroll
            for (int nt = 0; nt < 8; nt++) {
                int col = wn * 64 + nt * 8 + grp;
                b[nt][0] = EBS(cur,k0,col); b[nt][1] = EBS(cur,k0+4,col);
            }
            #pragma unroll
            for (int mt = 0; mt < 2; mt++)
                #pragma unroll
                for (int nt = 0; nt < 8; nt++)
                    mma_tf32(acc[mt][nt], a[mt], b[nt]);
        }
        if (t < 7) stT((t + 1) & 1);
        __syncthreads();
    }

    // epilogue: leaky(acc + bp1) . Wp2
    #pragma unroll
    for (int mt = 0; mt < 2; mt++) {
        float p0 = 0.f, p1 = 0.f;
        #pragma unroll
        for (int nt = 0; nt < 8; nt++) {
            int col = wn * 64 + nt * 8 + tig * 2;
            float bb0 = sBp1[col], bb1 = sBp1[col+1];
            float w0  = sWp2[col], w1  = sWp2[col+1];
            float y;
            y = acc[mt][nt][0] + bb0; y = (y > 0.f) ? y : 0.2f*y; p0 += y * w0;
            y = acc[mt][nt][1] + bb1; y = (y > 0.f) ? y : 0.2f*y; p0 += y * w1;
            y = acc[mt][nt][2] + bb0; y = (y > 0.f) ? y : 0.2f*y; p1 += y * w0;
            y = acc[mt][nt][3] + bb1; y = (y > 0.f) ? y : 0.2f*y; p1 += y * w1;
        }
        p0 += __shfl_xor_sync(0xffffffffu, p0, 1);
        p0 += __shfl_xor_sync(0xffffffffu, p0, 2);
        p1 += __shfl_xor_sync(0xffffffffu, p1, 1);
        p1 += __shfl_xor_sync(0xffffffffu, p1, 2);
        if (tig == 0) {
            int r0 = wm * 32 + mt * 16 + grp;
            sred[r0    ][wn] = p0;
            sred[r0 + 8][wn] = p1;
        }
    }
    __syncthreads();

    if (tid < 128) {
        int e = e0 + tid;
        if (e < E) out[e] = sred[tid][0] + sred[tid][1] + bp2[0];
    }
#undef EAS
#undef EBS
}

// ---------------- host orchestration ----------------
extern "C" void kernel_launch(void* const* d_in, const int* in_sizes, int n_in,
                              void* d_out, int out_size)
{
    const float* x        = (const float*)d_in[0];
    const int*   pos_src  = (const int*)  d_in[1];
    const int*   pos_dst  = (const int*)  d_in[2];
    const float* pos_w    = (const float*)d_in[3];
    const int*   neg_src  = (const int*)  d_in[4];
    const int*   neg_dst  = (const int*)  d_in[5];
    const float* neg_w    = (const float*)d_in[6];
    const float* Wi       = (const float*)d_in[7];
    const float* bi       = (const float*)d_in[8];
    const float* Wqkv     = (const float*)d_in[9];
    const float* bqkv     = (const float*)d_in[10];
    const float* Wo       = (const float*)d_in[11];
    const float* bo       = (const float*)d_in[12];
    const float* g1       = (const float*)d_in[13];
    const float* be1      = (const float*)d_in[14];
    const float* g2       = (const float*)d_in[15];
    const float* be2      = (const float*)d_in[16];
    const float* W1       = (const float*)d_in[17];
    const float* b1       = (const float*)d_in[18];
    const float* W2       = (const float*)d_in[19];
    const float* b2       = (const float*)d_in[20];
    const float* Wp1      = (const float*)d_in[21];
    const float* bp1      = (const float*)d_in[22];
    const float* Wp2      = (const float*)d_in[23];
    const float* bp2      = (const float*)d_in[24];

    const int E = in_sizes[1];   // 500000

    cudaFuncSetAttribute(sgemm_tc_kernel, cudaFuncAttributeMaxDynamicSharedMemorySize, SGEMM_SMEM);
    cudaFuncSetAttribute(attn_tc_kernel,  cudaFuncAttributeMaxDynamicSharedMemorySize, ATTN_SMEM);
    cudaFuncSetAttribute(edge_tc_kernel,  cudaFuncAttributeMaxDynamicSharedMemorySize, EDGE_SMEM);

    float* S = nullptr;
    cudaGetSymbolAddress((void**)&S, g_scratch);
    float* h0   = S + OFF_H0;
    float* h    = S + OFF_H;
    float* qkv  = S + OFF_QKV;
    float* attn = S + OFF_ATTN;
    float* tmp  = S + OFF_TMP;
    float* ff   = S + OFF_FF;
    float* hc   = S + OFF_HC;
    float* out  = (float*)d_out;

    // h0 = x @ Wi + bi
    sgemm_tc_kernel<<<dim3(DD/64, NN/128), 256, SGEMM_SMEM>>>(NN, DD, INF_, x, Wi, bi, h0, 0);

    for (int l = 0; l < LL; l++) {
        const float* hin = (l == 0) ? h0 : h;
        sgemm_tc_kernel<<<dim3(768/64, NN/128), 256, SGEMM_SMEM>>>(NN, 768, DD,
            hin, Wqkv + (size_t)l*DD*768, bqkv + (size_t)l*768, qkv, 0);
        attn_tc_kernel<<<dim3(NN/128, HH), 256, ATTN_SMEM>>>(qkv, attn);
        sgemm_tc_kernel<<<dim3(DD/64, NN/128), 256, SGEMM_SMEM>>>(NN, DD, DD,
            attn, Wo + (size_t)l*DD*DD, bo + (size_t)l*DD, tmp, 0);
        add_ln_kernel<<<NN, 256>>>(hin, tmp, g1 + (size_t)l*DD, be1 + (size_t)l*DD, h);
        sgemm_tc_kernel<<<dim3(FF_/64, NN/128), 256, SGEMM_SMEM>>>(NN, FF_, DD,
            h, W1 + (size_t)l*DD*FF_, b1 + (size_t)l*FF_, ff, 1);
        sgemm_tc_kernel<<<dim3(DD/64, NN/128), 256, SGEMM_SMEM>>>(NN, DD, FF_,
            ff, W2 + (size_t)l*FF_*DD, b2 + (size_t)l*DD, tmp, 0);
        add_ln_kernel<<<NN, 256>>>(h, tmp, g2 + (size_t)l*DD, be2 + (size_t)l*DD, h);
    }

    hc_kernel<<<NN*DD/256, 256>>>(h, h0, hc, out + 2*(size_t)E);

    int eblocks = (E + 127) / 128;
    edge_tc_kernel<<<eblocks, 256, EDGE_SMEM>>>(hc, pos_src, pos_dst, pos_w, Wp1, bp1, Wp2, bp2, out, E);
    edge_tc_kernel<<<eblocks, 256, EDGE_SMEM>>>(hc, neg_src, neg_dst, neg_w, Wp1, bp1, Wp2, bp2, out + E, E);
}

// round 8
// speedup vs baseline: 3.2516x; 1.1664x over previous
#include <cuda_runtime.h>
#include <cuda_bf16.h>
#include <math.h>
#include <stdint.h>

// ---------------- problem constants ----------------
#define NN   4096
#define INF_ 512
#define DD   256
#define LL   2
#define HH   8
#define DH   32
#define FF_  1024
#define HALF_ 128

// ---------------- scratch (device global, no allocs) ----------------
#define OFF_H0    0
#define OFF_H     (OFF_H0 + NN*DD)
#define OFF_QKV   (OFF_H  + NN*DD)
#define OFF_ATTN  (OFF_QKV + NN*3*DD)
#define OFF_TMP   (OFF_ATTN + NN*DD)
#define OFF_FF    (OFF_TMP + NN*DD)
#define OFF_HC    (OFF_FF + NN*FF_)
#define OFF_WP1T  (OFF_HC + NN*DD)
#define SCRATCH_FLOATS (OFF_WP1T + 8*4096)

__device__ float g_scratch[SCRATCH_FLOATS];

// dynamic smem sizes
#define SGEMM_SMEM ((2*128*36 + 2*32*68) * 4)
#define ATTN_SMEM  ((2*64*35 + 2*64*36 + 8*16*68) * 4)
#define EDGE_SMEM  ((2*128*36 + 2*32*132) * 4)

// ---------------- TF32 / async helpers ----------------
__device__ __forceinline__ float f2tf32(float x) {
    unsigned r;
    asm("cvt.rna.tf32.f32 %0, %1;" : "=r"(r) : "f"(x));
    return __uint_as_float(r);
}

__device__ __forceinline__ void mma_tf32(float* d, const float* a, const float* b) {
    asm("mma.sync.aligned.m16n8k8.row.col.f32.tf32.tf32.f32 "
        "{%0,%1,%2,%3},{%4,%5,%6,%7},{%8,%9},{%0,%1,%2,%3};"
        : "+f"(d[0]), "+f"(d[1]), "+f"(d[2]), "+f"(d[3])
        : "r"(__float_as_uint(a[0])), "r"(__float_as_uint(a[1])),
          "r"(__float_as_uint(a[2])), "r"(__float_as_uint(a[3])),
          "r"(__float_as_uint(b[0])), "r"(__float_as_uint(b[1])));
}

__device__ __forceinline__ uint32_t smem_u32(const void* p) {
    uint32_t a;
    asm("{ .reg .u64 t; cvta.to.shared.u64 t, %1; cvt.u32.u64 %0, t; }" : "=r"(a) : "l"(p));
    return a;
}
__device__ __forceinline__ void cp_async16(uint32_t dst, const void* src) {
    asm volatile("cp.async.ca.shared.global [%0], [%1], 16;" :: "r"(dst), "l"(src));
}
__device__ __forceinline__ void cp_commit() {
    asm volatile("cp.async.commit_group;" ::: "memory");
}
__device__ __forceinline__ void cp_wait0() {
    asm volatile("cp.async.wait_group 0;" ::: "memory");
}

// ---------------- Wp1 prepass: tf32-round into B-tile layout ----------------
// wp1t[kt*4096 + k*128 + j] = tf32(Wp1[(kt*32+k)*128 + j]), kt<8, k<32, j<128
__global__ __launch_bounds__(256) void wp1_prep_kernel(
    const float* __restrict__ Wp1, float* __restrict__ wp1t)
{
    int idx = blockIdx.x * 256 + threadIdx.x;   // 0..32767, layout identical
    wp1t[idx] = f2tf32(Wp1[idx]);
}

// ---------------- TF32 tensor-core SGEMM, ping-pong prefetch ----------------
__global__ __launch_bounds__(256) void sgemm_tc_kernel(
    int M, int N, int K,
    const float* __restrict__ A, const float* __restrict__ B,
    const float* __restrict__ bias, float* __restrict__ C, int act)
{
    extern __shared__ float sm[];
    float* As_ = sm;
    float* Bs_ = sm + 2*128*36;
#define AS(bb,r,c) As_[(bb)*(128*36) + (r)*36 + (c)]
#define BS(bb,r,c) Bs_[(bb)*(32*68) + (r)*68 + (c)]

    const int tid  = threadIdx.x;
    const int lane = tid & 31;
    const int wid  = tid >> 5;
    const int wm   = wid >> 1;
    const int wn   = wid & 1;
    const int grp  = lane >> 2;
    const int tig  = lane & 3;

    const int bx = blockIdx.x, by = blockIdx.y;
    A += (size_t)by * 128 * K;
    B += (size_t)bx * 64;
    C += (size_t)by * 128 * N + (size_t)bx * 64;
    bias += (size_t)bx * 64;

    float acc[2][4][4] = {};
    float4 rA[4], rB[2];

    auto ldT = [&](int kt) {
        #pragma unroll
        for (int i = 0; i < 4; i++) {
            int f = tid + i * 256, r = f >> 3, c4 = f & 7;
            rA[i] = *reinterpret_cast<const float4*>(A + (size_t)r * K + kt + c4 * 4);
        }
        #pragma unroll
        for (int i = 0; i < 2; i++) {
            int f = tid + i * 256, r = f >> 4, c4 = f & 15;
            rB[i] = *reinterpret_cast<const float4*>(B + (size_t)(kt + r) * N + c4 * 4);
        }
    };
    auto stT = [&](int bb) {
        #pragma unroll
        for (int i = 0; i < 4; i++) {
            int f = tid + i * 256, r = f >> 3, c4 = f & 7;
            AS(bb,r,c4*4+0) = f2tf32(rA[i].x); AS(bb,r,c4*4+1) = f2tf32(rA[i].y);
            AS(bb,r,c4*4+2) = f2tf32(rA[i].z); AS(bb,r,c4*4+3) = f2tf32(rA[i].w);
        }
        #pragma unroll
        for (int i = 0; i < 2; i++) {
            int f = tid + i * 256, r = f >> 4, c4 = f & 15;
            BS(bb,r,c4*4+0) = f2tf32(rB[i].x); BS(bb,r,c4*4+1) = f2tf32(rB[i].y);
            BS(bb,r,c4*4+2) = f2tf32(rB[i].z); BS(bb,r,c4*4+3) = f2tf32(rB[i].w);
        }
    };

    const int T = K / 32;
    ldT(0); stT(0); __syncthreads();

    for (int t = 0; t < T; t++) {
        int cur = t & 1;
        if (t + 1 < T) ldT((t + 1) * 32);
        #pragma unroll
        for (int ks = 0; ks < 4; ks++) {
            int k0 = ks * 8 + tig;
            float a[2][4], b[4][2];
            #pragma unroll
            for (int mt = 0; mt < 2; mt++) {
                int row = wm * 32 + mt * 16 + grp;
                a[mt][0] = AS(cur,row,  k0);   a[mt][1] = AS(cur,row+8,k0);
                a[mt][2] = AS(cur,row,  k0+4); a[mt][3] = AS(cur,row+8,k0+4);
            }
            #pragma unroll
            for (int nt = 0; nt < 4; nt++) {
                int col = wn * 32 + nt * 8 + grp;
                b[nt][0] = BS(cur,k0,col); b[nt][1] = BS(cur,k0+4,col);
            }
            #pragma unroll
            for (int mt = 0; mt < 2; mt++)
                #pragma unroll
                for (int nt = 0; nt < 4; nt++)
                    mma_tf32(acc[mt][nt], a[mt], b[nt]);
        }
        if (t + 1 < T) stT((t + 1) & 1);
        __syncthreads();
    }

    #pragma unroll
    for (int mt = 0; mt < 2; mt++) {
        #pragma unroll
        for (int nt = 0; nt < 4; nt++) {
            int row = wm * 32 + mt * 16 + grp;
            int col = wn * 32 + nt * 8 + tig * 2;
            float b0 = bias[col], b1 = bias[col+1];
            float2 v0, v1;
            v0.x = acc[mt][nt][0] + b0; v0.y = acc[mt][nt][1] + b1;
            v1.x = acc[mt][nt][2] + b0; v1.y = acc[mt][nt][3] + b1;
            if (act == 1) {
                v0.x = fmaxf(v0.x, 0.f); v0.y = fmaxf(v0.y, 0.f);
                v1.x = fmaxf(v1.x, 0.f); v1.y = fmaxf(v1.y, 0.f);
            }
            *reinterpret_cast<float2*>(C + (size_t)row * N + col)     = v0;
            *reinterpret_cast<float2*>(C + (size_t)(row+8) * N + col) = v1;
        }
    }
#undef AS
#undef BS
}

// ---------------- TF32 MMA flash attention (unchanged from R6) ----------------
__global__ __launch_bounds__(256) void attn_tc_kernel(
    const float* __restrict__ qkv, float* __restrict__ out)
{
    extern __shared__ float sm[];
    float* Ks_ = sm;
    float* Vs_ = sm + 2*64*35;
    float* Ps_ = sm + 2*64*35 + 2*64*36;
#define KS(bb,r,c) Ks_[(bb)*(64*35) + (r)*35 + (c)]
#define VS(bb,r,c) Vs_[(bb)*(64*36) + (r)*36 + (c)]
#define PS(w,r,c)  Ps_[(w)*(16*68) + (r)*68 + (c)]

    const int h  = blockIdx.y;
    const int qb = blockIdx.x * 128;
    const int tid  = threadIdx.x;
    const int lane = tid & 31;
    const int wid  = tid >> 5;
    const int grp  = lane >> 2;
    const int tig  = lane & 3;
    const float scale = 0.17677669529663687f;

    float qa[4][4];
    {
        const float* q0 = qkv + (size_t)(qb + wid*16 + grp) * 768 + h * 32;
        const float* q1 = q0 + (size_t)8 * 768;
        #pragma unroll
        for (int ks = 0; ks < 4; ks++) {
            qa[ks][0] = f2tf32(q0[ks*8 + tig]     * scale);
            qa[ks][1] = f2tf32(q1[ks*8 + tig]     * scale);
            qa[ks][2] = f2tf32(q0[ks*8 + tig + 4] * scale);
            qa[ks][3] = f2tf32(q1[ks*8 + tig + 4] * scale);
        }
    }

    float m0 = -1e30f, m1 = -1e30f, l0 = 0.f, l1 = 0.f;
    float o[4][4] = {};
    float4 rk[2], rv[2];

    auto ldKV = [&](int kb) {
        #pragma unroll
        for (int i = 0; i < 2; i++) {
            int f = tid + i * 256, r = f >> 3, c4 = f & 7;
            const float* p = qkv + (size_t)(kb + r) * 768 + 256 + h * 32 + c4 * 4;
            rk[i] = *reinterpret_cast<const float4*>(p);
            rv[i] = *reinterpret_cast<const float4*>(p + 256);
        }
    };
    auto stKV = [&](int bb) {
        #pragma unroll
        for (int i = 0; i < 2; i++) {
            int f = tid + i * 256, r = f >> 3, c4 = f & 7;
            KS(bb,r,c4*4+0) = f2tf32(rk[i].x); KS(bb,r,c4*4+1) = f2tf32(rk[i].y);
            KS(bb,r,c4*4+2) = f2tf32(rk[i].z); KS(bb,r,c4*4+3) = f2tf32(rk[i].w);
            VS(bb,r,c4*4+0) = f2tf32(rv[i].x); VS(bb,r,c4*4+1) = f2tf32(rv[i].y);
            VS(bb,r,c4*4+2) = f2tf32(rv[i].z); VS(bb,r,c4*4+3) = f2tf32(rv[i].w);
        }
    };

    ldKV(0); stKV(0); __syncthreads();

    for (int t = 0; t < NN/64; t++) {
        int cur = t & 1;
        if (t < NN/64 - 1) ldKV((t + 1) * 64);

        float sacc[8][4] = {};
        #pragma unroll
        for (int ks = 0; ks < 4; ks++) {
            #pragma unroll
            for (int nt = 0; nt < 8; nt++) {
                float b[2];
                b[0] = KS(cur, nt*8 + grp, ks*8 + tig);
                b[1] = KS(cur, nt*8 + grp, ks*8 + tig + 4);
                mma_tf32(sacc[nt], qa[ks], b);
            }
        }

        float rmax0 = -1e30f, rmax1 = -1e30f;
        #pragma unroll
        for (int nt = 0; nt < 8; nt++) {
            rmax0 = fmaxf(rmax0, fmaxf(sacc[nt][0], sacc[nt][1]));
            rmax1 = fmaxf(rmax1, fmaxf(sacc[nt][2], sacc[nt][3]));
        }
        rmax0 = fmaxf(rmax0, __shfl_xor_sync(0xffffffffu, rmax0, 1));
        rmax0 = fmaxf(rmax0, __shfl_xor_sync(0xffffffffu, rmax0, 2));
        rmax1 = fmaxf(rmax1, __shfl_xor_sync(0xffffffffu, rmax1, 1));
        rmax1 = fmaxf(rmax1, __shfl_xor_sync(0xffffffffu, rmax1, 2));
        float mn0 = fmaxf(m0, rmax0), mn1 = fmaxf(m1, rmax1);
        float a0 = __expf(m0 - mn0), a1 = __expf(m1 - mn1);
        float ps0 = 0.f, ps1 = 0.f;
        #pragma unroll
        for (int nt = 0; nt < 8; nt++) {
            float p00 = __expf(sacc[nt][0] - mn0);
            float p01 = __expf(sacc[nt][1] - mn0);
            float p10 = __expf(sacc[nt][2] - mn1);
            float p11 = __expf(sacc[nt][3] - mn1);
            ps0 += p00 + p01; ps1 += p10 + p11;
            PS(wid, grp,   nt*8 + tig*2    ) = p00;
            PS(wid, grp,   nt*8 + tig*2 + 1) = p01;
            PS(wid, grp+8, nt*8 + tig*2    ) = p10;
            PS(wid, grp+8, nt*8 + tig*2 + 1) = p11;
        }
        ps0 += __shfl_xor_sync(0xffffffffu, ps0, 1);
        ps0 += __shfl_xor_sync(0xffffffffu, ps0, 2);
        ps1 += __shfl_xor_sync(0xffffffffu, ps1, 1);
        ps1 += __shfl_xor_sync(0xffffffffu, ps1, 2);
        l0 = l0 * a0 + ps0; l1 = l1 * a1 + ps1;
        m0 = mn0; m1 = mn1;
        #pragma unroll
        for (int nt = 0; nt < 4; nt++) {
            o[nt][0] *= a0; o[nt][1] *= a0;
            o[nt][2] *= a1; o[nt][3] *= a1;
        }
        __syncwarp();

        #pragma unroll
        for (int ks = 0; ks < 8; ks++) {
            float a[4];
            a[0] = PS(wid, grp,   ks*8 + tig);
            a[1] = PS(wid, grp+8, ks*8 + tig);
            a[2] = PS(wid, grp,   ks*8 + tig + 4);
            a[3] = PS(wid, grp+8, ks*8 + tig + 4);
            #pragma unroll
            for (int nt = 0; nt < 4; nt++) {
                float b[2];
                b[0] = VS(cur, ks*8 + tig,     nt*8 + grp);
                b[1] = VS(cur, ks*8 + tig + 4, nt*8 + grp);
                mma_tf32(o[nt], a, b);
            }
        }
        __syncwarp();

        if (t < NN/64 - 1) stKV((t + 1) & 1);
        __syncthreads();
    }

    float inv0 = 1.f / l0, inv1 = 1.f / l1;
    int r0 = qb + wid*16 + grp;
    #pragma unroll
    for (int nt = 0; nt < 4; nt++) {
        int col = h * 32 + nt * 8 + tig * 2;
        *reinterpret_cast<float2*>(out + (size_t)r0 * 256 + col) =
            make_float2(o[nt][0] * inv0, o[nt][1] * inv0);
        *reinterpret_cast<float2*>(out + (size_t)(r0 + 8) * 256 + col) =
            make_float2(o[nt][2] * inv1, o[nt][3] * inv1);
    }
#undef KS
#undef VS
#undef PS
}

// ---------------- fused residual-add + LayerNorm (warp per row) ----------------
__global__ __launch_bounds__(256) void add_ln_kernel(
    const float* __restrict__ x, const float* __restrict__ y,
    const float* __restrict__ g, const float* __restrict__ b,
    float* __restrict__ out)
{
    int row = blockIdx.x * 8 + (threadIdx.x >> 5);
    int lid = threadIdx.x & 31;
    const float* xr = x + (size_t)row * 256;
    const float* yr = y + (size_t)row * 256;

    float4 v0 = *reinterpret_cast<const float4*>(xr + lid*4);
    float4 w0 = *reinterpret_cast<const float4*>(yr + lid*4);
    float4 v1 = *reinterpret_cast<const float4*>(xr + 128 + lid*4);
    float4 w1 = *reinterpret_cast<const float4*>(yr + 128 + lid*4);
    float a[8] = { v0.x+w0.x, v0.y+w0.y, v0.z+w0.z, v0.w+w0.w,
                   v1.x+w1.x, v1.y+w1.y, v1.z+w1.z, v1.w+w1.w };

    float s = 0.f;
    #pragma unroll
    for (int i = 0; i < 8; i++) s += a[i];
    #pragma unroll
    for (int o2 = 16; o2 > 0; o2 >>= 1) s += __shfl_xor_sync(0xffffffffu, s, o2);
    float mean = s * (1.f/256.f);

    float q = 0.f;
    #pragma unroll
    for (int i = 0; i < 8; i++) { float d = a[i] - mean; q += d*d; }
    #pragma unroll
    for (int o2 = 16; o2 > 0; o2 >>= 1) q += __shfl_xor_sync(0xffffffffu, q, o2);
    float rstd = rsqrtf(q * (1.f/256.f) + 1e-5f);

    float4 g0 = *reinterpret_cast<const float4*>(g + lid*4);
    float4 b0 = *reinterpret_cast<const float4*>(b + lid*4);
    float4 g1 = *reinterpret_cast<const float4*>(g + 128 + lid*4);
    float4 b1 = *reinterpret_cast<const float4*>(b + 128 + lid*4);
    float4 r0, r1;
    r0.x = (a[0]-mean)*rstd*g0.x + b0.x; r0.y = (a[1]-mean)*rstd*g0.y + b0.y;
    r0.z = (a[2]-mean)*rstd*g0.z + b0.z; r0.w = (a[3]-mean)*rstd*g0.w + b0.w;
    r1.x = (a[4]-mean)*rstd*g1.x + b1.x; r1.y = (a[5]-mean)*rstd*g1.y + b1.y;
    r1.z = (a[6]-mean)*rstd*g1.z + b1.z; r1.w = (a[7]-mean)*rstd*g1.w + b1.w;
    *reinterpret_cast<float4*>(out + (size_t)row*256 + lid*4)       = r0;
    *reinterpret_cast<float4*>(out + (size_t)row*256 + 128 + lid*4) = r1;
}

// ---------------- h_combined = h + h0 ----------------
__global__ __launch_bounds__(256) void hc_kernel(
    const float* __restrict__ h, const float* __restrict__ h0,
    float* __restrict__ hc, float* __restrict__ out_tail)
{
    int idx = blockIdx.x * 256 + threadIdx.x;
    float v = h[idx] + h0[idx];
    hc[idx] = v;
    out_tail[idx] = v;
}

// ---------------- fused edge predictor: cp.async B tiles + ping-pong A ----------------
// One launch covers pos (blocks [0,nblk)) and neg (blocks [nblk,2*nblk)).
// B tiles come pre-converted/pre-laid-out from wp1t via cp.async.
__global__ __launch_bounds__(256) void edge_tc_kernel(
    const float* __restrict__ hc,
    const int* __restrict__ psrc, const int* __restrict__ pdst, const float* __restrict__ pw,
    const int* __restrict__ nsrc, const int* __restrict__ ndst, const float* __restrict__ nw,
    const float* __restrict__ wp1t, const float* __restrict__ bp1,
    const float* __restrict__ Wp2, const float* __restrict__ bp2,
    float* __restrict__ out, int E, int nblk)
{
    extern __shared__ float sm[];
    float* As_ = sm;                  // [2][128][36]
    float* Bs_ = sm + 2*128*36;       // [2][32][132]
#define EAS(bb,r,c) As_[(bb)*(128*36) + (r)*36 + (c)]
#define EBS(bb,r,c) Bs_[(bb)*(32*132) + (r)*132 + (c)]
    __shared__ int   sSrc[128], sDst[128];
    __shared__ float sW[128], sWp2[128], sBp1[128];
    __shared__ float sred[128][2];

    const int tid  = threadIdx.x;
    const int lane = tid & 31;
    const int wid  = tid >> 5;
    const int wm   = wid >> 1;
    const int wn   = wid & 1;
    const int grp  = lane >> 2;
    const int tig  = lane & 3;

    const int pol  = (blockIdx.x >= nblk) ? 1 : 0;
    const int blk  = blockIdx.x - pol * nblk;
    const int e0   = blk * 128;
    const int* srcA = pol ? nsrc : psrc;
    const int* dstA = pol ? ndst : pdst;
    const float* wA = pol ? nw   : pw;
    float* op = out + (pol ? (size_t)E : 0);

    const uint32_t bs_u32 = smem_u32(Bs_);

    if (tid < 128) {
        int e = e0 + tid;
        if (e < E) { sSrc[tid] = srcA[e]; sDst[tid] = dstA[e]; sW[tid] = wA[e]; }
        else       { sSrc[tid] = 0;       sDst[tid] = 0;       sW[tid] = 0.f; }
        sWp2[tid] = Wp2[tid];
        sBp1[tid] = bp1[tid];
    }
    __syncthreads();

    float acc[2][8][4] = {};
    float4 ga[4], gb[4];

    // async copy of B tile kt into buffer bb (pre-converted, pre-laid-out)
    auto cpB = [&](int bb, int kt) {
        #pragma unroll
        for (int i = 0; i < 4; i++) {
            int f = tid + i * 256, r = f >> 5, c4 = f & 31;
            uint32_t dst = bs_u32 + (uint32_t)(bb * (32*132) + r * 132 + c4 * 4) * 4;
            cp_async16(dst, wp1t + (size_t)kt * 4096 + r * 128 + c4 * 4);
        }
        cp_commit();
    };
    auto ldA = [&](int kt) {
        #pragma unroll
        for (int i = 0; i < 4; i++) {
            int f = tid + i * 256, e = f >> 3, c4 = f & 7;
            ga[i] = *reinterpret_cast<const float4*>(hc + (size_t)sSrc[e]*256 + kt*32 + c4*4);
            gb[i] = *reinterpret_cast<const float4*>(hc + (size_t)sDst[e]*256 + kt*32 + c4*4);
        }
    };
    auto stA = [&](int bb) {
        #pragma unroll
        for (int i = 0; i < 4; i++) {
            int f = tid + i * 256, e = f >> 3, c4 = f & 7;
            float ww = sW[e];
            EAS(bb,e,c4*4+0) = f2tf32(ga[i].x * gb[i].x * ww);
            EAS(bb,e,c4*4+1) = f2tf32(ga[i].y * gb[i].y * ww);
            EAS(bb,e,c4*4+2) = f2tf32(ga[i].z * gb[i].z * ww);
            EAS(bb,e,c4*4+3) = f2tf32(ga[i].w * gb[i].w * ww);
        }
    };

    cpB(0, 0);
    ldA(0);
    cp_wait0();
    stA(0);
    __syncthreads();

    for (int t = 0; t < 8; t++) {
        int cur = t & 1;
        if (t < 7) { cpB(cur ^ 1, t + 1); ldA(t + 1); }
        #pragma unroll
        for (int ks = 0; ks < 4; ks++) {
            int k0 = ks * 8 + tig;
            float a[2][4], b[8][2];
            #pragma unroll
            for (int mt = 0; mt < 2; mt++) {
                int row = wm * 32 + mt * 16 + grp;
                a[mt][0] = EAS(cur,row,  k0);   a[mt][1] = EAS(cur,row+8,k0);
                a[mt][2] = EAS(cur,row,  k0+4); a[mt][3] = EAS(cur,row+8,k0+4);
            }
            #pragma unroll
            for (int nt = 0; nt < 8; nt++) {
                int col = wn * 64 + nt * 8 + grp;
                b[nt][0] = EBS(cur,k0,col); b[nt][1] = EBS(cur,k0+4,col);
            }
            #pragma unroll
            for (int mt = 0; mt < 2; mt++)
                #pragma unroll
                for (int nt = 0; nt < 8; nt++)
                    mma_tf32(acc[mt][nt], a[mt], b[nt]);
        }
        if (t < 7) { cp_wait0(); stA(cur ^ 1); }
        __syncthreads();
    }

    // epilogue: leaky(acc + bp1) . Wp2
    #pragma unroll
    for (int mt = 0; mt < 2; mt++) {
        float p0 = 0.f, p1 = 0.f;
        #pragma unroll
        for (int nt = 0; nt < 8; nt++) {
            int col = wn * 64 + nt * 8 + tig * 2;
            float bb0 = sBp1[col], bb1 = sBp1[col+1];
            float w0  = sWp2[col], w1  = sWp2[col+1];
            float y;
            y = acc[mt][nt][0] + bb0; y = (y > 0.f) ? y : 0.2f*y; p0 += y * w0;
            y = acc[mt][nt][1] + bb1; y = (y > 0.f) ? y : 0.2f*y; p0 += y * w1;
            y = acc[mt][nt][2] + bb0; y = (y > 0.f) ? y : 0.2f*y; p1 += y * w0;
            y = acc[mt][nt][3] + bb1; y = (y > 0.f) ? y : 0.2f*y; p1 += y * w1;
        }
        p0 += __shfl_xor_sync(0xffffffffu, p0, 1);
        p0 += __shfl_xor_sync(0xffffffffu, p0, 2);
        p1 += __shfl_xor_sync(0xffffffffu, p1, 1);
        p1 += __shfl_xor_sync(0xffffffffu, p1, 2);
        if (tig == 0) {
            int r0 = wm * 32 + mt * 16 + grp;
            sred[r0    ][wn] = p0;
            sred[r0 + 8][wn] = p1;
        }
    }
    __syncthreads();

    if (tid < 128) {
        int e = e0 + tid;
        if (e < E) op[e] = sred[tid][0] + sred[tid][1] + bp2[0];
    }
#undef EAS
#undef EBS
}

// ---------------- host orchestration ----------------
extern "C" void kernel_launch(void* const* d_in, const int* in_sizes, int n_in,
                              void* d_out, int out_size)
{
    const float* x        = (const float*)d_in[0];
    const int*   pos_src  = (const int*)  d_in[1];
    const int*   pos_dst  = (const int*)  d_in[2];
    const float* pos_w    = (const float*)d_in[3];
    const int*   neg_src  = (const int*)  d_in[4];
    const int*   neg_dst  = (const int*)  d_in[5];
    const float* neg_w    = (const float*)d_in[6];
    const float* Wi       = (const float*)d_in[7];
    const float* bi       = (const float*)d_in[8];
    const float* Wqkv     = (const float*)d_in[9];
    const float* bqkv     = (const float*)d_in[10];
    const float* Wo       = (const float*)d_in[11];
    const float* bo       = (const float*)d_in[12];
    const float* g1       = (const float*)d_in[13];
    const float* be1      = (const float*)d_in[14];
    const float* g2       = (const float*)d_in[15];
    const float* be2      = (const float*)d_in[16];
    const float* W1       = (const float*)d_in[17];
    const float* b1       = (const float*)d_in[18];
    const float* W2       = (const float*)d_in[19];
    const float* b2       = (const float*)d_in[20];
    const float* Wp1      = (const float*)d_in[21];
    const float* bp1      = (const float*)d_in[22];
    const float* Wp2      = (const float*)d_in[23];
    const float* bp2      = (const float*)d_in[24];

    const int E = in_sizes[1];   // 500000

    cudaFuncSetAttribute(sgemm_tc_kernel, cudaFuncAttributeMaxDynamicSharedMemorySize, SGEMM_SMEM);
    cudaFuncSetAttribute(attn_tc_kernel,  cudaFuncAttributeMaxDynamicSharedMemorySize, ATTN_SMEM);
    cudaFuncSetAttribute(edge_tc_kernel,  cudaFuncAttributeMaxDynamicSharedMemorySize, EDGE_SMEM);

    float* S = nullptr;
    cudaGetSymbolAddress((void**)&S, g_scratch);
    float* h0   = S + OFF_H0;
    float* h    = S + OFF_H;
    float* qkv  = S + OFF_QKV;
    float* attn = S + OFF_ATTN;
    float* tmp  = S + OFF_TMP;
    float* ff   = S + OFF_FF;
    float* hc   = S + OFF_HC;
    float* wp1t = S + OFF_WP1T;
    float* out  = (float*)d_out;

    // prepass: tf32-rounded Wp1 in B-tile layout
    wp1_prep_kernel<<<128, 256>>>(Wp1, wp1t);

    // h0 = x @ Wi + bi
    sgemm_tc_kernel<<<dim3(DD/64, NN/128), 256, SGEMM_SMEM>>>(NN, DD, INF_, x, Wi, bi, h0, 0);

    for (int l = 0; l < LL; l++) {
        const float* hin = (l == 0) ? h0 : h;
        sgemm_tc_kernel<<<dim3(768/64, NN/128), 256, SGEMM_SMEM>>>(NN, 768, DD,
            hin, Wqkv + (size_t)l*DD*768, bqkv + (size_t)l*768, qkv, 0);
        attn_tc_kernel<<<dim3(NN/128, HH), 256, ATTN_SMEM>>>(qkv, attn);
        sgemm_tc_kernel<<<dim3(DD/64, NN/128), 256, SGEMM_SMEM>>>(NN, DD, DD,
            attn, Wo + (size_t)l*DD*DD, bo + (size_t)l*DD, tmp, 0);
        add_ln_kernel<<<NN/8, 256>>>(hin, tmp, g1 + (size_t)l*DD, be1 + (size_t)l*DD, h);
        sgemm_tc_kernel<<<dim3(FF_/64, NN/128), 256, SGEMM_SMEM>>>(NN, FF_, DD,
            h, W1 + (size_t)l*DD*FF_, b1 + (size_t)l*FF_, ff, 1);
        sgemm_tc_kernel<<<dim3(DD/64, NN/128), 256, SGEMM_SMEM>>>(NN, DD, FF_,
            ff, W2 + (size_t)l*FF_*DD, b2 + (size_t)l*DD, tmp, 0);
        add_ln_kernel<<<NN/8, 256>>>(h, tmp, g2 + (size_t)l*DD, be2 + (size_t)l*DD, h);
    }

    hc_kernel<<<NN*DD/256, 256>>>(h, h0, hc, out + 2*(size_t)E);

    // single-launch edge predictor (pos + neg)
    const int nblk = (E + 127) / 128;
    edge_tc_kernel<<<2*nblk, 256, EDGE_SMEM>>>(
        hc, pos_src, pos_dst, pos_w, neg_src, neg_dst, neg_w,
        wp1t, bp1, Wp2, bp2, out, E, nblk);
}

// round 9
// speedup vs baseline: 4.9201x; 1.5131x over previous
#include <cuda_runtime.h>
#include <cuda_fp16.h>
#include <math.h>
#include <stdint.h>

// ---------------- problem constants ----------------
#define NN   4096
#define INF_ 512
#define DD   256
#define LL   2
#define HH   8
#define DH   32
#define FF_  1024
#define HALF_ 128

// ---------------- scratch (device global, no allocs) ----------------
#define OFF_H0    0
#define OFF_H     (OFF_H0 + NN*DD)
#define OFF_QKV   (OFF_H  + NN*DD)
#define OFF_ATTN  (OFF_QKV + NN*3*DD)
#define OFF_TMP   (OFF_ATTN + NN*DD)
#define OFF_FF    (OFF_TMP + NN*DD)
#define OFF_HC    (OFF_FF + NN*FF_)
#define OFF_WP1T  (OFF_HC + NN*DD)
#define SCRATCH_FLOATS (OFF_WP1T + 8*4096)

__device__ float g_scratch[SCRATCH_FLOATS];

// dynamic smem sizes (bytes)
#define SGEMM_SMEM ((2*128*40 + 2*64*40) * 2)
#define ATTN_SMEM  ((2*64*40 + 2*32*72 + 8*16*72) * 2)
#define EDGE_SMEM  ((2*128*40 + 2*128*40) * 2)

// ---------------- fp16 MMA helpers ----------------
__device__ __forceinline__ uint32_t pack_h2(float lo, float hi) {
    __half2 h = __floats2half2_rn(lo, hi);
    return *reinterpret_cast<uint32_t*>(&h);
}

// m16n8k16 row.col f32.f16.f16.f32
__device__ __forceinline__ void mma_f16(float* d, const uint32_t* a, const uint32_t* b) {
    asm("mma.sync.aligned.m16n8k16.row.col.f32.f16.f16.f32 "
        "{%0,%1,%2,%3},{%4,%5,%6,%7},{%8,%9},{%0,%1,%2,%3};"
        : "+f"(d[0]), "+f"(d[1]), "+f"(d[2]), "+f"(d[3])
        : "r"(a[0]), "r"(a[1]), "r"(a[2]), "r"(a[3]), "r"(b[0]), "r"(b[1]));
}

__device__ __forceinline__ uint32_t smem_u32(const void* p) {
    uint32_t a;
    asm("{ .reg .u64 t; cvta.to.shared.u64 t, %1; cvt.u32.u64 %0, t; }" : "=r"(a) : "l"(p));
    return a;
}
__device__ __forceinline__ void cp_async16(uint32_t dst, const void* src) {
    asm volatile("cp.async.ca.shared.global [%0], [%1], 16;" :: "r"(dst), "l"(src));
}
__device__ __forceinline__ void cp_commit() {
    asm volatile("cp.async.commit_group;" ::: "memory");
}
__device__ __forceinline__ void cp_wait0() {
    asm volatile("cp.async.wait_group 0;" ::: "memory");
}

// ---------------- Wp1 prepass: half, transposed [j][k] ----------------
__global__ __launch_bounds__(256) void wp1_prep_kernel(
    const float* __restrict__ Wp1, __half* __restrict__ wp1t)
{
    int idx = blockIdx.x * 256 + threadIdx.x;   // 0..32767
    int k = idx >> 7, j = idx & 127;
    wp1t[j * 256 + k] = __float2half_rn(Wp1[idx]);
}

// ---------------- fp16 tensor-core SGEMM, ping-pong prefetch ----------------
// C = A@B + bias, optional ReLU. BM=128, BN=64, BK=32. 8 warps (4m x 2n).
// As [2][128][40] half ([m][k]); Bs [2][64][40] half ([n][k], transposed on store).
__global__ __launch_bounds__(256) void sgemm_tc_kernel(
    int M, int N, int K,
    const float* __restrict__ A, const float* __restrict__ B,
    const float* __restrict__ bias, float* __restrict__ C, int act)
{
    extern __shared__ __align__(16) char smraw[];
    __half* As_ = (__half*)smraw;                   // [2][128][40]
    __half* Bs_ = (__half*)(smraw + 2*128*40*2);    // [2][64][40]

    const int tid  = threadIdx.x;
    const int lane = tid & 31;
    const int wid  = tid >> 5;
    const int wm   = wid >> 1;
    const int wn   = wid & 1;
    const int grp  = lane >> 2;
    const int tig  = lane & 3;

    const int bx = blockIdx.x, by = blockIdx.y;
    A += (size_t)by * 128 * K;
    B += (size_t)bx * 64;
    C += (size_t)by * 128 * N + (size_t)bx * 64;
    bias += (size_t)bx * 64;

    float acc[2][4][4] = {};
    float4 rA[4], rB[2];

    auto ldT = [&](int kt) {
        #pragma unroll
        for (int i = 0; i < 4; i++) {
            int f = tid + i * 256, r = f >> 3, c4 = f & 7;
            rA[i] = *reinterpret_cast<const float4*>(A + (size_t)r * K + kt + c4 * 4);
        }
        #pragma unroll
        for (int i = 0; i < 2; i++) {
            int f = tid + i * 256, r = f >> 4, c4 = f & 15;
            rB[i] = *reinterpret_cast<const float4*>(B + (size_t)(kt + r) * N + c4 * 4);
        }
    };
    auto stT = [&](int bb) {
        #pragma unroll
        for (int i = 0; i < 4; i++) {
            int f = tid + i * 256, r = f >> 3, c4 = f & 7;
            uint2 u;
            u.x = pack_h2(rA[i].x, rA[i].y);
            u.y = pack_h2(rA[i].z, rA[i].w);
            *reinterpret_cast<uint2*>(&As_[bb*(128*40) + r*40 + c4*4]) = u;
        }
        #pragma unroll
        for (int i = 0; i < 2; i++) {
            int f = tid + i * 256, r = f >> 4, c4 = f & 15;
            __half* bp = &Bs_[bb*(64*40)];
            bp[(c4*4+0)*40 + r] = __float2half_rn(rB[i].x);
            bp[(c4*4+1)*40 + r] = __float2half_rn(rB[i].y);
            bp[(c4*4+2)*40 + r] = __float2half_rn(rB[i].z);
            bp[(c4*4+3)*40 + r] = __float2half_rn(rB[i].w);
        }
    };

    const int T = K / 32;
    ldT(0); stT(0); __syncthreads();

    for (int t = 0; t < T; t++) {
        int cur = t & 1;
        if (t + 1 < T) ldT((t + 1) * 32);
        #pragma unroll
        for (int ks = 0; ks < 2; ks++) {
            int k0 = ks * 16 + 2 * tig;
            uint32_t a[2][4], b[4][2];
            #pragma unroll
            for (int mt = 0; mt < 2; mt++) {
                int row = wm * 32 + mt * 16 + grp;
                const __half* ap = &As_[cur*(128*40)];
                a[mt][0] = *reinterpret_cast<const uint32_t*>(&ap[row*40 + k0]);
                a[mt][1] = *reinterpret_cast<const uint32_t*>(&ap[(row+8)*40 + k0]);
                a[mt][2] = *reinterpret_cast<const uint32_t*>(&ap[row*40 + k0 + 8]);
                a[mt][3] = *reinterpret_cast<const uint32_t*>(&ap[(row+8)*40 + k0 + 8]);
            }
            #pragma unroll
            for (int nt = 0; nt < 4; nt++) {
                int col = wn * 32 + nt * 8 + grp;
                const __half* bp = &Bs_[cur*(64*40)];
                b[nt][0] = *reinterpret_cast<const uint32_t*>(&bp[col*40 + k0]);
                b[nt][1] = *reinterpret_cast<const uint32_t*>(&bp[col*40 + k0 + 8]);
            }
            #pragma unroll
            for (int mt = 0; mt < 2; mt++)
                #pragma unroll
                for (int nt = 0; nt < 4; nt++)
                    mma_f16(acc[mt][nt], a[mt], b[nt]);
        }
        if (t + 1 < T) stT((t + 1) & 1);
        __syncthreads();
    }

    #pragma unroll
    for (int mt = 0; mt < 2; mt++) {
        #pragma unroll
        for (int nt = 0; nt < 4; nt++) {
            int row = wm * 32 + mt * 16 + grp;
            int col = wn * 32 + nt * 8 + tig * 2;
            float b0 = bias[col], b1 = bias[col+1];
            float2 v0, v1;
            v0.x = acc[mt][nt][0] + b0; v0.y = acc[mt][nt][1] + b1;
            v1.x = acc[mt][nt][2] + b0; v1.y = acc[mt][nt][3] + b1;
            if (act == 1) {
                v0.x = fmaxf(v0.x, 0.f); v0.y = fmaxf(v0.y, 0.f);
                v1.x = fmaxf(v1.x, 0.f); v1.y = fmaxf(v1.y, 0.f);
            }
            *reinterpret_cast<float2*>(C + (size_t)row * N + col)     = v0;
            *reinterpret_cast<float2*>(C + (size_t)(row+8) * N + col) = v1;
        }
    }
}

// ---------------- fp16 MMA flash attention ----------------
// grid (NN/128, HH), 256 threads = 8 warps, warp owns 16 query rows.
// Ks [2][64][40] ([kv][d]); Vs [2][32][72] (transposed: [d][kv]); Ps [8][16][72].
__global__ __launch_bounds__(256) void attn_tc_kernel(
    const float* __restrict__ qkv, float* __restrict__ out)
{
    extern __shared__ __align__(16) char smraw[];
    __half* Ks_ = (__half*)smraw;                                  // [2][64][40]
    __half* Vs_ = (__half*)(smraw + 2*64*40*2);                    // [2][32][72]
    __half* Ps_ = (__half*)(smraw + (2*64*40 + 2*32*72)*2);        // [8][16][72]

    const int h  = blockIdx.y;
    const int qb = blockIdx.x * 128;
    const int tid  = threadIdx.x;
    const int lane = tid & 31;
    const int wid  = tid >> 5;
    const int grp  = lane >> 2;
    const int tig  = lane & 3;
    const float scale = 0.17677669529663687f;   // 1/sqrt(32)

    // Q fragments (scale folded), packed half2: 2 k-steps of 16
    uint32_t qa[2][4];
    {
        const float* q0 = qkv + (size_t)(qb + wid*16 + grp) * 768 + h * 32;
        const float* q1 = q0 + (size_t)8 * 768;
        #pragma unroll
        for (int ks = 0; ks < 2; ks++) {
            int b = ks * 16 + 2 * tig;
            qa[ks][0] = pack_h2(q0[b]   * scale, q0[b+1] * scale);
            qa[ks][1] = pack_h2(q1[b]   * scale, q1[b+1] * scale);
            qa[ks][2] = pack_h2(q0[b+8] * scale, q0[b+9] * scale);
            qa[ks][3] = pack_h2(q1[b+8] * scale, q1[b+9] * scale);
        }
    }

    float m0 = -1e30f, m1 = -1e30f, l0 = 0.f, l1 = 0.f;
    float o[4][4] = {};
    float4 rk[2], rv[2];

    auto ldKV = [&](int kb) {
        #pragma unroll
        for (int i = 0; i < 2; i++) {
            int f = tid + i * 256, r = f >> 3, c4 = f & 7;
            const float* p = qkv + (size_t)(kb + r) * 768 + 256 + h * 32 + c4 * 4;
            rk[i] = *reinterpret_cast<const float4*>(p);
            rv[i] = *reinterpret_cast<const float4*>(p + 256);
        }
    };
    auto stKV = [&](int bb) {
        #pragma unroll
        for (int i = 0; i < 2; i++) {
            int f = tid + i * 256, r = f >> 3, c4 = f & 7;
            uint2 u;
            u.x = pack_h2(rk[i].x, rk[i].y);
            u.y = pack_h2(rk[i].z, rk[i].w);
            *reinterpret_cast<uint2*>(&Ks_[bb*(64*40) + r*40 + c4*4]) = u;
            __half* vp = &Vs_[bb*(32*72)];
            vp[(c4*4+0)*72 + r] = __float2half_rn(rv[i].x);
            vp[(c4*4+1)*72 + r] = __float2half_rn(rv[i].y);
            vp[(c4*4+2)*72 + r] = __float2half_rn(rv[i].z);
            vp[(c4*4+3)*72 + r] = __float2half_rn(rv[i].w);
        }
    };

    ldKV(0); stKV(0); __syncthreads();

    for (int t = 0; t < NN/64; t++) {
        int cur = t & 1;
        if (t < NN/64 - 1) ldKV((t + 1) * 64);

        // S = Q @ K^T : 16 rows x 64 kv
        float sacc[8][4] = {};
        #pragma unroll
        for (int ks = 0; ks < 2; ks++) {
            int k0 = ks * 16 + 2 * tig;
            #pragma unroll
            for (int nt = 0; nt < 8; nt++) {
                const __half* kp = &Ks_[cur*(64*40) + (nt*8+grp)*40];
                uint32_t b[2];
                b[0] = *reinterpret_cast<const uint32_t*>(&kp[k0]);
                b[1] = *reinterpret_cast<const uint32_t*>(&kp[k0 + 8]);
                mma_f16(sacc[nt], qa[ks], b);
            }
        }

        // online softmax
        float rmax0 = -1e30f, rmax1 = -1e30f;
        #pragma unroll
        for (int nt = 0; nt < 8; nt++) {
            rmax0 = fmaxf(rmax0, fmaxf(sacc[nt][0], sacc[nt][1]));
            rmax1 = fmaxf(rmax1, fmaxf(sacc[nt][2], sacc[nt][3]));
        }
        rmax0 = fmaxf(rmax0, __shfl_xor_sync(0xffffffffu, rmax0, 1));
        rmax0 = fmaxf(rmax0, __shfl_xor_sync(0xffffffffu, rmax0, 2));
        rmax1 = fmaxf(rmax1, __shfl_xor_sync(0xffffffffu, rmax1, 1));
        rmax1 = fmaxf(rmax1, __shfl_xor_sync(0xffffffffu, rmax1, 2));
        float mn0 = fmaxf(m0, rmax0), mn1 = fmaxf(m1, rmax1);
        float a0 = __expf(m0 - mn0), a1 = __expf(m1 - mn1);
        float ps0 = 0.f, ps1 = 0.f;
        __half* pw = &Ps_[wid*(16*72)];
        #pragma unroll
        for (int nt = 0; nt < 8; nt++) {
            float p00 = __expf(sacc[nt][0] - mn0);
            float p01 = __expf(sacc[nt][1] - mn0);
            float p10 = __expf(sacc[nt][2] - mn1);
            float p11 = __expf(sacc[nt][3] - mn1);
            ps0 += p00 + p01; ps1 += p10 + p11;
            *reinterpret_cast<uint32_t*>(&pw[grp*72     + nt*8 + 2*tig]) = pack_h2(p00, p01);
            *reinterpret_cast<uint32_t*>(&pw[(grp+8)*72 + nt*8 + 2*tig]) = pack_h2(p10, p11);
        }
        ps0 += __shfl_xor_sync(0xffffffffu, ps0, 1);
        ps0 += __shfl_xor_sync(0xffffffffu, ps0, 2);
        ps1 += __shfl_xor_sync(0xffffffffu, ps1, 1);
        ps1 += __shfl_xor_sync(0xffffffffu, ps1, 2);
        l0 = l0 * a0 + ps0; l1 = l1 * a1 + ps1;
        m0 = mn0; m1 = mn1;
        #pragma unroll
        for (int nt = 0; nt < 4; nt++) {
            o[nt][0] *= a0; o[nt][1] *= a0;
            o[nt][2] *= a1; o[nt][3] *= a1;
        }
        __syncwarp();

        // O += P @ V   (A = P [16][64], B = V^T [d][kv])
        #pragma unroll
        for (int ks = 0; ks < 4; ks++) {
            int k0 = ks * 16 + 2 * tig;
            uint32_t a[4];
            a[0] = *reinterpret_cast<const uint32_t*>(&pw[grp*72     + k0]);
            a[1] = *reinterpret_cast<const uint32_t*>(&pw[(grp+8)*72 + k0]);
            a[2] = *reinterpret_cast<const uint32_t*>(&pw[grp*72     + k0 + 8]);
            a[3] = *reinterpret_cast<const uint32_t*>(&pw[(grp+8)*72 + k0 + 8]);
            #pragma unroll
            for (int nt = 0; nt < 4; nt++) {
                const __half* vp = &Vs_[cur*(32*72) + (nt*8+grp)*72];
                uint32_t b[2];
                b[0] = *reinterpret_cast<const uint32_t*>(&vp[k0]);
                b[1] = *reinterpret_cast<const uint32_t*>(&vp[k0 + 8]);
                mma_f16(o[nt], a, b);
            }
        }
        __syncwarp();

        if (t < NN/64 - 1) stKV((t + 1) & 1);
        __syncthreads();
    }

    float inv0 = 1.f / l0, inv1 = 1.f / l1;
    int r0 = qb + wid*16 + grp;
    #pragma unroll
    for (int nt = 0; nt < 4; nt++) {
        int col = h * 32 + nt * 8 + tig * 2;
        *reinterpret_cast<float2*>(out + (size_t)r0 * 256 + col) =
            make_float2(o[nt][0] * inv0, o[nt][1] * inv0);
        *reinterpret_cast<float2*>(out + (size_t)(r0 + 8) * 256 + col) =
            make_float2(o[nt][2] * inv1, o[nt][3] * inv1);
    }
}

// ---------------- fused residual-add + LayerNorm (warp per row) ----------------
__global__ __launch_bounds__(256) void add_ln_kernel(
    const float* __restrict__ x, const float* __restrict__ y,
    const float* __restrict__ g, const float* __restrict__ b,
    float* __restrict__ out)
{
    int row = blockIdx.x * 8 + (threadIdx.x >> 5);
    int lid = threadIdx.x & 31;
    const float* xr = x + (size_t)row * 256;
    const float* yr = y + (size_t)row * 256;

    float4 v0 = *reinterpret_cast<const float4*>(xr + lid*4);
    float4 w0 = *reinterpret_cast<const float4*>(yr + lid*4);
    float4 v1 = *reinterpret_cast<const float4*>(xr + 128 + lid*4);
    float4 w1 = *reinterpret_cast<const float4*>(yr + 128 + lid*4);
    float a[8] = { v0.x+w0.x, v0.y+w0.y, v0.z+w0.z, v0.w+w0.w,
                   v1.x+w1.x, v1.y+w1.y, v1.z+w1.z, v1.w+w1.w };

    float s = 0.f;
    #pragma unroll
    for (int i = 0; i < 8; i++) s += a[i];
    #pragma unroll
    for (int o2 = 16; o2 > 0; o2 >>= 1) s += __shfl_xor_sync(0xffffffffu, s, o2);
    float mean = s * (1.f/256.f);

    float q = 0.f;
    #pragma unroll
    for (int i = 0; i < 8; i++) { float d = a[i] - mean; q += d*d; }
    #pragma unroll
    for (int o2 = 16; o2 > 0; o2 >>= 1) q += __shfl_xor_sync(0xffffffffu, q, o2);
    float rstd = rsqrtf(q * (1.f/256.f) + 1e-5f);

    float4 g0 = *reinterpret_cast<const float4*>(g + lid*4);
    float4 b0 = *reinterpret_cast<const float4*>(b + lid*4);
    float4 g1 = *reinterpret_cast<const float4*>(g + 128 + lid*4);
    float4 b1 = *reinterpret_cast<const float4*>(b + 128 + lid*4);
    float4 r0, r1;
    r0.x = (a[0]-mean)*rstd*g0.x + b0.x; r0.y = (a[1]-mean)*rstd*g0.y + b0.y;
    r0.z = (a[2]-mean)*rstd*g0.z + b0.z; r0.w = (a[3]-mean)*rstd*g0.w + b0.w;
    r1.x = (a[4]-mean)*rstd*g1.x + b1.x; r1.y = (a[5]-mean)*rstd*g1.y + b1.y;
    r1.z = (a[6]-mean)*rstd*g1.z + b1.z; r1.w = (a[7]-mean)*rstd*g1.w + b1.w;
    *reinterpret_cast<float4*>(out + (size_t)row*256 + lid*4)       = r0;
    *reinterpret_cast<float4*>(out + (size_t)row*256 + 128 + lid*4) = r1;
}

// ---------------- h_combined = h + h0 ----------------
__global__ __launch_bounds__(256) void hc_kernel(
    const float* __restrict__ h, const float* __restrict__ h0,
    float* __restrict__ hc, float* __restrict__ out_tail)
{
    int idx = blockIdx.x * 256 + threadIdx.x;
    float v = h[idx] + h0[idx];
    hc[idx] = v;
    out_tail[idx] = v;
}

// ---------------- fused edge predictor: fp16 MMA + cp.async B + ping-pong A ----------------
// As [2][128][40] half ([e][k]); Bs [2][128][40] half ([j][k] via cp.async from wp1t).
__global__ __launch_bounds__(256) void edge_tc_kernel(
    const float* __restrict__ hc,
    const int* __restrict__ psrc, const int* __restrict__ pdst, const float* __restrict__ pw,
    const int* __restrict__ nsrc, const int* __restrict__ ndst, const float* __restrict__ nw,
    const __half* __restrict__ wp1t, const float* __restrict__ bp1,
    const float* __restrict__ Wp2, const float* __restrict__ bp2,
    float* __restrict__ out, int E, int nblk)
{
    extern __shared__ __align__(16) char smraw[];
    __half* As_ = (__half*)smraw;                  // [2][128][40]
    __half* Bs_ = (__half*)(smraw + 2*128*40*2);   // [2][128][40]
    __shared__ int   sSrc[128], sDst[128];
    __shared__ float sW[128], sWp2[128], sBp1[128];
    __shared__ float sred[128][2];

    const int tid  = threadIdx.x;
    const int lane = tid & 31;
    const int wid  = tid >> 5;
    const int wm   = wid >> 1;
    const int wn   = wid & 1;
    const int grp  = lane >> 2;
    const int tig  = lane & 3;

    const int pol  = (blockIdx.x >= nblk) ? 1 : 0;
    const int blk  = blockIdx.x - pol * nblk;
    const int e0   = blk * 128;
    const int* srcA = pol ? nsrc : psrc;
    const int* dstA = pol ? ndst : pdst;
    const float* wA = pol ? nw   : pw;
    float* op = out + (pol ? (size_t)E : 0);

    const uint32_t bs_u32 = smem_u32(Bs_);

    if (tid < 128) {
        int e = e0 + tid;
        if (e < E) { sSrc[tid] = srcA[e]; sDst[tid] = dstA[e]; sW[tid] = wA[e]; }
        else       { sSrc[tid] = 0;       sDst[tid] = 0;       sW[tid] = 0.f; }
        sWp2[tid] = Wp2[tid];
        sBp1[tid] = bp1[tid];
    }
    __syncthreads();

    float acc[2][8][4] = {};
    float4 ga[4], gb[4];

    // async copy of B tile kt (columns kt*32..+31 of wp1t[j][256]) into buffer bb
    auto cpB = [&](int bb, int kt) {
        #pragma unroll
        for (int i = 0; i < 2; i++) {
            int cid = tid + i * 256;          // 0..511
            int j = cid >> 2, c = cid & 3;    // 4 x 16B chunks per row (32 halfs)
            uint32_t dst = bs_u32 + (uint32_t)(bb * (128*40) + j * 40 + c * 8) * 2;
            cp_async16(dst, wp1t + (size_t)j * 256 + kt * 32 + c * 8);
        }
        cp_commit();
    };
    auto ldA = [&](int kt) {
        #pragma unroll
        for (int i = 0; i < 4; i++) {
            int f = tid + i * 256, e = f >> 3, c4 = f & 7;
            ga[i] = *reinterpret_cast<const float4*>(hc + (size_t)sSrc[e]*256 + kt*32 + c4*4);
            gb[i] = *reinterpret_cast<const float4*>(hc + (size_t)sDst[e]*256 + kt*32 + c4*4);
        }
    };
    auto stA = [&](int bb) {
        #pragma unroll
        for (int i = 0; i < 4; i++) {
            int f = tid + i * 256, e = f >> 3, c4 = f & 7;
            float ww = sW[e];
            uint2 u;
            u.x = pack_h2(ga[i].x * gb[i].x * ww, ga[i].y * gb[i].y * ww);
            u.y = pack_h2(ga[i].z * gb[i].z * ww, ga[i].w * gb[i].w * ww);
            *reinterpret_cast<uint2*>(&As_[bb*(128*40) + e*40 + c4*4]) = u;
        }
    };

    cpB(0, 0);
    ldA(0);
    cp_wait0();
    stA(0);
    __syncthreads();

    for (int t = 0; t < 8; t++) {
        int cur = t & 1;
        if (t < 7) { cpB(cur ^ 1, t + 1); ldA(t + 1); }
        #pragma unroll
        for (int ks = 0; ks < 2; ks++) {
            int k0 = ks * 16 + 2 * tig;
            uint32_t a[2][4], b[8][2];
            #pragma unroll
            for (int mt = 0; mt < 2; mt++) {
                int row = wm * 32 + mt * 16 + grp;
                const __half* ap = &As_[cur*(128*40)];
                a[mt][0] = *reinterpret_cast<const uint32_t*>(&ap[row*40 + k0]);
                a[mt][1] = *reinterpret_cast<const uint32_t*>(&ap[(row+8)*40 + k0]);
                a[mt][2] = *reinterpret_cast<const uint32_t*>(&ap[row*40 + k0 + 8]);
                a[mt][3] = *reinterpret_cast<const uint32_t*>(&ap[(row+8)*40 + k0 + 8]);
            }
            #pragma unroll
            for (int nt = 0; nt < 8; nt++) {
                int j = wn * 64 + nt * 8 + grp;
                const __half* bp = &Bs_[cur*(128*40)];
                b[nt][0] = *reinterpret_cast<const uint32_t*>(&bp[j*40 + k0]);
                b[nt][1] = *reinterpret_cast<const uint32_t*>(&bp[j*40 + k0 + 8]);
            }
            #pragma unroll
            for (int mt = 0; mt < 2; mt++)
                #pragma unroll
                for (int nt = 0; nt < 8; nt++)
                    mma_f16(acc[mt][nt], a[mt], b[nt]);
        }
        if (t < 7) { cp_wait0(); stA(cur ^ 1); }
        __syncthreads();
    }

    // epilogue: leaky(acc + bp1) . Wp2
    #pragma unroll
    for (int mt = 0; mt < 2; mt++) {
        float p0 = 0.f, p1 = 0.f;
        #pragma unroll
        for (int nt = 0; nt < 8; nt++) {
            int col = wn * 64 + nt * 8 + tig * 2;
            float bb0 = sBp1[col], bb1 = sBp1[col+1];
            float w0  = sWp2[col], w1  = sWp2[col+1];
            float y;
            y = acc[mt][nt][0] + bb0; y = (y > 0.f) ? y : 0.2f*y; p0 += y * w0;
            y = acc[mt][nt][1] + bb1; y = (y > 0.f) ? y : 0.2f*y; p0 += y * w1;
            y = acc[mt][nt][2] + bb0; y = (y > 0.f) ? y : 0.2f*y; p1 += y * w0;
            y = acc[mt][nt][3] + bb1; y = (y > 0.f) ? y : 0.2f*y; p1 += y * w1;
        }
        p0 += __shfl_xor_sync(0xffffffffu, p0, 1);
        p0 += __shfl_xor_sync(0xffffffffu, p0, 2);
        p1 += __shfl_xor_sync(0xffffffffu, p1, 1);
        p1 += __shfl_xor_sync(0xffffffffu, p1, 2);
        if (tig == 0) {
            int r0 = wm * 32 + mt * 16 + grp;
            sred[r0    ][wn] = p0;
            sred[r0 + 8][wn] = p1;
        }
    }
    __syncthreads();

    if (tid < 128) {
        int e = e0 + tid;
        if (e < E) op[e] = sred[tid][0] + sred[tid][1] + bp2[0];
    }
}

// ---------------- host orchestration ----------------
extern "C" void kernel_launch(void* const* d_in, const int* in_sizes, int n_in,
                              void* d_out, int out_size)
{
    const float* x        = (const float*)d_in[0];
    const int*   pos_src  = (const int*)  d_in[1];
    const int*   pos_dst  = (const int*)  d_in[2];
    const float* pos_w    = (const float*)d_in[3];
    const int*   neg_src  = (const int*)  d_in[4];
    const int*   neg_dst  = (const int*)  d_in[5];
    const float* neg_w    = (const float*)d_in[6];
    const float* Wi       = (const float*)d_in[7];
    const float* bi       = (const float*)d_in[8];
    const float* Wqkv     = (const float*)d_in[9];
    const float* bqkv     = (const float*)d_in[10];
    const float* Wo       = (const float*)d_in[11];
    const float* bo       = (const float*)d_in[12];
    const float* g1       = (const float*)d_in[13];
    const float* be1      = (const float*)d_in[14];
    const float* g2       = (const float*)d_in[15];
    const float* be2      = (const float*)d_in[16];
    const float* W1       = (const float*)d_in[17];
    const float* b1       = (const float*)d_in[18];
    const float* W2       = (const float*)d_in[19];
    const float* b2       = (const float*)d_in[20];
    const float* Wp1      = (const float*)d_in[21];
    const float* bp1      = (const float*)d_in[22];
    const float* Wp2      = (const float*)d_in[23];
    const float* bp2      = (const float*)d_in[24];

    const int E = in_sizes[1];   // 500000

    cudaFuncSetAttribute(sgemm_tc_kernel, cudaFuncAttributeMaxDynamicSharedMemorySize, SGEMM_SMEM);
    cudaFuncSetAttribute(attn_tc_kernel,  cudaFuncAttributeMaxDynamicSharedMemorySize, ATTN_SMEM);
    cudaFuncSetAttribute(edge_tc_kernel,  cudaFuncAttributeMaxDynamicSharedMemorySize, EDGE_SMEM);

    float* S = nullptr;
    cudaGetSymbolAddress((void**)&S, g_scratch);
    float* h0   = S + OFF_H0;
    float* h    = S + OFF_H;
    float* qkv  = S + OFF_QKV;
    float* attn = S + OFF_ATTN;
    float* tmp  = S + OFF_TMP;
    float* ff   = S + OFF_FF;
    float* hc   = S + OFF_HC;
    __half* wp1t = (__half*)(S + OFF_WP1T);
    float* out  = (float*)d_out;

    // prepass: half, transposed Wp1 -> wp1t[j][k]
    wp1_prep_kernel<<<128, 256>>>(Wp1, wp1t);

    // h0 = x @ Wi + bi
    sgemm_tc_kernel<<<dim3(DD/64, NN/128), 256, SGEMM_SMEM>>>(NN, DD, INF_, x, Wi, bi, h0, 0);

    for (int l = 0; l < LL; l++) {
        const float* hin = (l == 0) ? h0 : h;
        sgemm_tc_kernel<<<dim3(768/64, NN/128), 256, SGEMM_SMEM>>>(NN, 768, DD,
            hin, Wqkv + (size_t)l*DD*768, bqkv + (size_t)l*768, qkv, 0);
        attn_tc_kernel<<<dim3(NN/128, HH), 256, ATTN_SMEM>>>(qkv, attn);
        sgemm_tc_kernel<<<dim3(DD/64, NN/128), 256, SGEMM_SMEM>>>(NN, DD, DD,
            attn, Wo + (size_t)l*DD*DD, bo + (size_t)l*DD, tmp, 0);
        add_ln_kernel<<<NN/8, 256>>>(hin, tmp, g1 + (size_t)l*DD, be1 + (size_t)l*DD, h);
        sgemm_tc_kernel<<<dim3(FF_/64, NN/128), 256, SGEMM_SMEM>>>(NN, FF_, DD,
            h, W1 + (size_t)l*DD*FF_, b1 + (size_t)l*FF_, ff, 1);
        sgemm_tc_kernel<<<dim3(DD/64, NN/128), 256, SGEMM_SMEM>>>(NN, DD, FF_,
            ff, W2 + (size_t)l*FF_*DD, b2 + (size_t)l*DD, tmp, 0);
        add_ln_kernel<<<NN/8, 256>>>(h, tmp, g2 + (size_t)l*DD, be2 + (size_t)l*DD, h);
    }

    hc_kernel<<<NN*DD/256, 256>>>(h, h0, hc, out + 2*(size_t)E);

    // single-launch edge predictor (pos + neg)
    const int nblk = (E + 127) / 128;
    edge_tc_kernel<<<2*nblk, 256, EDGE_SMEM>>>(
        hc, pos_src, pos_dst, pos_w, neg_src, neg_dst, neg_w,
        wp1t, bp1, Wp2, bp2, out, E, nblk);
}

// round 10
// speedup vs baseline: 5.1663x; 1.0500x over previous
#include <cuda_runtime.h>
#include <cuda_fp16.h>
#include <math.h>
#include <stdint.h>

// ---------------- problem constants ----------------
#define NN   4096
#define INF_ 512
#define DD   256
#define LL   2
#define HH   8
#define DH   32
#define FF_  1024
#define HALF_ 128

// ---------------- scratch (device global, no allocs) ----------------
#define OFF_H0    0
#define OFF_H     (OFF_H0 + NN*DD)
#define OFF_QKV   (OFF_H  + NN*DD)
#define OFF_ATTN  (OFF_QKV + NN*3*DD)
#define OFF_TMP   (OFF_ATTN + NN*DD)
#define OFF_FF    (OFF_TMP + NN*DD)
#define OFF_WP1T  (OFF_FF + NN*FF_)
#define OFF_KH    (OFF_WP1T + 16384)     // 8*4096*32 halfs = 524288 floats
#define OFF_VTH   (OFF_KH + 524288)
#define OFF_HCH   (OFF_VTH + 524288)     // 4096*256 halfs
#define SCRATCH_FLOATS (OFF_HCH + 524288)

__device__ float g_scratch[SCRATCH_FLOATS];

// dynamic smem sizes (bytes)
#define SGEMM_SMEM ((2*128*40 + 2*64*40) * 2)
#define ATTN_SMEM  ((2*64*40 + 2*32*72 + 8*16*72) * 2)
#define EDGE_SMEM  ((2*128*40 + 2*128*40) * 2)

// ---------------- fp16 MMA helpers ----------------
__device__ __forceinline__ uint32_t pack_h2(float lo, float hi) {
    __half2 h = __floats2half2_rn(lo, hi);
    return *reinterpret_cast<uint32_t*>(&h);
}

__device__ __forceinline__ void mma_f16(float* d, const uint32_t* a, const uint32_t* b) {
    asm("mma.sync.aligned.m16n8k16.row.col.f32.f16.f16.f32 "
        "{%0,%1,%2,%3},{%4,%5,%6,%7},{%8,%9},{%0,%1,%2,%3};"
        : "+f"(d[0]), "+f"(d[1]), "+f"(d[2]), "+f"(d[3])
        : "r"(a[0]), "r"(a[1]), "r"(a[2]), "r"(a[3]), "r"(b[0]), "r"(b[1]));
}

__device__ __forceinline__ uint32_t smem_u32(const void* p) {
    uint32_t a;
    asm("{ .reg .u64 t; cvta.to.shared.u64 t, %1; cvt.u32.u64 %0, t; }" : "=r"(a) : "l"(p));
    return a;
}
__device__ __forceinline__ void cp_async16(uint32_t dst, const void* src) {
    asm volatile("cp.async.ca.shared.global [%0], [%1], 16;" :: "r"(dst), "l"(src));
}
__device__ __forceinline__ void cp_commit() {
    asm volatile("cp.async.commit_group;" ::: "memory");
}
__device__ __forceinline__ void cp_wait0() {
    asm volatile("cp.async.wait_group 0;" ::: "memory");
}

// ---------------- Wp1 prepass: half, transposed [j][k] ----------------
__global__ __launch_bounds__(256) void wp1_prep_kernel(
    const float* __restrict__ Wp1, __half* __restrict__ wp1t)
{
    int idx = blockIdx.x * 256 + threadIdx.x;   // 0..32767
    int k = idx >> 7, j = idx & 127;
    wp1t[j * 256 + k] = __float2half_rn(Wp1[idx]);
}

// ---------------- per-layer KV prepass ----------------
// kh[h][kv][d] = half(qkv[kv][256+h*32+d]);  vth[h][d][kv] = half(qkv[kv][512+h*32+d])
__global__ __launch_bounds__(256) void kvprep_kernel(
    const float* __restrict__ qkv, __half* __restrict__ kh, __half* __restrict__ vth)
{
    int gid = blockIdx.x * 256 + threadIdx.x;
    if (gid < 262144) {                      // K: 1M elems, 4 per thread
        int idx = gid * 4;
        int h   = idx >> 17;
        int rem = idx & 131071;
        int kv  = rem >> 5;
        int d   = rem & 31;
        float4 v = *reinterpret_cast<const float4*>(qkv + (size_t)kv*768 + 256 + h*32 + d);
        __half2* o = reinterpret_cast<__half2*>(kh + idx);
        o[0] = __floats2half2_rn(v.x, v.y);
        o[1] = __floats2half2_rn(v.z, v.w);
    } else {                                 // V transposed
        int idx = (gid - 262144) * 4;
        int h   = idx >> 17;
        int rem = idx & 131071;
        int d   = rem >> 12;
        int kv  = rem & 4095;
        const float* src = qkv + 512 + h*32 + d;
        __half2* o = reinterpret_cast<__half2*>(vth + idx);
        o[0] = __floats2half2_rn(src[(size_t)kv*768],     src[(size_t)(kv+1)*768]);
        o[1] = __floats2half2_rn(src[(size_t)(kv+2)*768], src[(size_t)(kv+3)*768]);
    }
}

// ---------------- fp16 tensor-core SGEMM, ping-pong prefetch ----------------
__global__ __launch_bounds__(256) void sgemm_tc_kernel(
    int M, int N, int K,
    const float* __restrict__ A, const float* __restrict__ B,
    const float* __restrict__ bias, float* __restrict__ C, int act)
{
    extern __shared__ __align__(16) char smraw[];
    __half* As_ = (__half*)smraw;                   // [2][128][40]
    __half* Bs_ = (__half*)(smraw + 2*128*40*2);    // [2][64][40]

    const int tid  = threadIdx.x;
    const int lane = tid & 31;
    const int wid  = tid >> 5;
    const int wm   = wid >> 1;
    const int wn   = wid & 1;
    const int grp  = lane >> 2;
    const int tig  = lane & 3;

    const int bx = blockIdx.x, by = blockIdx.y;
    A += (size_t)by * 128 * K;
    B += (size_t)bx * 64;
    C += (size_t)by * 128 * N + (size_t)bx * 64;
    bias += (size_t)bx * 64;

    float acc[2][4][4] = {};
    float4 rA[4], rB[2];

    auto ldT = [&](int kt) {
        #pragma unroll
        for (int i = 0; i < 4; i++) {
            int f = tid + i * 256, r = f >> 3, c4 = f & 7;
            rA[i] = *reinterpret_cast<const float4*>(A + (size_t)r * K + kt + c4 * 4);
        }
        #pragma unroll
        for (int i = 0; i < 2; i++) {
            int f = tid + i * 256, r = f >> 4, c4 = f & 15;
            rB[i] = *reinterpret_cast<const float4*>(B + (size_t)(kt + r) * N + c4 * 4);
        }
    };
    auto stT = [&](int bb) {
        #pragma unroll
        for (int i = 0; i < 4; i++) {
            int f = tid + i * 256, r = f >> 3, c4 = f & 7;
            uint2 u;
            u.x = pack_h2(rA[i].x, rA[i].y);
            u.y = pack_h2(rA[i].z, rA[i].w);
            *reinterpret_cast<uint2*>(&As_[bb*(128*40) + r*40 + c4*4]) = u;
        }
        #pragma unroll
        for (int i = 0; i < 2; i++) {
            int f = tid + i * 256, r = f >> 4, c4 = f & 15;
            __half* bp = &Bs_[bb*(64*40)];
            bp[(c4*4+0)*40 + r] = __float2half_rn(rB[i].x);
            bp[(c4*4+1)*40 + r] = __float2half_rn(rB[i].y);
            bp[(c4*4+2)*40 + r] = __float2half_rn(rB[i].z);
            bp[(c4*4+3)*40 + r] = __float2half_rn(rB[i].w);
        }
    };

    const int T = K / 32;
    ldT(0); stT(0); __syncthreads();

    for (int t = 0; t < T; t++) {
        int cur = t & 1;
        if (t + 1 < T) ldT((t + 1) * 32);
        #pragma unroll
        for (int ks = 0; ks < 2; ks++) {
            int k0 = ks * 16 + 2 * tig;
            uint32_t a[2][4], b[4][2];
            #pragma unroll
            for (int mt = 0; mt < 2; mt++) {
                int row = wm * 32 + mt * 16 + grp;
                const __half* ap = &As_[cur*(128*40)];
                a[mt][0] = *reinterpret_cast<const uint32_t*>(&ap[row*40 + k0]);
                a[mt][1] = *reinterpret_cast<const uint32_t*>(&ap[(row+8)*40 + k0]);
                a[mt][2] = *reinterpret_cast<const uint32_t*>(&ap[row*40 + k0 + 8]);
                a[mt][3] = *reinterpret_cast<const uint32_t*>(&ap[(row+8)*40 + k0 + 8]);
            }
            #pragma unroll
            for (int nt = 0; nt < 4; nt++) {
                int col = wn * 32 + nt * 8 + grp;
                const __half* bp = &Bs_[cur*(64*40)];
                b[nt][0] = *reinterpret_cast<const uint32_t*>(&bp[col*40 + k0]);
                b[nt][1] = *reinterpret_cast<const uint32_t*>(&bp[col*40 + k0 + 8]);
            }
            #pragma unroll
            for (int mt = 0; mt < 2; mt++)
                #pragma unroll
                for (int nt = 0; nt < 4; nt++)
                    mma_f16(acc[mt][nt], a[mt], b[nt]);
        }
        if (t + 1 < T) stT((t + 1) & 1);
        __syncthreads();
    }

    #pragma unroll
    for (int mt = 0; mt < 2; mt++) {
        #pragma unroll
        for (int nt = 0; nt < 4; nt++) {
            int row = wm * 32 + mt * 16 + grp;
            int col = wn * 32 + nt * 8 + tig * 2;
            float b0 = bias[col], b1 = bias[col+1];
            float2 v0, v1;
            v0.x = acc[mt][nt][0] + b0; v0.y = acc[mt][nt][1] + b1;
            v1.x = acc[mt][nt][2] + b0; v1.y = acc[mt][nt][3] + b1;
            if (act == 1) {
                v0.x = fmaxf(v0.x, 0.f); v0.y = fmaxf(v0.y, 0.f);
                v1.x = fmaxf(v1.x, 0.f); v1.y = fmaxf(v1.y, 0.f);
            }
            *reinterpret_cast<float2*>(C + (size_t)row * N + col)     = v0;
            *reinterpret_cast<float2*>(C + (size_t)(row+8) * N + col) = v1;
        }
    }
}

// ---------------- fp16 MMA flash attention, cp.async KV tiles ----------------
// grid (NN/128, HH), 256 threads = 8 warps, warp owns 16 query rows.
__global__ __launch_bounds__(256) void attn_tc_kernel(
    const float* __restrict__ qkv,
    const __half* __restrict__ kh, const __half* __restrict__ vth,
    float* __restrict__ out)
{
    extern __shared__ __align__(16) char smraw[];
    __half* Ks_ = (__half*)smraw;                                  // [2][64][40]
    __half* Vs_ = (__half*)(smraw + 2*64*40*2);                    // [2][32][72]
    __half* Ps_ = (__half*)(smraw + (2*64*40 + 2*32*72)*2);        // [8][16][72]

    const int h  = blockIdx.y;
    const int qb = blockIdx.x * 128;
    const int tid  = threadIdx.x;
    const int lane = tid & 31;
    const int wid  = tid >> 5;
    const int grp  = lane >> 2;
    const int tig  = lane & 3;
    const float scale = 0.17677669529663687f;   // 1/sqrt(32)

    const uint32_t ks_u32 = smem_u32(Ks_);
    const uint32_t vs_u32 = smem_u32(Vs_);
    const __half* khh = kh  + (size_t)h * 131072;
    const __half* vhh = vth + (size_t)h * 131072;

    // Q fragments (scale folded), packed half2
    uint32_t qa[2][4];
    {
        const float* q0 = qkv + (size_t)(qb + wid*16 + grp) * 768 + h * 32;
        const float* q1 = q0 + (size_t)8 * 768;
        #pragma unroll
        for (int ks = 0; ks < 2; ks++) {
            int b = ks * 16 + 2 * tig;
            qa[ks][0] = pack_h2(q0[b]   * scale, q0[b+1] * scale);
            qa[ks][1] = pack_h2(q1[b]   * scale, q1[b+1] * scale);
            qa[ks][2] = pack_h2(q0[b+8] * scale, q0[b+9] * scale);
            qa[ks][3] = pack_h2(q1[b+8] * scale, q1[b+9] * scale);
        }
    }

    float m0 = -1e30f, m1 = -1e30f, l0 = 0.f, l1 = 0.f;
    float o[4][4] = {};

    auto cpKV = [&](int bb, int kb) {
        // K tile: 64 rows x 32 halfs, one 16B chunk per thread
        int r = tid >> 2, c = tid & 3;
        cp_async16(ks_u32 + (uint32_t)(bb*(64*40) + r*40 + c*8) * 2,
                   khh + (size_t)(kb + r) * 32 + c * 8);
        // V tile (transposed): 32 rows x 64 halfs, one 16B chunk per thread
        int r2 = tid >> 3, c2 = tid & 7;
        cp_async16(vs_u32 + (uint32_t)(bb*(32*72) + r2*72 + c2*8) * 2,
                   vhh + (size_t)r2 * 4096 + kb + c2 * 8);
        cp_commit();
    };

    cpKV(0, 0);
    cp_wait0();
    __syncthreads();

    for (int t = 0; t < NN/64; t++) {
        int cur = t & 1;
        if (t < NN/64 - 1) cpKV(cur ^ 1, (t + 1) * 64);

        // S = Q @ K^T : 16 rows x 64 kv
        float sacc[8][4] = {};
        #pragma unroll
        for (int ks = 0; ks < 2; ks++) {
            int k0 = ks * 16 + 2 * tig;
            #pragma unroll
            for (int nt = 0; nt < 8; nt++) {
                const __half* kp = &Ks_[cur*(64*40) + (nt*8+grp)*40];
                uint32_t b[2];
                b[0] = *reinterpret_cast<const uint32_t*>(&kp[k0]);
                b[1] = *reinterpret_cast<const uint32_t*>(&kp[k0 + 8]);
                mma_f16(sacc[nt], qa[ks], b);
            }
        }

        // online softmax
        float rmax0 = -1e30f, rmax1 = -1e30f;
        #pragma unroll
        for (int nt = 0; nt < 8; nt++) {
            rmax0 = fmaxf(rmax0, fmaxf(sacc[nt][0], sacc[nt][1]));
            rmax1 = fmaxf(rmax1, fmaxf(sacc[nt][2], sacc[nt][3]));
        }
        rmax0 = fmaxf(rmax0, __shfl_xor_sync(0xffffffffu, rmax0, 1));
        rmax0 = fmaxf(rmax0, __shfl_xor_sync(0xffffffffu, rmax0, 2));
        rmax1 = fmaxf(rmax1, __shfl_xor_sync(0xffffffffu, rmax1, 1));
        rmax1 = fmaxf(rmax1, __shfl_xor_sync(0xffffffffu, rmax1, 2));
        float mn0 = fmaxf(m0, rmax0), mn1 = fmaxf(m1, rmax1);
        float a0 = __expf(m0 - mn0), a1 = __expf(m1 - mn1);
        float ps0 = 0.f, ps1 = 0.f;
        __half* pw = &Ps_[wid*(16*72)];
        #pragma unroll
        for (int nt = 0; nt < 8; nt++) {
            float p00 = __expf(sacc[nt][0] - mn0);
            float p01 = __expf(sacc[nt][1] - mn0);
            float p10 = __expf(sacc[nt][2] - mn1);
            float p11 = __expf(sacc[nt][3] - mn1);
            ps0 += p00 + p01; ps1 += p10 + p11;
            *reinterpret_cast<uint32_t*>(&pw[grp*72     + nt*8 + 2*tig]) = pack_h2(p00, p01);
            *reinterpret_cast<uint32_t*>(&pw[(grp+8)*72 + nt*8 + 2*tig]) = pack_h2(p10, p11);
        }
        ps0 += __shfl_xor_sync(0xffffffffu, ps0, 1);
        ps0 += __shfl_xor_sync(0xffffffffu, ps0, 2);
        ps1 += __shfl_xor_sync(0xffffffffu, ps1, 1);
        ps1 += __shfl_xor_sync(0xffffffffu, ps1, 2);
        l0 = l0 * a0 + ps0; l1 = l1 * a1 + ps1;
        m0 = mn0; m1 = mn1;
        #pragma unroll
        for (int nt = 0; nt < 4; nt++) {
            o[nt][0] *= a0; o[nt][1] *= a0;
            o[nt][2] *= a1; o[nt][3] *= a1;
        }
        __syncwarp();

        // O += P @ V
        #pragma unroll
        for (int ks = 0; ks < 4; ks++) {
            int k0 = ks * 16 + 2 * tig;
            uint32_t a[4];
            a[0] = *reinterpret_cast<const uint32_t*>(&pw[grp*72     + k0]);
            a[1] = *reinterpret_cast<const uint32_t*>(&pw[(grp+8)*72 + k0]);
            a[2] = *reinterpret_cast<const uint32_t*>(&pw[grp*72     + k0 + 8]);
            a[3] = *reinterpret_cast<const uint32_t*>(&pw[(grp+8)*72 + k0 + 8]);
            #pragma unroll
            for (int nt = 0; nt < 4; nt++) {
                const __half* vp = &Vs_[cur*(32*72) + (nt*8+grp)*72];
                uint32_t b[2];
                b[0] = *reinterpret_cast<const uint32_t*>(&vp[k0]);
                b[1] = *reinterpret_cast<const uint32_t*>(&vp[k0 + 8]);
                mma_f16(o[nt], a, b);
            }
        }
        __syncwarp();

        if (t < NN/64 - 1) cp_wait0();
        __syncthreads();
    }

    float inv0 = 1.f / l0, inv1 = 1.f / l1;
    int r0 = qb + wid*16 + grp;
    #pragma unroll
    for (int nt = 0; nt < 4; nt++) {
        int col = h * 32 + nt * 8 + tig * 2;
        *reinterpret_cast<float2*>(out + (size_t)r0 * 256 + col) =
            make_float2(o[nt][0] * inv0, o[nt][1] * inv0);
        *reinterpret_cast<float2*>(out + (size_t)(r0 + 8) * 256 + col) =
            make_float2(o[nt][2] * inv1, o[nt][3] * inv1);
    }
}

// ---------------- fused residual-add + LayerNorm (warp per row) ----------------
__global__ __launch_bounds__(256) void add_ln_kernel(
    const float* __restrict__ x, const float* __restrict__ y,
    const float* __restrict__ g, const float* __restrict__ b,
    float* __restrict__ out)
{
    int row = blockIdx.x * 8 + (threadIdx.x >> 5);
    int lid = threadIdx.x & 31;
    const float* xr = x + (size_t)row * 256;
    const float* yr = y + (size_t)row * 256;

    float4 v0 = *reinterpret_cast<const float4*>(xr + lid*4);
    float4 w0 = *reinterpret_cast<const float4*>(yr + lid*4);
    float4 v1 = *reinterpret_cast<const float4*>(xr + 128 + lid*4);
    float4 w1 = *reinterpret_cast<const float4*>(yr + 128 + lid*4);
    float a[8] = { v0.x+w0.x, v0.y+w0.y, v0.z+w0.z, v0.w+w0.w,
                   v1.x+w1.x, v1.y+w1.y, v1.z+w1.z, v1.w+w1.w };

    float s = 0.f;
    #pragma unroll
    for (int i = 0; i < 8; i++) s += a[i];
    #pragma unroll
    for (int o2 = 16; o2 > 0; o2 >>= 1) s += __shfl_xor_sync(0xffffffffu, s, o2);
    float mean = s * (1.f/256.f);

    float q = 0.f;
    #pragma unroll
    for (int i = 0; i < 8; i++) { float d = a[i] - mean; q += d*d; }
    #pragma unroll
    for (int o2 = 16; o2 > 0; o2 >>= 1) q += __shfl_xor_sync(0xffffffffu, q, o2);
    float rstd = rsqrtf(q * (1.f/256.f) + 1e-5f);

    float4 g0 = *reinterpret_cast<const float4*>(g + lid*4);
    float4 b0 = *reinterpret_cast<const float4*>(b + lid*4);
    float4 g1 = *reinterpret_cast<const float4*>(g + 128 + lid*4);
    float4 b1 = *reinterpret_cast<const float4*>(b + 128 + lid*4);
    float4 r0, r1;
    r0.x = (a[0]-mean)*rstd*g0.x + b0.x; r0.y = (a[1]-mean)*rstd*g0.y + b0.y;
    r0.z = (a[2]-mean)*rstd*g0.z + b0.z; r0.w = (a[3]-mean)*rstd*g0.w + b0.w;
    r1.x = (a[4]-mean)*rstd*g1.x + b1.x; r1.y = (a[5]-mean)*rstd*g1.y + b1.y;
    r1.z = (a[6]-mean)*rstd*g1.z + b1.z; r1.w = (a[7]-mean)*rstd*g1.w + b1.w;
    *reinterpret_cast<float4*>(out + (size_t)row*256 + lid*4)       = r0;
    *reinterpret_cast<float4*>(out + (size_t)row*256 + 128 + lid*4) = r1;
}

// final layer: h_combined = LN(x+y) + h0, write fp32 tail + fp16 copy
__global__ __launch_bounds__(256) void add_ln_hc_kernel(
    const float* __restrict__ x, const float* __restrict__ y,
    const float* __restrict__ g, const float* __restrict__ b,
    const float* __restrict__ h0,
    float* __restrict__ out_tail, __half* __restrict__ hch)
{
    int row = blockIdx.x * 8 + (threadIdx.x >> 5);
    int lid = threadIdx.x & 31;
    const float* xr = x + (size_t)row * 256;
    const float* yr = y + (size_t)row * 256;
    const float* hr = h0 + (size_t)row * 256;

    float4 v0 = *reinterpret_cast<const float4*>(xr + lid*4);
    float4 w0 = *reinterpret_cast<const float4*>(yr + lid*4);
    float4 v1 = *reinterpret_cast<const float4*>(xr + 128 + lid*4);
    float4 w1 = *reinterpret_cast<const float4*>(yr + 128 + lid*4);
    float a[8] = { v0.x+w0.x, v0.y+w0.y, v0.z+w0.z, v0.w+w0.w,
                   v1.x+w1.x, v1.y+w1.y, v1.z+w1.z, v1.w+w1.w };

    float s = 0.f;
    #pragma unroll
    for (int i = 0; i < 8; i++) s += a[i];
    #pragma unroll
    for (int o2 = 16; o2 > 0; o2 >>= 1) s += __shfl_xor_sync(0xffffffffu, s, o2);
    float mean = s * (1.f/256.f);

    float q = 0.f;
    #pragma unroll
    for (int i = 0; i < 8; i++) { float d = a[i] - mean; q += d*d; }
    #pragma unroll
    for (int o2 = 16; o2 > 0; o2 >>= 1) q += __shfl_xor_sync(0xffffffffu, q, o2);
    float rstd = rsqrtf(q * (1.f/256.f) + 1e-5f);

    float4 g0 = *reinterpret_cast<const float4*>(g + lid*4);
    float4 b0 = *reinterpret_cast<const float4*>(b + lid*4);
    float4 g1 = *reinterpret_cast<const float4*>(g + 128 + lid*4);
    float4 b1 = *reinterpret_cast<const float4*>(b + 128 + lid*4);
    float4 h00 = *reinterpret_cast<const float4*>(hr + lid*4);
    float4 h01 = *reinterpret_cast<const float4*>(hr + 128 + lid*4);

    float4 c0, c1;
    c0.x = (a[0]-mean)*rstd*g0.x + b0.x + h00.x;
    c0.y = (a[1]-mean)*rstd*g0.y + b0.y + h00.y;
    c0.z = (a[2]-mean)*rstd*g0.z + b0.z + h00.z;
    c0.w = (a[3]-mean)*rstd*g0.w + b0.w + h00.w;
    c1.x = (a[4]-mean)*rstd*g1.x + b1.x + h01.x;
    c1.y = (a[5]-mean)*rstd*g1.y + b1.y + h01.y;
    c1.z = (a[6]-mean)*rstd*g1.z + b1.z + h01.z;
    c1.w = (a[7]-mean)*rstd*g1.w + b1.w + h01.w;

    *reinterpret_cast<float4*>(out_tail + (size_t)row*256 + lid*4)       = c0;
    *reinterpret_cast<float4*>(out_tail + (size_t)row*256 + 128 + lid*4) = c1;

    uint2 u0, u1;
    u0.x = pack_h2(c0.x, c0.y); u0.y = pack_h2(c0.z, c0.w);
    u1.x = pack_h2(c1.x, c1.y); u1.y = pack_h2(c1.z, c1.w);
    *reinterpret_cast<uint2*>(hch + (size_t)row*256 + lid*4)       = u0;
    *reinterpret_cast<uint2*>(hch + (size_t)row*256 + 128 + lid*4) = u1;
}

// ---------------- fused edge predictor: fp16 gathers + cp.async B ----------------
__global__ __launch_bounds__(256) void edge_tc_kernel(
    const __half* __restrict__ hch,
    const int* __restrict__ psrc, const int* __restrict__ pdst, const float* __restrict__ pw,
    const int* __restrict__ nsrc, const int* __restrict__ ndst, const float* __restrict__ nw,
    const __half* __restrict__ wp1t, const float* __restrict__ bp1,
    const float* __restrict__ Wp2, const float* __restrict__ bp2,
    float* __restrict__ out, int E, int nblk)
{
    extern __shared__ __align__(16) char smraw[];
    __half* As_ = (__half*)smraw;                  // [2][128][40]
    __half* Bs_ = (__half*)(smraw + 2*128*40*2);   // [2][128][40]
    __shared__ int      sSrc[128], sDst[128];
    __shared__ uint32_t sWh[128];
    __shared__ float    sWp2[128], sBp1[128];
    __shared__ float    sred[128][2];

    const int tid  = threadIdx.x;
    const int lane = tid & 31;
    const int wid  = tid >> 5;
    const int wm   = wid >> 1;
    const int wn   = wid & 1;
    const int grp  = lane >> 2;
    const int tig  = lane & 3;

    const int pol  = (blockIdx.x >= nblk) ? 1 : 0;
    const int blk  = blockIdx.x - pol * nblk;
    const int e0   = blk * 128;
    const int* srcA = pol ? nsrc : psrc;
    const int* dstA = pol ? ndst : pdst;
    const float* wA = pol ? nw   : pw;
    float* op = out + (pol ? (size_t)E : 0);

    const uint32_t bs_u32 = smem_u32(Bs_);

    if (tid < 128) {
        int e = e0 + tid;
        float wv = (e < E) ? wA[e] : 0.f;
        if (e < E) { sSrc[tid] = srcA[e]; sDst[tid] = dstA[e]; }
        else       { sSrc[tid] = 0;       sDst[tid] = 0; }
        sWh[tid]  = pack_h2(wv, wv);
        sWp2[tid] = Wp2[tid];
        sBp1[tid] = bp1[tid];
    }
    __syncthreads();

    float acc[2][8][4] = {};
    uint4 gs[2], gd[2];

    auto cpB = [&](int bb, int kt) {
        #pragma unroll
        for (int i = 0; i < 2; i++) {
            int cid = tid + i * 256;
            int j = cid >> 2, c = cid & 3;
            uint32_t dst = bs_u32 + (uint32_t)(bb * (128*40) + j * 40 + c * 8) * 2;
            cp_async16(dst, wp1t + (size_t)j * 256 + kt * 32 + c * 8);
        }
        cp_commit();
    };
    auto ldA = [&](int kt) {
        #pragma unroll
        for (int i = 0; i < 2; i++) {
            int f = tid + i * 256, e = f >> 2, q = f & 3;
            gs[i] = *reinterpret_cast<const uint4*>(hch + (size_t)sSrc[e]*256 + kt*32 + q*8);
            gd[i] = *reinterpret_cast<const uint4*>(hch + (size_t)sDst[e]*256 + kt*32 + q*8);
        }
    };
    auto stA = [&](int bb) {
        #pragma unroll
        for (int i = 0; i < 2; i++) {
            int f = tid + i * 256, e = f >> 2, q = f & 3;
            __half2 w2 = *reinterpret_cast<const __half2*>(&sWh[e]);
            const __half2* sp = reinterpret_cast<const __half2*>(&gs[i]);
            const __half2* dp = reinterpret_cast<const __half2*>(&gd[i]);
            uint4 r;
            __half2* rp = reinterpret_cast<__half2*>(&r);
            rp[0] = __hmul2(__hmul2(sp[0], dp[0]), w2);
            rp[1] = __hmul2(__hmul2(sp[1], dp[1]), w2);
            rp[2] = __hmul2(__hmul2(sp[2], dp[2]), w2);
            rp[3] = __hmul2(__hmul2(sp[3], dp[3]), w2);
            *reinterpret_cast<uint4*>(&As_[bb*(128*40) + e*40 + q*8]) = r;
        }
    };

    cpB(0, 0);
    ldA(0);
    cp_wait0();
    stA(0);
    __syncthreads();

    for (int t = 0; t < 8; t++) {
        int cur = t & 1;
        if (t < 7) { cpB(cur ^ 1, t + 1); ldA(t + 1); }
        #pragma unroll
        for (int ks = 0; ks < 2; ks++) {
            int k0 = ks * 16 + 2 * tig;
            uint32_t a[2][4], b[8][2];
            #pragma unroll
            for (int mt = 0; mt < 2; mt++) {
                int row = wm * 32 + mt * 16 + grp;
                const __half* ap = &As_[cur*(128*40)];
                a[mt][0] = *reinterpret_cast<const uint32_t*>(&ap[row*40 + k0]);
                a[mt][1] = *reinterpret_cast<const uint32_t*>(&ap[(row+8)*40 + k0]);
                a[mt][2] = *reinterpret_cast<const uint32_t*>(&ap[row*40 + k0 + 8]);
                a[mt][3] = *reinterpret_cast<const uint32_t*>(&ap[(row+8)*40 + k0 + 8]);
            }
            #pragma unroll
            for (int nt = 0; nt < 8; nt++) {
                int j = wn * 64 + nt * 8 + grp;
                const __half* bp = &Bs_[cur*(128*40)];
                b[nt][0] = *reinterpret_cast<const uint32_t*>(&bp[j*40 + k0]);
                b[nt][1] = *reinterpret_cast<const uint32_t*>(&bp[j*40 + k0 + 8]);
            }
            #pragma unroll
            for (int mt = 0; mt < 2; mt++)
                #pragma unroll
                for (int nt = 0; nt < 8; nt++)
                    mma_f16(acc[mt][nt], a[mt], b[nt]);
        }
        if (t < 7) { cp_wait0(); stA(cur ^ 1); }
        __syncthreads();
    }

    // epilogue: leaky(acc + bp1) . Wp2
    #pragma unroll
    for (int mt = 0; mt < 2; mt++) {
        float p0 = 0.f, p1 = 0.f;
        #pragma unroll
        for (int nt = 0; nt < 8; nt++) {
            int col = wn * 64 + nt * 8 + tig * 2;
            float bb0 = sBp1[col], bb1 = sBp1[col+1];
            float w0  = sWp2[col], w1  = sWp2[col+1];
            float y;
            y = acc[mt][nt][0] + bb0; y = (y > 0.f) ? y : 0.2f*y; p0 += y * w0;
            y = acc[mt][nt][1] + bb1; y = (y > 0.f) ? y : 0.2f*y; p0 += y * w1;
            y = acc[mt][nt][2] + bb0; y = (y > 0.f) ? y : 0.2f*y; p1 += y * w0;
            y = acc[mt][nt][3] + bb1; y = (y > 0.f) ? y : 0.2f*y; p1 += y * w1;
        }
        p0 += __shfl_xor_sync(0xffffffffu, p0, 1);
        p0 += __shfl_xor_sync(0xffffffffu, p0, 2);
        p1 += __shfl_xor_sync(0xffffffffu, p1, 1);
        p1 += __shfl_xor_sync(0xffffffffu, p1, 2);
        if (tig == 0) {
            int r0 = wm * 32 + mt * 16 + grp;
            sred[r0    ][wn] = p0;
            sred[r0 + 8][wn] = p1;
        }
    }
    __syncthreads();

    if (tid < 128) {
        int e = e0 + tid;
        if (e < E) op[e] = sred[tid][0] + sred[tid][1] + bp2[0];
    }
}

// ---------------- host orchestration ----------------
extern "C" void kernel_launch(void* const* d_in, const int* in_sizes, int n_in,
                              void* d_out, int out_size)
{
    const float* x        = (const float*)d_in[0];
    const int*   pos_src  = (const int*)  d_in[1];
    const int*   pos_dst  = (const int*)  d_in[2];
    const float* pos_w    = (const float*)d_in[3];
    const int*   neg_src  = (const int*)  d_in[4];
    const int*   neg_dst  = (const int*)  d_in[5];
    const float* neg_w    = (const float*)d_in[6];
    const float* Wi       = (const float*)d_in[7];
    const float* bi       = (const float*)d_in[8];
    const float* Wqkv     = (const float*)d_in[9];
    const float* bqkv     = (const float*)d_in[10];
    const float* Wo       = (const float*)d_in[11];
    const float* bo       = (const float*)d_in[12];
    const float* g1       = (const float*)d_in[13];
    const float* be1      = (const float*)d_in[14];
    const float* g2       = (const float*)d_in[15];
    const float* be2      = (const float*)d_in[16];
    const float* W1       = (const float*)d_in[17];
    const float* b1       = (const float*)d_in[18];
    const float* W2       = (const float*)d_in[19];
    const float* b2       = (const float*)d_in[20];
    const float* Wp1      = (const float*)d_in[21];
    const float* bp1      = (const float*)d_in[22];
    const float* Wp2      = (const float*)d_in[23];
    const float* bp2      = (const float*)d_in[24];

    const int E = in_sizes[1];   // 500000

    cudaFuncSetAttribute(sgemm_tc_kernel, cudaFuncAttributeMaxDynamicSharedMemorySize, SGEMM_SMEM);
    cudaFuncSetAttribute(attn_tc_kernel,  cudaFuncAttributeMaxDynamicSharedMemorySize, ATTN_SMEM);
    cudaFuncSetAttribute(edge_tc_kernel,  cudaFuncAttributeMaxDynamicSharedMemorySize, EDGE_SMEM);

    float* S = nullptr;
    cudaGetSymbolAddress((void**)&S, g_scratch);
    float* h0    = S + OFF_H0;
    float* h     = S + OFF_H;
    float* qkv   = S + OFF_QKV;
    float* attn  = S + OFF_ATTN;
    float* tmp   = S + OFF_TMP;
    float* ff    = S + OFF_FF;
    __half* wp1t = (__half*)(S + OFF_WP1T);
    __half* kh   = (__half*)(S + OFF_KH);
    __half* vth  = (__half*)(S + OFF_VTH);
    __half* hch  = (__half*)(S + OFF_HCH);
    float* out   = (float*)d_out;

    // prepass: half, transposed Wp1 -> wp1t[j][k]
    wp1_prep_kernel<<<128, 256>>>(Wp1, wp1t);

    // h0 = x @ Wi + bi
    sgemm_tc_kernel<<<dim3(DD/64, NN/128), 256, SGEMM_SMEM>>>(NN, DD, INF_, x, Wi, bi, h0, 0);

    for (int l = 0; l < LL; l++) {
        const float* hin = (l == 0) ? h0 : h;
        sgemm_tc_kernel<<<dim3(768/64, NN/128), 256, SGEMM_SMEM>>>(NN, 768, DD,
            hin, Wqkv + (size_t)l*DD*768, bqkv + (size_t)l*768, qkv, 0);
        kvprep_kernel<<<2048, 256>>>(qkv, kh, vth);
        attn_tc_kernel<<<dim3(NN/128, HH), 256, ATTN_SMEM>>>(qkv, kh, vth, attn);
        sgemm_tc_kernel<<<dim3(DD/64, NN/128), 256, SGEMM_SMEM>>>(NN, DD, DD,
            attn, Wo + (size_t)l*DD*DD, bo + (size_t)l*DD, tmp, 0);
        add_ln_kernel<<<NN/8, 256>>>(hin, tmp, g1 + (size_t)l*DD, be1 + (size_t)l*DD, h);
        sgemm_tc_kernel<<<dim3(FF_/64, NN/128), 256, SGEMM_SMEM>>>(NN, FF_, DD,
            h, W1 + (size_t)l*DD*FF_, b1 + (size_t)l*FF_, ff, 1);
        sgemm_tc_kernel<<<dim3(DD/64, NN/128), 256, SGEMM_SMEM>>>(NN, DD, FF_,
            ff, W2 + (size_t)l*FF_*DD, b2 + (size_t)l*DD, tmp, 0);
        if (l == LL - 1) {
            add_ln_hc_kernel<<<NN/8, 256>>>(h, tmp, g2 + (size_t)l*DD, be2 + (size_t)l*DD,
                                            h0, out + 2*(size_t)E, hch);
        } else {
            add_ln_kernel<<<NN/8, 256>>>(h, tmp, g2 + (size_t)l*DD, be2 + (size_t)l*DD, h);
        }
    }

    // single-launch edge predictor (pos + neg)
    const int nblk = (E + 127) / 128;
    edge_tc_kernel<<<2*nblk, 256, EDGE_SMEM>>>(
        hch, pos_src, pos_dst, pos_w, neg_src, neg_dst, neg_w,
        wp1t, bp1, Wp2, bp2, out, E, nblk);
}

// round 11
// speedup vs baseline: 5.4138x; 1.0479x over previous
#include <cuda_runtime.h>
#include <cuda_fp16.h>
#include <math.h>
#include <stdint.h>

// ---------------- problem constants ----------------
#define NN   4096
#define INF_ 512
#define DD   256
#define LL   2
#define HH   8
#define DH   32
#define FF_  1024
#define HALF_ 128

// ---------------- scratch (device global, no allocs) ----------------
#define OFF_H0    0
#define OFF_H     (OFF_H0 + NN*DD)
#define OFF_QKV   (OFF_H  + NN*DD)
#define OFF_ATTN  (OFF_QKV + NN*3*DD)
#define OFF_TMP   (OFF_ATTN + NN*DD)
#define OFF_FF    (OFF_TMP + NN*DD)
#define OFF_WP1T  (OFF_FF + NN*FF_)
#define OFF_KH    (OFF_WP1T + 16384)
#define OFF_VTH   (OFF_KH + 524288)
#define OFF_HCH   (OFF_VTH + 524288)
#define SCRATCH_FLOATS (OFF_HCH + 524288)

__device__ float g_scratch[SCRATCH_FLOATS];

// dynamic smem sizes (bytes)
#define SGEMM_SMEM ((2*128*40 + 2*64*40) * 2)
#define ATTN_SMEM  ((2*64*40 + 2*32*72) * 2)
#define EDGE_BS_H  264                       // B row stride in halfs (256 + 8 pad)
#define EDGE_SMEM  (128*EDGE_BS_H*2 + 2*128*40*2)
#define EDGE_NU    4                         // edge units per block

// ---------------- fp16 MMA helpers ----------------
__device__ __forceinline__ uint32_t pack_h2(float lo, float hi) {
    __half2 h = __floats2half2_rn(lo, hi);
    return *reinterpret_cast<uint32_t*>(&h);
}

__device__ __forceinline__ void mma_f16(float* d, const uint32_t* a, const uint32_t* b) {
    asm("mma.sync.aligned.m16n8k16.row.col.f32.f16.f16.f32 "
        "{%0,%1,%2,%3},{%4,%5,%6,%7},{%8,%9},{%0,%1,%2,%3};"
        : "+f"(d[0]), "+f"(d[1]), "+f"(d[2]), "+f"(d[3])
        : "r"(a[0]), "r"(a[1]), "r"(a[2]), "r"(a[3]), "r"(b[0]), "r"(b[1]));
}

__device__ __forceinline__ uint32_t smem_u32(const void* p) {
    uint32_t a;
    asm("{ .reg .u64 t; cvta.to.shared.u64 t, %1; cvt.u32.u64 %0, t; }" : "=r"(a) : "l"(p));
    return a;
}
__device__ __forceinline__ void cp_async16(uint32_t dst, const void* src) {
    asm volatile("cp.async.ca.shared.global [%0], [%1], 16;" :: "r"(dst), "l"(src));
}
__device__ __forceinline__ void cp_commit() {
    asm volatile("cp.async.commit_group;" ::: "memory");
}
__device__ __forceinline__ void cp_wait0() {
    asm volatile("cp.async.wait_group 0;" ::: "memory");
}

// ---------------- Wp1 prepass: half, transposed [j][k] ----------------
__global__ __launch_bounds__(256) void wp1_prep_kernel(
    const float* __restrict__ Wp1, __half* __restrict__ wp1t)
{
    int idx = blockIdx.x * 256 + threadIdx.x;
    int k = idx >> 7, j = idx & 127;
    wp1t[j * 256 + k] = __float2half_rn(Wp1[idx]);
}

// ---------------- per-layer KV prepass ----------------
__global__ __launch_bounds__(256) void kvprep_kernel(
    const float* __restrict__ qkv, __half* __restrict__ kh, __half* __restrict__ vth)
{
    int gid = blockIdx.x * 256 + threadIdx.x;
    if (gid < 262144) {
        int idx = gid * 4;
        int h   = idx >> 17;
        int rem = idx & 131071;
        int kv  = rem >> 5;
        int d   = rem & 31;
        float4 v = *reinterpret_cast<const float4*>(qkv + (size_t)kv*768 + 256 + h*32 + d);
        __half2* o = reinterpret_cast<__half2*>(kh + idx);
        o[0] = __floats2half2_rn(v.x, v.y);
        o[1] = __floats2half2_rn(v.z, v.w);
    } else {
        int idx = (gid - 262144) * 4;
        int h   = idx >> 17;
        int rem = idx & 131071;
        int d   = rem >> 12;
        int kv  = rem & 4095;
        const float* src = qkv + 512 + h*32 + d;
        __half2* o = reinterpret_cast<__half2*>(vth + idx);
        o[0] = __floats2half2_rn(src[(size_t)kv*768],     src[(size_t)(kv+1)*768]);
        o[1] = __floats2half2_rn(src[(size_t)(kv+2)*768], src[(size_t)(kv+3)*768]);
    }
}

// ---------------- fp16 tensor-core SGEMM, ping-pong prefetch ----------------
__global__ __launch_bounds__(256) void sgemm_tc_kernel(
    int M, int N, int K,
    const float* __restrict__ A, const float* __restrict__ B,
    const float* __restrict__ bias, float* __restrict__ C, int act)
{
    extern __shared__ __align__(16) char smraw[];
    __half* As_ = (__half*)smraw;                   // [2][128][40]
    __half* Bs_ = (__half*)(smraw + 2*128*40*2);    // [2][64][40]

    const int tid  = threadIdx.x;
    const int lane = tid & 31;
    const int wid  = tid >> 5;
    const int wm   = wid >> 1;
    const int wn   = wid & 1;
    const int grp  = lane >> 2;
    const int tig  = lane & 3;

    const int bx = blockIdx.x, by = blockIdx.y;
    A += (size_t)by * 128 * K;
    B += (size_t)bx * 64;
    C += (size_t)by * 128 * N + (size_t)bx * 64;
    bias += (size_t)bx * 64;

    float acc[2][4][4] = {};
    float4 rA[4], rB[2];

    auto ldT = [&](int kt) {
        #pragma unroll
        for (int i = 0; i < 4; i++) {
            int f = tid + i * 256, r = f >> 3, c4 = f & 7;
            rA[i] = *reinterpret_cast<const float4*>(A + (size_t)r * K + kt + c4 * 4);
        }
        #pragma unroll
        for (int i = 0; i < 2; i++) {
            int f = tid + i * 256, r = f >> 4, c4 = f & 15;
            rB[i] = *reinterpret_cast<const float4*>(B + (size_t)(kt + r) * N + c4 * 4);
        }
    };
    auto stT = [&](int bb) {
        #pragma unroll
        for (int i = 0; i < 4; i++) {
            int f = tid + i * 256, r = f >> 3, c4 = f & 7;
            uint2 u;
            u.x = pack_h2(rA[i].x, rA[i].y);
            u.y = pack_h2(rA[i].z, rA[i].w);
            *reinterpret_cast<uint2*>(&As_[bb*(128*40) + r*40 + c4*4]) = u;
        }
        #pragma unroll
        for (int i = 0; i < 2; i++) {
            int f = tid + i * 256, r = f >> 4, c4 = f & 15;
            __half* bp = &Bs_[bb*(64*40)];
            bp[(c4*4+0)*40 + r] = __float2half_rn(rB[i].x);
            bp[(c4*4+1)*40 + r] = __float2half_rn(rB[i].y);
            bp[(c4*4+2)*40 + r] = __float2half_rn(rB[i].z);
            bp[(c4*4+3)*40 + r] = __float2half_rn(rB[i].w);
        }
    };

    const int T = K / 32;
    ldT(0); stT(0); __syncthreads();

    for (int t = 0; t < T; t++) {
        int cur = t & 1;
        if (t + 1 < T) ldT((t + 1) * 32);
        #pragma unroll
        for (int ks = 0; ks < 2; ks++) {
            int k0 = ks * 16 + 2 * tig;
            uint32_t a[2][4], b[4][2];
            #pragma unroll
            for (int mt = 0; mt < 2; mt++) {
                int row = wm * 32 + mt * 16 + grp;
                const __half* ap = &As_[cur*(128*40)];
                a[mt][0] = *reinterpret_cast<const uint32_t*>(&ap[row*40 + k0]);
                a[mt][1] = *reinterpret_cast<const uint32_t*>(&ap[(row+8)*40 + k0]);
                a[mt][2] = *reinterpret_cast<const uint32_t*>(&ap[row*40 + k0 + 8]);
                a[mt][3] = *reinterpret_cast<const uint32_t*>(&ap[(row+8)*40 + k0 + 8]);
            }
            #pragma unroll
            for (int nt = 0; nt < 4; nt++) {
                int col = wn * 32 + nt * 8 + grp;
                const __half* bp = &Bs_[cur*(64*40)];
                b[nt][0] = *reinterpret_cast<const uint32_t*>(&bp[col*40 + k0]);
                b[nt][1] = *reinterpret_cast<const uint32_t*>(&bp[col*40 + k0 + 8]);
            }
            #pragma unroll
            for (int mt = 0; mt < 2; mt++)
                #pragma unroll
                for (int nt = 0; nt < 4; nt++)
                    mma_f16(acc[mt][nt], a[mt], b[nt]);
        }
        if (t + 1 < T) stT((t + 1) & 1);
        __syncthreads();
    }

    #pragma unroll
    for (int mt = 0; mt < 2; mt++) {
        #pragma unroll
        for (int nt = 0; nt < 4; nt++) {
            int row = wm * 32 + mt * 16 + grp;
            int col = wn * 32 + nt * 8 + tig * 2;
            float b0 = bias[col], b1 = bias[col+1];
            float2 v0, v1;
            v0.x = acc[mt][nt][0] + b0; v0.y = acc[mt][nt][1] + b1;
            v1.x = acc[mt][nt][2] + b0; v1.y = acc[mt][nt][3] + b1;
            if (act == 1) {
                v0.x = fmaxf(v0.x, 0.f); v0.y = fmaxf(v0.y, 0.f);
                v1.x = fmaxf(v1.x, 0.f); v1.y = fmaxf(v1.y, 0.f);
            }
            *reinterpret_cast<float2*>(C + (size_t)row * N + col)     = v0;
            *reinterpret_cast<float2*>(C + (size_t)(row+8) * N + col) = v1;
        }
    }
}

// ---------------- fp16 MMA flash attention, register-fragment P (FA2) ----------------
// grid (NN/128, HH), 256 threads = 8 warps, warp owns 16 query rows.
__global__ __launch_bounds__(256) void attn_tc_kernel(
    const float* __restrict__ qkv,
    const __half* __restrict__ kh, const __half* __restrict__ vth,
    float* __restrict__ out)
{
    extern __shared__ __align__(16) char smraw[];
    __half* Ks_ = (__half*)smraw;                    // [2][64][40]
    __half* Vs_ = (__half*)(smraw + 2*64*40*2);      // [2][32][72]

    const int h  = blockIdx.y;
    const int qb = blockIdx.x * 128;
    const int tid  = threadIdx.x;
    const int lane = tid & 31;
    const int wid  = tid >> 5;
    const int grp  = lane >> 2;
    const int tig  = lane & 3;
    const float scale = 0.17677669529663687f;

    const uint32_t ks_u32 = smem_u32(Ks_);
    const uint32_t vs_u32 = smem_u32(Vs_);
    const __half* khh = kh  + (size_t)h * 131072;
    const __half* vhh = vth + (size_t)h * 131072;

    uint32_t qa[2][4];
    {
        const float* q0 = qkv + (size_t)(qb + wid*16 + grp) * 768 + h * 32;
        const float* q1 = q0 + (size_t)8 * 768;
        #pragma unroll
        for (int ks = 0; ks < 2; ks++) {
            int b = ks * 16 + 2 * tig;
            qa[ks][0] = pack_h2(q0[b]   * scale, q0[b+1] * scale);
            qa[ks][1] = pack_h2(q1[b]   * scale, q1[b+1] * scale);
            qa[ks][2] = pack_h2(q0[b+8] * scale, q0[b+9] * scale);
            qa[ks][3] = pack_h2(q1[b+8] * scale, q1[b+9] * scale);
        }
    }

    float m0 = -1e30f, m1 = -1e30f, l0 = 0.f, l1 = 0.f;
    float o[4][4] = {};

    auto cpKV = [&](int bb, int kb) {
        int r = tid >> 2, c = tid & 3;
        cp_async16(ks_u32 + (uint32_t)(bb*(64*40) + r*40 + c*8) * 2,
                   khh + (size_t)(kb + r) * 32 + c * 8);
        int r2 = tid >> 3, c2 = tid & 7;
        cp_async16(vs_u32 + (uint32_t)(bb*(32*72) + r2*72 + c2*8) * 2,
                   vhh + (size_t)r2 * 4096 + kb + c2 * 8);
        cp_commit();
    };

    cpKV(0, 0);
    cp_wait0();
    __syncthreads();

    for (int t = 0; t < NN/64; t++) {
        int cur = t & 1;
        if (t < NN/64 - 1) cpKV(cur ^ 1, (t + 1) * 64);

        // S = Q @ K^T : 16 rows x 64 kv
        float sacc[8][4] = {};
        #pragma unroll
        for (int ks = 0; ks < 2; ks++) {
            int k0 = ks * 16 + 2 * tig;
            #pragma unroll
            for (int nt = 0; nt < 8; nt++) {
                const __half* kp = &Ks_[cur*(64*40) + (nt*8+grp)*40];
                uint32_t b[2];
                b[0] = *reinterpret_cast<const uint32_t*>(&kp[k0]);
                b[1] = *reinterpret_cast<const uint32_t*>(&kp[k0 + 8]);
                mma_f16(sacc[nt], qa[ks], b);
            }
        }

        // online softmax + pack P straight into A-fragments (no smem)
        float rmax0 = -1e30f, rmax1 = -1e30f;
        #pragma unroll
        for (int nt = 0; nt < 8; nt++) {
            rmax0 = fmaxf(rmax0, fmaxf(sacc[nt][0], sacc[nt][1]));
            rmax1 = fmaxf(rmax1, fmaxf(sacc[nt][2], sacc[nt][3]));
        }
        rmax0 = fmaxf(rmax0, __shfl_xor_sync(0xffffffffu, rmax0, 1));
        rmax0 = fmaxf(rmax0, __shfl_xor_sync(0xffffffffu, rmax0, 2));
        rmax1 = fmaxf(rmax1, __shfl_xor_sync(0xffffffffu, rmax1, 1));
        rmax1 = fmaxf(rmax1, __shfl_xor_sync(0xffffffffu, rmax1, 2));
        float mn0 = fmaxf(m0, rmax0), mn1 = fmaxf(m1, rmax1);
        float a0 = __expf(m0 - mn0), a1 = __expf(m1 - mn1);
        float ps0 = 0.f, ps1 = 0.f;
        uint32_t pa[4][4];
        #pragma unroll
        for (int nt = 0; nt < 8; nt++) {
            float p00 = __expf(sacc[nt][0] - mn0);
            float p01 = __expf(sacc[nt][1] - mn0);
            float p10 = __expf(sacc[nt][2] - mn1);
            float p11 = __expf(sacc[nt][3] - mn1);
            ps0 += p00 + p01; ps1 += p10 + p11;
            int ks2 = nt >> 1, hf = (nt & 1) * 2;
            pa[ks2][hf + 0] = pack_h2(p00, p01);   // row grp
            pa[ks2][hf + 1] = pack_h2(p10, p11);   // row grp+8
        }
        // fix fragment order: a = {row g k0, row g+8 k0, row g k0+8, row g+8 k0+8}
        // pa[ks2] currently = {g lo, g+8 lo, g hi, g+8 hi} -> already correct layout
        ps0 += __shfl_xor_sync(0xffffffffu, ps0, 1);
        ps0 += __shfl_xor_sync(0xffffffffu, ps0, 2);
        ps1 += __shfl_xor_sync(0xffffffffu, ps1, 1);
        ps1 += __shfl_xor_sync(0xffffffffu, ps1, 2);
        l0 = l0 * a0 + ps0; l1 = l1 * a1 + ps1;
        m0 = mn0; m1 = mn1;
        #pragma unroll
        for (int nt = 0; nt < 4; nt++) {
            o[nt][0] *= a0; o[nt][1] *= a0;
            o[nt][2] *= a1; o[nt][3] *= a1;
        }

        // O += P @ V  (P in registers; V^T tiles in smem)
        #pragma unroll
        for (int ks = 0; ks < 4; ks++) {
            int k0 = ks * 16 + 2 * tig;
            #pragma unroll
            for (int nt = 0; nt < 4; nt++) {
                const __half* vp = &Vs_[cur*(32*72) + (nt*8+grp)*72];
                uint32_t b[2];
                b[0] = *reinterpret_cast<const uint32_t*>(&vp[k0]);
                b[1] = *reinterpret_cast<const uint32_t*>(&vp[k0 + 8]);
                mma_f16(o[nt], pa[ks], b);
            }
        }

        if (t < NN/64 - 1) cp_wait0();
        __syncthreads();
    }

    float inv0 = 1.f / l0, inv1 = 1.f / l1;
    int r0 = qb + wid*16 + grp;
    #pragma unroll
    for (int nt = 0; nt < 4; nt++) {
        int col = h * 32 + nt * 8 + tig * 2;
        *reinterpret_cast<float2*>(out + (size_t)r0 * 256 + col) =
            make_float2(o[nt][0] * inv0, o[nt][1] * inv0);
        *reinterpret_cast<float2*>(out + (size_t)(r0 + 8) * 256 + col) =
            make_float2(o[nt][2] * inv1, o[nt][3] * inv1);
    }
}

// ---------------- fused residual-add + LayerNorm (warp per row) ----------------
__global__ __launch_bounds__(256) void add_ln_kernel(
    const float* __restrict__ x, const float* __restrict__ y,
    const float* __restrict__ g, const float* __restrict__ b,
    float* __restrict__ out)
{
    int row = blockIdx.x * 8 + (threadIdx.x >> 5);
    int lid = threadIdx.x & 31;
    const float* xr = x + (size_t)row * 256;
    const float* yr = y + (size_t)row * 256;

    float4 v0 = *reinterpret_cast<const float4*>(xr + lid*4);
    float4 w0 = *reinterpret_cast<const float4*>(yr + lid*4);
    float4 v1 = *reinterpret_cast<const float4*>(xr + 128 + lid*4);
    float4 w1 = *reinterpret_cast<const float4*>(yr + 128 + lid*4);
    float a[8] = { v0.x+w0.x, v0.y+w0.y, v0.z+w0.z, v0.w+w0.w,
                   v1.x+w1.x, v1.y+w1.y, v1.z+w1.z, v1.w+w1.w };

    float s = 0.f;
    #pragma unroll
    for (int i = 0; i < 8; i++) s += a[i];
    #pragma unroll
    for (int o2 = 16; o2 > 0; o2 >>= 1) s += __shfl_xor_sync(0xffffffffu, s, o2);
    float mean = s * (1.f/256.f);

    float q = 0.f;
    #pragma unroll
    for (int i = 0; i < 8; i++) { float d = a[i] - mean; q += d*d; }
    #pragma unroll
    for (int o2 = 16; o2 > 0; o2 >>= 1) q += __shfl_xor_sync(0xffffffffu, q, o2);
    float rstd = rsqrtf(q * (1.f/256.f) + 1e-5f);

    float4 g0 = *reinterpret_cast<const float4*>(g + lid*4);
    float4 b0 = *reinterpret_cast<const float4*>(b + lid*4);
    float4 g1 = *reinterpret_cast<const float4*>(g + 128 + lid*4);
    float4 b1 = *reinterpret_cast<const float4*>(b + 128 + lid*4);
    float4 r0, r1;
    r0.x = (a[0]-mean)*rstd*g0.x + b0.x; r0.y = (a[1]-mean)*rstd*g0.y + b0.y;
    r0.z = (a[2]-mean)*rstd*g0.z + b0.z; r0.w = (a[3]-mean)*rstd*g0.w + b0.w;
    r1.x = (a[4]-mean)*rstd*g1.x + b1.x; r1.y = (a[5]-mean)*rstd*g1.y + b1.y;
    r1.z = (a[6]-mean)*rstd*g1.z + b1.z; r1.w = (a[7]-mean)*rstd*g1.w + b1.w;
    *reinterpret_cast<float4*>(out + (size_t)row*256 + lid*4)       = r0;
    *reinterpret_cast<float4*>(out + (size_t)row*256 + 128 + lid*4) = r1;
}

// final layer: h_combined = LN(x+y) + h0, write fp32 tail + fp16 copy
__global__ __launch_bounds__(256) void add_ln_hc_kernel(
    const float* __restrict__ x, const float* __restrict__ y,
    const float* __restrict__ g, const float* __restrict__ b,
    const float* __restrict__ h0,
    float* __restrict__ out_tail, __half* __restrict__ hch)
{
    int row = blockIdx.x * 8 + (threadIdx.x >> 5);
    int lid = threadIdx.x & 31;
    const float* xr = x + (size_t)row * 256;
    const float* yr = y + (size_t)row * 256;
    const float* hr = h0 + (size_t)row * 256;

    float4 v0 = *reinterpret_cast<const float4*>(xr + lid*4);
    float4 w0 = *reinterpret_cast<const float4*>(yr + lid*4);
    float4 v1 = *reinterpret_cast<const float4*>(xr + 128 + lid*4);
    float4 w1 = *reinterpret_cast<const float4*>(yr + 128 + lid*4);
    float a[8] = { v0.x+w0.x, v0.y+w0.y, v0.z+w0.z, v0.w+w0.w,
                   v1.x+w1.x, v1.y+w1.y, v1.z+w1.z, v1.w+w1.w };

    float s = 0.f;
    #pragma unroll
    for (int i = 0; i < 8; i++) s += a[i];
    #pragma unroll
    for (int o2 = 16; o2 > 0; o2 >>= 1) s += __shfl_xor_sync(0xffffffffu, s, o2);
    float mean = s * (1.f/256.f);

    float q = 0.f;
    #pragma unroll
    for (int i = 0; i < 8; i++) { float d = a[i] - mean; q += d*d; }
    #pragma unroll
    for (int o2 = 16; o2 > 0; o2 >>= 1) q += __shfl_xor_sync(0xffffffffu, q, o2);
    float rstd = rsqrtf(q * (1.f/256.f) + 1e-5f);

    float4 g0 = *reinterpret_cast<const float4*>(g + lid*4);
    float4 b0 = *reinterpret_cast<const float4*>(b + lid*4);
    float4 g1 = *reinterpret_cast<const float4*>(g + 128 + lid*4);
    float4 b1 = *reinterpret_cast<const float4*>(b + 128 + lid*4);
    float4 h00 = *reinterpret_cast<const float4*>(hr + lid*4);
    float4 h01 = *reinterpret_cast<const float4*>(hr + 128 + lid*4);

    float4 c0, c1;
    c0.x = (a[0]-mean)*rstd*g0.x + b0.x + h00.x;
    c0.y = (a[1]-mean)*rstd*g0.y + b0.y + h00.y;
    c0.z = (a[2]-mean)*rstd*g0.z + b0.z + h00.z;
    c0.w = (a[3]-mean)*rstd*g0.w + b0.w + h00.w;
    c1.x = (a[4]-mean)*rstd*g1.x + b1.x + h01.x;
    c1.y = (a[5]-mean)*rstd*g1.y + b1.y + h01.y;
    c1.z = (a[6]-mean)*rstd*g1.z + b1.z + h01.z;
    c1.w = (a[7]-mean)*rstd*g1.w + b1.w + h01.w;

    *reinterpret_cast<float4*>(out_tail + (size_t)row*256 + lid*4)       = c0;
    *reinterpret_cast<float4*>(out_tail + (size_t)row*256 + 128 + lid*4) = c1;

    uint2 u0, u1;
    u0.x = pack_h2(c0.x, c0.y); u0.y = pack_h2(c0.z, c0.w);
    u1.x = pack_h2(c1.x, c1.y); u1.y = pack_h2(c1.z, c1.w);
    *reinterpret_cast<uint2*>(hch + (size_t)row*256 + lid*4)       = u0;
    *reinterpret_cast<uint2*>(hch + (size_t)row*256 + 128 + lid*4) = u1;
}

// ---------------- fused edge predictor: persistent Wp1 in smem, 4 units/block ----------------
__global__ __launch_bounds__(256) void edge_tc_kernel(
    const __half* __restrict__ hch,
    const int* __restrict__ psrc, const int* __restrict__ pdst, const float* __restrict__ pw,
    const int* __restrict__ nsrc, const int* __restrict__ ndst, const float* __restrict__ nw,
    const __half* __restrict__ wp1t, const float* __restrict__ bp1,
    const float* __restrict__ Wp2, const float* __restrict__ bp2,
    float* __restrict__ out, int E, int nblk)
{
    extern __shared__ __align__(16) char smraw[];
    __half* Bs_ = (__half*)smraw;                        // [128][264]  (persistent)
    __half* As_ = (__half*)(smraw + 128*EDGE_BS_H*2);    // [2][128][40]
    __shared__ int      sSrc[128], sDst[128];
    __shared__ uint32_t sWh[128];
    __shared__ float    sWp2[128], sBp1[128];
    __shared__ float    sred[128][2];

    const int tid  = threadIdx.x;
    const int lane = tid & 31;
    const int wid  = tid >> 5;
    const int wm   = wid >> 1;
    const int wn   = wid & 1;
    const int grp  = lane >> 2;
    const int tig  = lane & 3;

    const uint32_t bs_u32 = smem_u32(Bs_);

    // load full Wp1 [128 j][256 k] once: 4096 16B chunks, 16 per thread
    #pragma unroll
    for (int i = 0; i < 16; i++) {
        int cid = tid + i * 256;
        int j = cid >> 5, c = cid & 31;
        cp_async16(bs_u32 + (uint32_t)(j * EDGE_BS_H + c * 8) * 2,
                   wp1t + (size_t)j * 256 + c * 8);
    }
    cp_commit();
    if (tid < 128) { sWp2[tid] = Wp2[tid]; sBp1[tid] = bp1[tid]; }
    cp_wait0();
    __syncthreads();

    const float bp2v = bp2[0];
    uint4 gs[2], gd[2];

    auto ldA = [&](int kt) {
        #pragma unroll
        for (int i = 0; i < 2; i++) {
            int f = tid + i * 256, e = f >> 2, q = f & 3;
            gs[i] = *reinterpret_cast<const uint4*>(hch + (size_t)sSrc[e]*256 + kt*32 + q*8);
            gd[i] = *reinterpret_cast<const uint4*>(hch + (size_t)sDst[e]*256 + kt*32 + q*8);
        }
    };
    auto stA = [&](int bb) {
        #pragma unroll
        for (int i = 0; i < 2; i++) {
            int f = tid + i * 256, e = f >> 2, q = f & 3;
            __half2 w2 = *reinterpret_cast<const __half2*>(&sWh[e]);
            const __half2* sp = reinterpret_cast<const __half2*>(&gs[i]);
            const __half2* dp = reinterpret_cast<const __half2*>(&gd[i]);
            uint4 r;
            __half2* rp = reinterpret_cast<__half2*>(&r);
            rp[0] = __hmul2(__hmul2(sp[0], dp[0]), w2);
            rp[1] = __hmul2(__hmul2(sp[1], dp[1]), w2);
            rp[2] = __hmul2(__hmul2(sp[2], dp[2]), w2);
            rp[3] = __hmul2(__hmul2(sp[3], dp[3]), w2);
            *reinterpret_cast<uint4*>(&As_[bb*(128*40) + e*40 + q*8]) = r;
        }
    };

    for (int uu = 0; uu < EDGE_NU; uu++) {
        int u = blockIdx.x * EDGE_NU + uu;
        if (u >= 2 * nblk) break;
        const int pol = (u >= nblk) ? 1 : 0;
        const int blk = u - pol * nblk;
        const int e0  = blk * 128;
        const int* srcA = pol ? nsrc : psrc;
        const int* dstA = pol ? ndst : pdst;
        const float* wA = pol ? nw   : pw;
        float* op = out + (pol ? (size_t)E : 0);

        if (tid < 128) {
            int e = e0 + tid;
            float wv = (e < E) ? wA[e] : 0.f;
            if (e < E) { sSrc[tid] = srcA[e]; sDst[tid] = dstA[e]; }
            else       { sSrc[tid] = 0;       sDst[tid] = 0; }
            sWh[tid] = pack_h2(wv, wv);
        }
        __syncthreads();

        float acc[2][8][4] = {};

        ldA(0);
        stA(0);
        __syncthreads();

        for (int t = 0; t < 8; t++) {
            int cur = t & 1;
            if (t < 7) ldA(t + 1);
            #pragma unroll
            for (int ks = 0; ks < 2; ks++) {
                int k0g = t * 32 + ks * 16 + 2 * tig;   // global k into persistent B
                int k0  = ks * 16 + 2 * tig;            // local k into A tile
                uint32_t a[2][4], b[8][2];
                #pragma unroll
                for (int mt = 0; mt < 2; mt++) {
                    int row = wm * 32 + mt * 16 + grp;
                    const __half* ap = &As_[cur*(128*40)];
                    a[mt][0] = *reinterpret_cast<const uint32_t*>(&ap[row*40 + k0]);
                    a[mt][1] = *reinterpret_cast<const uint32_t*>(&ap[(row+8)*40 + k0]);
                    a[mt][2] = *reinterpret_cast<const uint32_t*>(&ap[row*40 + k0 + 8]);
                    a[mt][3] = *reinterpret_cast<const uint32_t*>(&ap[(row+8)*40 + k0 + 8]);
                }
                #pragma unroll
                for (int nt = 0; nt < 8; nt++) {
                    int j = wn * 64 + nt * 8 + grp;
                    b[nt][0] = *reinterpret_cast<const uint32_t*>(&Bs_[j*EDGE_BS_H + k0g]);
                    b[nt][1] = *reinterpret_cast<const uint32_t*>(&Bs_[j*EDGE_BS_H + k0g + 8]);
                }
                #pragma unroll
                for (int mt = 0; mt < 2; mt++)
                    #pragma unroll
                    for (int nt = 0; nt < 8; nt++)
                        mma_f16(acc[mt][nt], a[mt], b[nt]);
            }
            if (t < 7) stA((t + 1) & 1);
            __syncthreads();
        }

        // epilogue: leaky(acc + bp1) . Wp2
        #pragma unroll
        for (int mt = 0; mt < 2; mt++) {
            float p0 = 0.f, p1 = 0.f;
            #pragma unroll
            for (int nt = 0; nt < 8; nt++) {
                int col = wn * 64 + nt * 8 + tig * 2;
                float bb0 = sBp1[col], bb1 = sBp1[col+1];
                float w0  = sWp2[col], w1  = sWp2[col+1];
                float y;
                y = acc[mt][nt][0] + bb0; y = (y > 0.f) ? y : 0.2f*y; p0 += y * w0;
                y = acc[mt][nt][1] + bb1; y = (y > 0.f) ? y : 0.2f*y; p0 += y * w1;
                y = acc[mt][nt][2] + bb0; y = (y > 0.f) ? y : 0.2f*y; p1 += y * w0;
                y = acc[mt][nt][3] + bb1; y = (y > 0.f) ? y : 0.2f*y; p1 += y * w1;
            }
            p0 += __shfl_xor_sync(0xffffffffu, p0, 1);
            p0 += __shfl_xor_sync(0xffffffffu, p0, 2);
            p1 += __shfl_xor_sync(0xffffffffu, p1, 1);
            p1 += __shfl_xor_sync(0xffffffffu, p1, 2);
            if (tig == 0) {
                int r0 = wm * 32 + mt * 16 + grp;
                sred[r0    ][wn] = p0;
                sred[r0 + 8][wn] = p1;
            }
        }
        __syncthreads();

        if (tid < 128) {
            int e = e0 + tid;
            if (e < E) op[e] = sred[tid][0] + sred[tid][1] + bp2v;
        }
        __syncthreads();
    }
}

// ---------------- host orchestration ----------------
extern "C" void kernel_launch(void* const* d_in, const int* in_sizes, int n_in,
                              void* d_out, int out_size)
{
    const float* x        = (const float*)d_in[0];
    const int*   pos_src  = (const int*)  d_in[1];
    const int*   pos_dst  = (const int*)  d_in[2];
    const float* pos_w    = (const float*)d_in[3];
    const int*   neg_src  = (const int*)  d_in[4];
    const int*   neg_dst  = (const int*)  d_in[5];
    const float* neg_w    = (const float*)d_in[6];
    const float* Wi       = (const float*)d_in[7];
    const float* bi       = (const float*)d_in[8];
    const float* Wqkv     = (const float*)d_in[9];
    const float* bqkv     = (const float*)d_in[10];
    const float* Wo       = (const float*)d_in[11];
    const float* bo       = (const float*)d_in[12];
    const float* g1       = (const float*)d_in[13];
    const float* be1      = (const float*)d_in[14];
    const float* g2       = (const float*)d_in[15];
    const float* be2      = (const float*)d_in[16];
    const float* W1       = (const float*)d_in[17];
    const float* b1       = (const float*)d_in[18];
    const float* W2       = (const float*)d_in[19];
    const float* b2       = (const float*)d_in[20];
    const float* Wp1      = (const float*)d_in[21];
    const float* bp1      = (const float*)d_in[22];
    const float* Wp2      = (const float*)d_in[23];
    const float* bp2      = (const float*)d_in[24];

    const int E = in_sizes[1];   // 500000

    cudaFuncSetAttribute(sgemm_tc_kernel, cudaFuncAttributeMaxDynamicSharedMemorySize, SGEMM_SMEM);
    cudaFuncSetAttribute(attn_tc_kernel,  cudaFuncAttributeMaxDynamicSharedMemorySize, ATTN_SMEM);
    cudaFuncSetAttribute(edge_tc_kernel,  cudaFuncAttributeMaxDynamicSharedMemorySize, EDGE_SMEM);

    float* S = nullptr;
    cudaGetSymbolAddress((void**)&S, g_scratch);
    float* h0    = S + OFF_H0;
    float* h     = S + OFF_H;
    float* qkv   = S + OFF_QKV;
    float* attn  = S + OFF_ATTN;
    float* tmp   = S + OFF_TMP;
    float* ff    = S + OFF_FF;
    __half* wp1t = (__half*)(S + OFF_WP1T);
    __half* kh   = (__half*)(S + OFF_KH);
    __half* vth  = (__half*)(S + OFF_VTH);
    __half* hch  = (__half*)(S + OFF_HCH);
    float* out   = (float*)d_out;

    wp1_prep_kernel<<<128, 256>>>(Wp1, wp1t);

    sgemm_tc_kernel<<<dim3(DD/64, NN/128), 256, SGEMM_SMEM>>>(NN, DD, INF_, x, Wi, bi, h0, 0);

    for (int l = 0; l < LL; l++) {
        const float* hin = (l == 0) ? h0 : h;
        sgemm_tc_kernel<<<dim3(768/64, NN/128), 256, SGEMM_SMEM>>>(NN, 768, DD,
            hin, Wqkv + (size_t)l*DD*768, bqkv + (size_t)l*768, qkv, 0);
        kvprep_kernel<<<2048, 256>>>(qkv, kh, vth);
        attn_tc_kernel<<<dim3(NN/128, HH), 256, ATTN_SMEM>>>(qkv, kh, vth, attn);
        sgemm_tc_kernel<<<dim3(DD/64, NN/128), 256, SGEMM_SMEM>>>(NN, DD, DD,
            attn, Wo + (size_t)l*DD*DD, bo + (size_t)l*DD, tmp, 0);
        add_ln_kernel<<<NN/8, 256>>>(hin, tmp, g1 + (size_t)l*DD, be1 + (size_t)l*DD, h);
        sgemm_tc_kernel<<<dim3(FF_/64, NN/128), 256, SGEMM_SMEM>>>(NN, FF_, DD,
            h, W1 + (size_t)l*DD*FF_, b1 + (size_t)l*FF_, ff, 1);
        sgemm_tc_kernel<<<dim3(DD/64, NN/128), 256, SGEMM_SMEM>>>(NN, DD, FF_,
            ff, W2 + (size_t)l*FF_*DD, b2 + (size_t)l*DD, tmp, 0);
        if (l == LL - 1) {
            add_ln_hc_kernel<<<NN/8, 256>>>(h, tmp, g2 + (size_t)l*DD, be2 + (size_t)l*DD,
                                            h0, out + 2*(size_t)E, hch);
        } else {
            add_ln_kernel<<<NN/8, 256>>>(h, tmp, g2 + (size_t)l*DD, be2 + (size_t)l*DD, h);
        }
    }

    // edge predictor: persistent-B blocks, 4 units each
    const int nblk = (E + 127) / 128;
    const int units = 2 * nblk;
    const int egrid = (units + EDGE_NU - 1) / EDGE_NU;
    edge_tc_kernel<<<egrid, 256, EDGE_SMEM>>>(
        hch, pos_src, pos_dst, pos_w, neg_src, neg_dst, neg_w,
        wp1t, bp1, Wp2, bp2, out, E, nblk);
}

// round 12
// speedup vs baseline: 5.9644x; 1.1017x over previous
#include <cuda_runtime.h>
#include <cuda_fp16.h>
#include <math.h>
#include <stdint.h>

// ---------------- problem constants ----------------
#define NN   4096
#define INF_ 512
#define DD   256
#define LL   2
#define HH   8
#define DH   32
#define FF_  1024
#define HALF_ 128

// ---------------- scratch (device global, no allocs) ----------------
#define OFF_H0    0
#define OFF_H     (OFF_H0 + NN*DD)
#define OFF_QKV   (OFF_H  + NN*DD)
#define OFF_ATTN  (OFF_QKV + NN*3*DD)
#define OFF_TMP   (OFF_ATTN + NN*DD)
#define OFF_FF    (OFF_TMP + NN*DD)
#define OFF_WP1T  (OFF_FF + NN*FF_)
#define OFF_KH    (OFF_WP1T + 16384)
#define OFF_VTH   (OFF_KH + 524288)
#define OFF_HCH   (OFF_VTH + 524288)
#define SCRATCH_FLOATS (OFF_HCH + 524288)

__device__ float g_scratch[SCRATCH_FLOATS];

// dynamic smem sizes (bytes)
#define SGEMM_SMEM ((2*128*40 + 2*64*40) * 2)
#define ATTN_SMEM  ((2*64*40 + 2*32*72) * 2)
#define EDGE_BS_H  264
#define EDGE_SMEM  (128*EDGE_BS_H*2 + 2*128*40*2)
#define EDGE_NU    8

// ---------------- fp16 MMA helpers ----------------
__device__ __forceinline__ uint32_t pack_h2(float lo, float hi) {
    __half2 h = __floats2half2_rn(lo, hi);
    return *reinterpret_cast<uint32_t*>(&h);
}

__device__ __forceinline__ void mma_f16(float* d, const uint32_t* a, const uint32_t* b) {
    asm("mma.sync.aligned.m16n8k16.row.col.f32.f16.f16.f32 "
        "{%0,%1,%2,%3},{%4,%5,%6,%7},{%8,%9},{%0,%1,%2,%3};"
        : "+f"(d[0]), "+f"(d[1]), "+f"(d[2]), "+f"(d[3])
        : "r"(a[0]), "r"(a[1]), "r"(a[2]), "r"(a[3]), "r"(b[0]), "r"(b[1]));
}

__device__ __forceinline__ void ldsm_x4(uint32_t* r, uint32_t addr) {
    asm volatile("ldmatrix.sync.aligned.m8n8.x4.shared.b16 {%0,%1,%2,%3}, [%4];"
        : "=r"(r[0]), "=r"(r[1]), "=r"(r[2]), "=r"(r[3]) : "r"(addr));
}

__device__ __forceinline__ uint32_t smem_u32(const void* p) {
    uint32_t a;
    asm("{ .reg .u64 t; cvta.to.shared.u64 t, %1; cvt.u32.u64 %0, t; }" : "=r"(a) : "l"(p));
    return a;
}
__device__ __forceinline__ void cp_async16(uint32_t dst, const void* src) {
    asm volatile("cp.async.ca.shared.global [%0], [%1], 16;" :: "r"(dst), "l"(src));
}
__device__ __forceinline__ void cp_commit() {
    asm volatile("cp.async.commit_group;" ::: "memory");
}
__device__ __forceinline__ void cp_wait0() {
    asm volatile("cp.async.wait_group 0;" ::: "memory");
}

// ldmatrix per-thread offset helpers (within a 16-row fragment group):
//  A (m16k16): row = base + (lane&15), k-half = (lane>>4)&1  -> +16 bytes
//  B (two n8 tiles x k16): n = (lane&7) + ((lane>>4)<<3), k-half = (lane>>3)&1 -> +16 bytes

// ---------------- Wp1 prepass: half, transposed [j][k] ----------------
__global__ __launch_bounds__(256) void wp1_prep_kernel(
    const float* __restrict__ Wp1, __half* __restrict__ wp1t)
{
    int idx = blockIdx.x * 256 + threadIdx.x;
    int k = idx >> 7, j = idx & 127;
    wp1t[j * 256 + k] = __float2half_rn(Wp1[idx]);
}

// ---------------- per-layer KV prepass ----------------
__global__ __launch_bounds__(256) void kvprep_kernel(
    const float* __restrict__ qkv, __half* __restrict__ kh, __half* __restrict__ vth)
{
    int gid = blockIdx.x * 256 + threadIdx.x;
    if (gid < 262144) {
        int idx = gid * 4;
        int h   = idx >> 17;
        int rem = idx & 131071;
        int kv  = rem >> 5;
        int d   = rem & 31;
        float4 v = *reinterpret_cast<const float4*>(qkv + (size_t)kv*768 + 256 + h*32 + d);
        __half2* o = reinterpret_cast<__half2*>(kh + idx);
        o[0] = __floats2half2_rn(v.x, v.y);
        o[1] = __floats2half2_rn(v.z, v.w);
    } else {
        int idx = (gid - 262144) * 4;
        int h   = idx >> 17;
        int rem = idx & 131071;
        int d   = rem >> 12;
        int kv  = rem & 4095;
        const float* src = qkv + 512 + h*32 + d;
        __half2* o = reinterpret_cast<__half2*>(vth + idx);
        o[0] = __floats2half2_rn(src[(size_t)kv*768],     src[(size_t)(kv+1)*768]);
        o[1] = __floats2half2_rn(src[(size_t)(kv+2)*768], src[(size_t)(kv+3)*768]);
    }
}

// ---------------- fp16 tensor-core SGEMM, ping-pong + ldmatrix ----------------
__global__ __launch_bounds__(256) void sgemm_tc_kernel(
    int M, int N, int K,
    const float* __restrict__ A, const float* __restrict__ B,
    const float* __restrict__ bias, float* __restrict__ C, int act)
{
    extern __shared__ __align__(16) char smraw[];
    __half* As_ = (__half*)smraw;                   // [2][128][40]
    __half* Bs_ = (__half*)(smraw + 2*128*40*2);    // [2][64][40]

    const int tid  = threadIdx.x;
    const int lane = tid & 31;
    const int wid  = tid >> 5;
    const int wm   = wid >> 1;
    const int wn   = wid & 1;
    const int grp  = lane >> 2;
    const int tig  = lane & 3;

    const int bx = blockIdx.x, by = blockIdx.y;
    A += (size_t)by * 128 * K;
    B += (size_t)bx * 64;
    C += (size_t)by * 128 * N + (size_t)bx * 64;
    bias += (size_t)bx * 64;

    const uint32_t as_b = smem_u32(As_);
    const uint32_t bs_b = smem_u32(Bs_);
    // ldmatrix per-thread offsets
    const int a_row = lane & 15;
    const int a_kh  = (lane >> 4) & 1;
    const int b_n   = (lane & 7) + ((lane >> 4) << 3);
    const int b_kh  = (lane >> 3) & 1;
    uint32_t aAddr[2], bAddr[2];
    #pragma unroll
    for (int mt = 0; mt < 2; mt++)
        aAddr[mt] = as_b + (uint32_t)((wm*32 + mt*16 + a_row) * 40) * 2 + a_kh * 16;
    #pragma unroll
    for (int pr = 0; pr < 2; pr++)
        bAddr[pr] = bs_b + (uint32_t)((wn*32 + pr*16 + b_n) * 40) * 2 + b_kh * 16;

    float acc[2][4][4] = {};
    float4 rA[4], rB[2];

    auto ldT = [&](int kt) {
        #pragma unroll
        for (int i = 0; i < 4; i++) {
            int f = tid + i * 256, r = f >> 3, c4 = f & 7;
            rA[i] = *reinterpret_cast<const float4*>(A + (size_t)r * K + kt + c4 * 4);
        }
        #pragma unroll
        for (int i = 0; i < 2; i++) {
            int f = tid + i * 256, r = f >> 4, c4 = f & 15;
            rB[i] = *reinterpret_cast<const float4*>(B + (size_t)(kt + r) * N + c4 * 4);
        }
    };
    auto stT = [&](int bb) {
        #pragma unroll
        for (int i = 0; i < 4; i++) {
            int f = tid + i * 256, r = f >> 3, c4 = f & 7;
            uint2 u;
            u.x = pack_h2(rA[i].x, rA[i].y);
            u.y = pack_h2(rA[i].z, rA[i].w);
            *reinterpret_cast<uint2*>(&As_[bb*(128*40) + r*40 + c4*4]) = u;
        }
        #pragma unroll
        for (int i = 0; i < 2; i++) {
            int f = tid + i * 256, r = f >> 4, c4 = f & 15;
            __half* bp = &Bs_[bb*(64*40)];
            bp[(c4*4+0)*40 + r] = __float2half_rn(rB[i].x);
            bp[(c4*4+1)*40 + r] = __float2half_rn(rB[i].y);
            bp[(c4*4+2)*40 + r] = __float2half_rn(rB[i].z);
            bp[(c4*4+3)*40 + r] = __float2half_rn(rB[i].w);
        }
    };

    const int T = K / 32;
    ldT(0); stT(0); __syncthreads();

    for (int t = 0; t < T; t++) {
        int cur = t & 1;
        uint32_t curA = cur * (128*40*2);
        uint32_t curB = cur * (64*40*2);
        if (t + 1 < T) ldT((t + 1) * 32);
        #pragma unroll
        for (int ks = 0; ks < 2; ks++) {
            uint32_t a[2][4], b[2][4];
            ldsm_x4(a[0], aAddr[0] + curA + ks*32);
            ldsm_x4(a[1], aAddr[1] + curA + ks*32);
            ldsm_x4(b[0], bAddr[0] + curB + ks*32);
            ldsm_x4(b[1], bAddr[1] + curB + ks*32);
            #pragma unroll
            for (int mt = 0; mt < 2; mt++) {
                mma_f16(acc[mt][0], a[mt], b[0]);
                mma_f16(acc[mt][1], a[mt], b[0] + 2);
                mma_f16(acc[mt][2], a[mt], b[1]);
                mma_f16(acc[mt][3], a[mt], b[1] + 2);
            }
        }
        if (t + 1 < T) stT((t + 1) & 1);
        __syncthreads();
    }

    #pragma unroll
    for (int mt = 0; mt < 2; mt++) {
        #pragma unroll
        for (int nt = 0; nt < 4; nt++) {
            int row = wm * 32 + mt * 16 + grp;
            int col = wn * 32 + nt * 8 + tig * 2;
            float b0 = bias[col], b1 = bias[col+1];
            float2 v0, v1;
            v0.x = acc[mt][nt][0] + b0; v0.y = acc[mt][nt][1] + b1;
            v1.x = acc[mt][nt][2] + b0; v1.y = acc[mt][nt][3] + b1;
            if (act == 1) {
                v0.x = fmaxf(v0.x, 0.f); v0.y = fmaxf(v0.y, 0.f);
                v1.x = fmaxf(v1.x, 0.f); v1.y = fmaxf(v1.y, 0.f);
            }
            *reinterpret_cast<float2*>(C + (size_t)row * N + col)     = v0;
            *reinterpret_cast<float2*>(C + (size_t)(row+8) * N + col) = v1;
        }
    }
}

// ---------------- fp16 MMA flash attention, ldmatrix + exp2 ----------------
__global__ __launch_bounds__(256) void attn_tc_kernel(
    const float* __restrict__ qkv,
    const __half* __restrict__ kh, const __half* __restrict__ vth,
    float* __restrict__ out)
{
    extern __shared__ __align__(16) char smraw[];
    __half* Ks_ = (__half*)smraw;                    // [2][64][40]
    __half* Vs_ = (__half*)(smraw + 2*64*40*2);      // [2][32][72]

    const int h  = blockIdx.y;
    const int qb = blockIdx.x * 128;
    const int tid  = threadIdx.x;
    const int lane = tid & 31;
    const int wid  = tid >> 5;
    const int grp  = lane >> 2;
    const int tig  = lane & 3;
    const float scale = 0.17677669529663687f * 1.4426950408889634f;  // 1/sqrt(32) * log2(e)

    const uint32_t ks_u32 = smem_u32(Ks_);
    const uint32_t vs_u32 = smem_u32(Vs_);
    const __half* khh = kh  + (size_t)h * 131072;
    const __half* vhh = vth + (size_t)h * 131072;

    // ldmatrix B offsets
    const int b_n  = (lane & 7) + ((lane >> 4) << 3);
    const int b_kh = (lane >> 3) & 1;
    uint32_t kAddr[4], vAddr[2];
    #pragma unroll
    for (int pr = 0; pr < 4; pr++)
        kAddr[pr] = ks_u32 + (uint32_t)((pr*16 + b_n) * 40) * 2 + b_kh * 16;
    #pragma unroll
    for (int pr = 0; pr < 2; pr++)
        vAddr[pr] = vs_u32 + (uint32_t)((pr*16 + b_n) * 72) * 2 + b_kh * 16;

    uint32_t qa[2][4];
    {
        const float* q0 = qkv + (size_t)(qb + wid*16 + grp) * 768 + h * 32;
        const float* q1 = q0 + (size_t)8 * 768;
        #pragma unroll
        for (int ks = 0; ks < 2; ks++) {
            int b = ks * 16 + 2 * tig;
            qa[ks][0] = pack_h2(q0[b]   * scale, q0[b+1] * scale);
            qa[ks][1] = pack_h2(q1[b]   * scale, q1[b+1] * scale);
            qa[ks][2] = pack_h2(q0[b+8] * scale, q0[b+9] * scale);
            qa[ks][3] = pack_h2(q1[b+8] * scale, q1[b+9] * scale);
        }
    }

    float m0 = -1e30f, m1 = -1e30f, l0 = 0.f, l1 = 0.f;
    float o[4][4] = {};

    auto cpKV = [&](int bb, int kb) {
        int r = tid >> 2, c = tid & 3;
        cp_async16(ks_u32 + (uint32_t)(bb*(64*40) + r*40 + c*8) * 2,
                   khh + (size_t)(kb + r) * 32 + c * 8);
        int r2 = tid >> 3, c2 = tid & 7;
        cp_async16(vs_u32 + (uint32_t)(bb*(32*72) + r2*72 + c2*8) * 2,
                   vhh + (size_t)r2 * 4096 + kb + c2 * 8);
        cp_commit();
    };

    cpKV(0, 0);
    cp_wait0();
    __syncthreads();

    for (int t = 0; t < NN/64; t++) {
        int cur = t & 1;
        uint32_t curK = cur * (64*40*2);
        uint32_t curV = cur * (32*72*2);
        if (t < NN/64 - 1) cpKV(cur ^ 1, (t + 1) * 64);

        // S = Q @ K^T : 16 rows x 64 kv
        float sacc[8][4] = {};
        #pragma unroll
        for (int ks = 0; ks < 2; ks++) {
            #pragma unroll
            for (int pr = 0; pr < 4; pr++) {
                uint32_t b[4];
                ldsm_x4(b, kAddr[pr] + curK + ks*32);
                mma_f16(sacc[pr*2    ], qa[ks], b);
                mma_f16(sacc[pr*2 + 1], qa[ks], b + 2);
            }
        }

        // online softmax (log2 domain) + register-fragment P
        float rmax0 = -1e30f, rmax1 = -1e30f;
        #pragma unroll
        for (int nt = 0; nt < 8; nt++) {
            rmax0 = fmaxf(rmax0, fmaxf(sacc[nt][0], sacc[nt][1]));
            rmax1 = fmaxf(rmax1, fmaxf(sacc[nt][2], sacc[nt][3]));
        }
        rmax0 = fmaxf(rmax0, __shfl_xor_sync(0xffffffffu, rmax0, 1));
        rmax0 = fmaxf(rmax0, __shfl_xor_sync(0xffffffffu, rmax0, 2));
        rmax1 = fmaxf(rmax1, __shfl_xor_sync(0xffffffffu, rmax1, 1));
        rmax1 = fmaxf(rmax1, __shfl_xor_sync(0xffffffffu, rmax1, 2));
        float mn0 = fmaxf(m0, rmax0), mn1 = fmaxf(m1, rmax1);
        float a0 = exp2f(m0 - mn0), a1 = exp2f(m1 - mn1);
        float ps0 = 0.f, ps1 = 0.f;
        uint32_t pa[4][4];
        #pragma unroll
        for (int nt = 0; nt < 8; nt++) {
            float p00 = exp2f(sacc[nt][0] - mn0);
            float p01 = exp2f(sacc[nt][1] - mn0);
            float p10 = exp2f(sacc[nt][2] - mn1);
            float p11 = exp2f(sacc[nt][3] - mn1);
            ps0 += p00 + p01; ps1 += p10 + p11;
            int ks2 = nt >> 1, hf = (nt & 1) * 2;
            pa[ks2][hf + 0] = pack_h2(p00, p01);
            pa[ks2][hf + 1] = pack_h2(p10, p11);
        }
        ps0 += __shfl_xor_sync(0xffffffffu, ps0, 1);
        ps0 += __shfl_xor_sync(0xffffffffu, ps0, 2);
        ps1 += __shfl_xor_sync(0xffffffffu, ps1, 1);
        ps1 += __shfl_xor_sync(0xffffffffu, ps1, 2);
        l0 = l0 * a0 + ps0; l1 = l1 * a1 + ps1;
        m0 = mn0; m1 = mn1;
        #pragma unroll
        for (int nt = 0; nt < 4; nt++) {
            o[nt][0] *= a0; o[nt][1] *= a0;
            o[nt][2] *= a1; o[nt][3] *= a1;
        }

        // O += P @ V
        #pragma unroll
        for (int ks = 0; ks < 4; ks++) {
            #pragma unroll
            for (int pr = 0; pr < 2; pr++) {
                uint32_t b[4];
                ldsm_x4(b, vAddr[pr] + curV + ks*32);
                mma_f16(o[pr*2    ], pa[ks], b);
                mma_f16(o[pr*2 + 1], pa[ks], b + 2);
            }
        }

        if (t < NN/64 - 1) cp_wait0();
        __syncthreads();
    }

    float inv0 = 1.f / l0, inv1 = 1.f / l1;
    int r0 = qb + wid*16 + grp;
    #pragma unroll
    for (int nt = 0; nt < 4; nt++) {
        int col = h * 32 + nt * 8 + tig * 2;
        *reinterpret_cast<float2*>(out + (size_t)r0 * 256 + col) =
            make_float2(o[nt][0] * inv0, o[nt][1] * inv0);
        *reinterpret_cast<float2*>(out + (size_t)(r0 + 8) * 256 + col) =
            make_float2(o[nt][2] * inv1, o[nt][3] * inv1);
    }
}

// ---------------- fused residual-add + LayerNorm (warp per row) ----------------
__global__ __launch_bounds__(256) void add_ln_kernel(
    const float* __restrict__ x, const float* __restrict__ y,
    const float* __restrict__ g, const float* __restrict__ b,
    float* __restrict__ out)
{
    int row = blockIdx.x * 8 + (threadIdx.x >> 5);
    int lid = threadIdx.x & 31;
    const float* xr = x + (size_t)row * 256;
    const float* yr = y + (size_t)row * 256;

    float4 v0 = *reinterpret_cast<const float4*>(xr + lid*4);
    float4 w0 = *reinterpret_cast<const float4*>(yr + lid*4);
    float4 v1 = *reinterpret_cast<const float4*>(xr + 128 + lid*4);
    float4 w1 = *reinterpret_cast<const float4*>(yr + 128 + lid*4);
    float a[8] = { v0.x+w0.x, v0.y+w0.y, v0.z+w0.z, v0.w+w0.w,
                   v1.x+w1.x, v1.y+w1.y, v1.z+w1.z, v1.w+w1.w };

    float s = 0.f;
    #pragma unroll
    for (int i = 0; i < 8; i++) s += a[i];
    #pragma unroll
    for (int o2 = 16; o2 > 0; o2 >>= 1) s += __shfl_xor_sync(0xffffffffu, s, o2);
    float mean = s * (1.f/256.f);

    float q = 0.f;
    #pragma unroll
    for (int i = 0; i < 8; i++) { float d = a[i] - mean; q += d*d; }
    #pragma unroll
    for (int o2 = 16; o2 > 0; o2 >>= 1) q += __shfl_xor_sync(0xffffffffu, q, o2);
    float rstd = rsqrtf(q * (1.f/256.f) + 1e-5f);

    float4 g0 = *reinterpret_cast<const float4*>(g + lid*4);
    float4 b0 = *reinterpret_cast<const float4*>(b + lid*4);
    float4 g1 = *reinterpret_cast<const float4*>(g + 128 + lid*4);
    float4 b1 = *reinterpret_cast<const float4*>(b + 128 + lid*4);
    float4 r0, r1;
    r0.x = (a[0]-mean)*rstd*g0.x + b0.x; r0.y = (a[1]-mean)*rstd*g0.y + b0.y;
    r0.z = (a[2]-mean)*rstd*g0.z + b0.z; r0.w = (a[3]-mean)*rstd*g0.w + b0.w;
    r1.x = (a[4]-mean)*rstd*g1.x + b1.x; r1.y = (a[5]-mean)*rstd*g1.y + b1.y;
    r1.z = (a[6]-mean)*rstd*g1.z + b1.z; r1.w = (a[7]-mean)*rstd*g1.w + b1.w;
    *reinterpret_cast<float4*>(out + (size_t)row*256 + lid*4)       = r0;
    *reinterpret_cast<float4*>(out + (size_t)row*256 + 128 + lid*4) = r1;
}

// final layer: h_combined = LN(x+y) + h0, write fp32 tail + fp16 copy
__global__ __launch_bounds__(256) void add_ln_hc_kernel(
    const float* __restrict__ x, const float* __restrict__ y,
    const float* __restrict__ g, const float* __restrict__ b,
    const float* __restrict__ h0,
    float* __restrict__ out_tail, __half* __restrict__ hch)
{
    int row = blockIdx.x * 8 + (threadIdx.x >> 5);
    int lid = threadIdx.x & 31;
    const float* xr = x + (size_t)row * 256;
    const float* yr = y + (size_t)row * 256;
    const float* hr = h0 + (size_t)row * 256;

    float4 v0 = *reinterpret_cast<const float4*>(xr + lid*4);
    float4 w0 = *reinterpret_cast<const float4*>(yr + lid*4);
    float4 v1 = *reinterpret_cast<const float4*>(xr + 128 + lid*4);
    float4 w1 = *reinterpret_cast<const float4*>(yr + 128 + lid*4);
    float a[8] = { v0.x+w0.x, v0.y+w0.y, v0.z+w0.z, v0.w+w0.w,
                   v1.x+w1.x, v1.y+w1.y, v1.z+w1.z, v1.w+w1.w };

    float s = 0.f;
    #pragma unroll
    for (int i = 0; i < 8; i++) s += a[i];
    #pragma unroll
    for (int o2 = 16; o2 > 0; o2 >>= 1) s += __shfl_xor_sync(0xffffffffu, s, o2);
    float mean = s * (1.f/256.f);

    float q = 0.f;
    #pragma unroll
    for (int i = 0; i < 8; i++) { float d = a[i] - mean; q += d*d; }
    #pragma unroll
    for (int o2 = 16; o2 > 0; o2 >>= 1) q += __shfl_xor_sync(0xffffffffu, q, o2);
    float rstd = rsqrtf(q * (1.f/256.f) + 1e-5f);

    float4 g0 = *reinterpret_cast<const float4*>(g + lid*4);
    float4 b0 = *reinterpret_cast<const float4*>(b + lid*4);
    float4 g1 = *reinterpret_cast<const float4*>(g + 128 + lid*4);
    float4 b1 = *reinterpret_cast<const float4*>(b + 128 + lid*4);
    float4 h00 = *reinterpret_cast<const float4*>(hr + lid*4);
    float4 h01 = *reinterpret_cast<const float4*>(hr + 128 + lid*4);

    float4 c0, c1;
    c0.x = (a[0]-mean)*rstd*g0.x + b0.x + h00.x;
    c0.y = (a[1]-mean)*rstd*g0.y + b0.y + h00.y;
    c0.z = (a[2]-mean)*rstd*g0.z + b0.z + h00.z;
    c0.w = (a[3]-mean)*rstd*g0.w + b0.w + h00.w;
    c1.x = (a[4]-mean)*rstd*g1.x + b1.x + h01.x;
    c1.y = (a[5]-mean)*rstd*g1.y + b1.y + h01.y;
    c1.z = (a[6]-mean)*rstd*g1.z + b1.z + h01.z;
    c1.w = (a[7]-mean)*rstd*g1.w + b1.w + h01.w;

    *reinterpret_cast<float4*>(out_tail + (size_t)row*256 + lid*4)       = c0;
    *reinterpret_cast<float4*>(out_tail + (size_t)row*256 + 128 + lid*4) = c1;

    uint2 u0, u1;
    u0.x = pack_h2(c0.x, c0.y); u0.y = pack_h2(c0.z, c0.w);
    u1.x = pack_h2(c1.x, c1.y); u1.y = pack_h2(c1.z, c1.w);
    *reinterpret_cast<uint2*>(hch + (size_t)row*256 + lid*4)       = u0;
    *reinterpret_cast<uint2*>(hch + (size_t)row*256 + 128 + lid*4) = u1;
}

// ---------------- fused edge predictor: persistent Wp1, ldmatrix, 8 units/block ----------------
__global__ __launch_bounds__(256) void edge_tc_kernel(
    const __half* __restrict__ hch,
    const int* __restrict__ psrc, const int* __restrict__ pdst, const float* __restrict__ pw,
    const int* __restrict__ nsrc, const int* __restrict__ ndst, const float* __restrict__ nw,
    const __half* __restrict__ wp1t, const float* __restrict__ bp1,
    const float* __restrict__ Wp2, const float* __restrict__ bp2,
    float* __restrict__ out, int E, int nblk)
{
    extern __shared__ __align__(16) char smraw[];
    __half* Bs_ = (__half*)smraw;                        // [128][264]
    __half* As_ = (__half*)(smraw + 128*EDGE_BS_H*2);    // [2][128][40]
    __shared__ int      sSrc[128], sDst[128];
    __shared__ uint32_t sWh[128];
    __shared__ float    sWp2[128], sBp1[128];
    __shared__ float    sred[128][2];

    const int tid  = threadIdx.x;
    const int lane = tid & 31;
    const int wid  = tid >> 5;
    const int wm   = wid >> 1;
    const int wn   = wid & 1;
    const int grp  = lane >> 2;
    const int tig  = lane & 3;

    const uint32_t bs_u32 = smem_u32(Bs_);
    const uint32_t as_u32 = smem_u32(As_);

    // ldmatrix offsets
    const int a_row = lane & 15;
    const int a_kh  = (lane >> 4) & 1;
    const int b_n   = (lane & 7) + ((lane >> 4) << 3);
    const int b_kh  = (lane >> 3) & 1;
    uint32_t aAddr[2], bAddr[4];
    #pragma unroll
    for (int mt = 0; mt < 2; mt++)
        aAddr[mt] = as_u32 + (uint32_t)((wm*32 + mt*16 + a_row) * 40) * 2 + a_kh * 16;
    #pragma unroll
    for (int pr = 0; pr < 4; pr++)
        bAddr[pr] = bs_u32 + (uint32_t)((wn*64 + pr*16 + b_n) * EDGE_BS_H) * 2 + b_kh * 16;

    // load full Wp1 [128][256] once
    #pragma unroll
    for (int i = 0; i < 16; i++) {
        int cid = tid + i * 256;
        int j = cid >> 5, c = cid & 31;
        cp_async16(bs_u32 + (uint32_t)(j * EDGE_BS_H + c * 8) * 2,
                   wp1t + (size_t)j * 256 + c * 8);
    }
    cp_commit();
    if (tid < 128) { sWp2[tid] = Wp2[tid]; sBp1[tid] = bp1[tid]; }
    cp_wait0();
    __syncthreads();

    const float bp2v = bp2[0];
    uint4 gs[2], gd[2];

    auto ldA = [&](int kt) {
        #pragma unroll
        for (int i = 0; i < 2; i++) {
            int f = tid + i * 256, e = f >> 2, q = f & 3;
            gs[i] = *reinterpret_cast<const uint4*>(hch + (size_t)sSrc[e]*256 + kt*32 + q*8);
            gd[i] = *reinterpret_cast<const uint4*>(hch + (size_t)sDst[e]*256 + kt*32 + q*8);
        }
    };
    auto stA = [&](int bb) {
        #pragma unroll
        for (int i = 0; i < 2; i++) {
            int f = tid + i * 256, e = f >> 2, q = f & 3;
            __half2 w2 = *reinterpret_cast<const __half2*>(&sWh[e]);
            const __half2* sp = reinterpret_cast<const __half2*>(&gs[i]);
            const __half2* dp = reinterpret_cast<const __half2*>(&gd[i]);
            uint4 r;
            __half2* rp = reinterpret_cast<__half2*>(&r);
            rp[0] = __hmul2(__hmul2(sp[0], dp[0]), w2);
            rp[1] = __hmul2(__hmul2(sp[1], dp[1]), w2);
            rp[2] = __hmul2(__hmul2(sp[2], dp[2]), w2);
            rp[3] = __hmul2(__hmul2(sp[3], dp[3]), w2);
            *reinterpret_cast<uint4*>(&As_[bb*(128*40) + e*40 + q*8]) = r;
        }
    };

    for (int uu = 0; uu < EDGE_NU; uu++) {
        int u = blockIdx.x * EDGE_NU + uu;
        if (u >= 2 * nblk) break;
        const int pol = (u >= nblk) ? 1 : 0;
        const int blk = u - pol * nblk;
        const int e0  = blk * 128;
        const int* srcA = pol ? nsrc : psrc;
        const int* dstA = pol ? ndst : pdst;
        const float* wA = pol ? nw   : pw;
        float* op = out + (pol ? (size_t)E : 0);

        if (tid < 128) {
            int e = e0 + tid;
            float wv = (e < E) ? wA[e] : 0.f;
            if (e < E) { sSrc[tid] = srcA[e]; sDst[tid] = dstA[e]; }
            else       { sSrc[tid] = 0;       sDst[tid] = 0; }
            sWh[tid] = pack_h2(wv, wv);
        }
        __syncthreads();

        float acc[2][8][4] = {};

        ldA(0);
        stA(0);
        __syncthreads();

        for (int t = 0; t < 8; t++) {
            int cur = t & 1;
            uint32_t curA = cur * (128*40*2);
            if (t < 7) ldA(t + 1);
            #pragma unroll
            for (int ks = 0; ks < 2; ks++) {
                uint32_t kb = t*64 + ks*32;   // byte offset into persistent B k-dim
                uint32_t a[2][4];
                ldsm_x4(a[0], aAddr[0] + curA + ks*32);
                ldsm_x4(a[1], aAddr[1] + curA + ks*32);
                #pragma unroll
                for (int pr = 0; pr < 4; pr++) {
                    uint32_t b[4];
                    ldsm_x4(b, bAddr[pr] + kb);
                    #pragma unroll
                    for (int mt = 0; mt < 2; mt++) {
                        mma_f16(acc[mt][pr*2    ], a[mt], b);
                        mma_f16(acc[mt][pr*2 + 1], a[mt], b + 2);
                    }
                }
            }
            if (t < 7) stA((t + 1) & 1);
            __syncthreads();
        }

        // epilogue: leaky(acc + bp1) . Wp2
        #pragma unroll
        for (int mt = 0; mt < 2; mt++) {
            float p0 = 0.f, p1 = 0.f;
            #pragma unroll
            for (int nt = 0; nt < 8; nt++) {
                int col = wn * 64 + nt * 8 + tig * 2;
                float bb0 = sBp1[col], bb1 = sBp1[col+1];
                float w0  = sWp2[col], w1  = sWp2[col+1];
                float y;
                y = acc[mt][nt][0] + bb0; y = (y > 0.f) ? y : 0.2f*y; p0 += y * w0;
                y = acc[mt][nt][1] + bb1; y = (y > 0.f) ? y : 0.2f*y; p0 += y * w1;
                y = acc[mt][nt][2] + bb0; y = (y > 0.f) ? y : 0.2f*y; p1 += y * w0;
                y = acc[mt][nt][3] + bb1; y = (y > 0.f) ? y : 0.2f*y; p1 += y * w1;
            }
            p0 += __shfl_xor_sync(0xffffffffu, p0, 1);
            p0 += __shfl_xor_sync(0xffffffffu, p0, 2);
            p1 += __shfl_xor_sync(0xffffffffu, p1, 1);
            p1 += __shfl_xor_sync(0xffffffffu, p1, 2);
            if (tig == 0) {
                int r0 = wm * 32 + mt * 16 + grp;
                sred[r0    ][wn] = p0;
                sred[r0 + 8][wn] = p1;
            }
        }
        __syncthreads();

        if (tid < 128) {
            int e = e0 + tid;
            if (e < E) op[e] = sred[tid][0] + sred[tid][1] + bp2v;
        }
        __syncthreads();
    }
}

// ---------------- host orchestration ----------------
extern "C" void kernel_launch(void* const* d_in, const int* in_sizes, int n_in,
                              void* d_out, int out_size)
{
    const float* x        = (const float*)d_in[0];
    const int*   pos_src  = (const int*)  d_in[1];
    const int*   pos_dst  = (const int*)  d_in[2];
    const float* pos_w    = (const float*)d_in[3];
    const int*   neg_src  = (const int*)  d_in[4];
    const int*   neg_dst  = (const int*)  d_in[5];
    const float* neg_w    = (const float*)d_in[6];
    const float* Wi       = (const float*)d_in[7];
    const float* bi       = (const float*)d_in[8];
    const float* Wqkv     = (const float*)d_in[9];
    const float* bqkv     = (const float*)d_in[10];
    const float* Wo       = (const float*)d_in[11];
    const float* bo       = (const float*)d_in[12];
    const float* g1       = (const float*)d_in[13];
    const float* be1      = (const float*)d_in[14];
    const float* g2       = (const float*)d_in[15];
    const float* be2      = (const float*)d_in[16];
    const float* W1       = (const float*)d_in[17];
    const float* b1       = (const float*)d_in[18];
    const float* W2       = (const float*)d_in[19];
    const float* b2       = (const float*)d_in[20];
    const float* Wp1      = (const float*)d_in[21];
    const float* bp1      = (const float*)d_in[22];
    const float* Wp2      = (const float*)d_in[23];
    const float* bp2      = (const float*)d_in[24];

    const int E = in_sizes[1];   // 500000

    cudaFuncSetAttribute(sgemm_tc_kernel, cudaFuncAttributeMaxDynamicSharedMemorySize, SGEMM_SMEM);
    cudaFuncSetAttribute(attn_tc_kernel,  cudaFuncAttributeMaxDynamicSharedMemorySize, ATTN_SMEM);
    cudaFuncSetAttribute(edge_tc_kernel,  cudaFuncAttributeMaxDynamicSharedMemorySize, EDGE_SMEM);

    float* S = nullptr;
    cudaGetSymbolAddress((void**)&S, g_scratch);
    float* h0    = S + OFF_H0;
    float* h     = S + OFF_H;
    float* qkv   = S + OFF_QKV;
    float* attn  = S + OFF_ATTN;
    float* tmp   = S + OFF_TMP;
    float* ff    = S + OFF_FF;
    __half* wp1t = (__half*)(S + OFF_WP1T);
    __half* kh   = (__half*)(S + OFF_KH);
    __half* vth  = (__half*)(S + OFF_VTH);
    __half* hch  = (__half*)(S + OFF_HCH);
    float* out   = (float*)d_out;

    wp1_prep_kernel<<<128, 256>>>(Wp1, wp1t);

    sgemm_tc_kernel<<<dim3(DD/64, NN/128), 256, SGEMM_SMEM>>>(NN, DD, INF_, x, Wi, bi, h0, 0);

    for (int l = 0; l < LL; l++) {
        const float* hin = (l == 0) ? h0 : h;
        sgemm_tc_kernel<<<dim3(768/64, NN/128), 256, SGEMM_SMEM>>>(NN, 768, DD,
            hin, Wqkv + (size_t)l*DD*768, bqkv + (size_t)l*768, qkv, 0);
        kvprep_kernel<<<2048, 256>>>(qkv, kh, vth);
        attn_tc_kernel<<<dim3(NN/128, HH), 256, ATTN_SMEM>>>(qkv, kh, vth, attn);
        sgemm_tc_kernel<<<dim3(DD/64, NN/128), 256, SGEMM_SMEM>>>(NN, DD, DD,
            attn, Wo + (size_t)l*DD*DD, bo + (size_t)l*DD, tmp, 0);
        add_ln_kernel<<<NN/8, 256>>>(hin, tmp, g1 + (size_t)l*DD, be1 + (size_t)l*DD, h);
        sgemm_tc_kernel<<<dim3(FF_/64, NN/128), 256, SGEMM_SMEM>>>(NN, FF_, DD,
            h, W1 + (size_t)l*DD*FF_, b1 + (size_t)l*FF_, ff, 1);
        sgemm_tc_kernel<<<dim3(DD/64, NN/128), 256, SGEMM_SMEM>>>(NN, DD, FF_,
            ff, W2 + (size_t)l*FF_*DD, b2 + (size_t)l*DD, tmp, 0);
        if (l == LL - 1) {
            add_ln_hc_kernel<<<NN/8, 256>>>(h, tmp, g2 + (size_t)l*DD, be2 + (size_t)l*DD,
                                            h0, out + 2*(size_t)E, hch);
        } else {
            add_ln_kernel<<<NN/8, 256>>>(h, tmp, g2 + (size_t)l*DD, be2 + (size_t)l*DD, h);
        }
    }

    const int nblk = (E + 127) / 128;
    const int units = 2 * nblk;
    const int egrid = (units + EDGE_NU - 1) / EDGE_NU;
    edge_tc_kernel<<<egrid, 256, EDGE_SMEM>>>(
        hch, pos_src, pos_dst, pos_w, neg_src, neg_dst, neg_w,
        wp1t, bp1, Wp2, bp2, out, E, nblk);
}

// round 13
// speedup vs baseline: 6.2001x; 1.0395x over previous
#include <cuda_runtime.h>
#include <cuda_fp16.h>
#include <math.h>
#include <stdint.h>

// ---------------- problem constants ----------------
#define NN   4096
#define INF_ 512
#define DD   256
#define LL   2
#define HH   8
#define DH   32
#define FF_  1024
#define HALF_ 128

// ---------------- scratch (device global, no allocs) ----------------
#define OFF_H0    0
#define OFF_H     (OFF_H0 + NN*DD)
#define OFF_QKV   (OFF_H  + NN*DD)
#define OFF_ATTN  (OFF_QKV + NN*3*DD)
#define OFF_TMP   (OFF_ATTN + NN*DD)
#define OFF_FF    (OFF_TMP + NN*DD)
#define OFF_WP1T  (OFF_FF + NN*FF_)
#define OFF_KH    (OFF_WP1T + 16384)
#define OFF_VTH   (OFF_KH + 524288)
#define OFF_HCH   (OFF_VTH + 524288)
#define SCRATCH_FLOATS (OFF_HCH + 524288)

__device__ float g_scratch[SCRATCH_FLOATS];

// dynamic smem sizes (bytes)
#define SGEMM_SMEM ((2*128*40 + 2*64*40) * 2)
#define ATTN_SMEM  ((2*64*40 + 2*32*72) * 2)
#define EDGE_BS_H  264
#define EDGE_SMEM  (128*EDGE_BS_H*2 + 2*128*40*2)
#define EDGE_NU    8

// ---------------- fp16 MMA helpers ----------------
__device__ __forceinline__ uint32_t pack_h2(float lo, float hi) {
    __half2 h = __floats2half2_rn(lo, hi);
    return *reinterpret_cast<uint32_t*>(&h);
}

__device__ __forceinline__ void mma_f16(float* d, const uint32_t* a, const uint32_t* b) {
    asm("mma.sync.aligned.m16n8k16.row.col.f32.f16.f16.f32 "
        "{%0,%1,%2,%3},{%4,%5,%6,%7},{%8,%9},{%0,%1,%2,%3};"
        : "+f"(d[0]), "+f"(d[1]), "+f"(d[2]), "+f"(d[3])
        : "r"(a[0]), "r"(a[1]), "r"(a[2]), "r"(a[3]), "r"(b[0]), "r"(b[1]));
}

__device__ __forceinline__ void ldsm_x4(uint32_t* r, uint32_t addr) {
    asm volatile("ldmatrix.sync.aligned.m8n8.x4.shared.b16 {%0,%1,%2,%3}, [%4];"
        : "=r"(r[0]), "=r"(r[1]), "=r"(r[2]), "=r"(r[3]) : "r"(addr));
}

__device__ __forceinline__ uint32_t smem_u32(const void* p) {
    uint32_t a;
    asm("{ .reg .u64 t; cvta.to.shared.u64 t, %1; cvt.u32.u64 %0, t; }" : "=r"(a) : "l"(p));
    return a;
}
__device__ __forceinline__ void cp_async16(uint32_t dst, const void* src) {
    asm volatile("cp.async.ca.shared.global [%0], [%1], 16;" :: "r"(dst), "l"(src));
}
__device__ __forceinline__ void cp_commit() {
    asm volatile("cp.async.commit_group;" ::: "memory");
}
__device__ __forceinline__ void cp_wait0() {
    asm volatile("cp.async.wait_group 0;" ::: "memory");
}
__device__ __forceinline__ void bar_pair(int id) {
    asm volatile("bar.sync %0, 64;" :: "r"(id) : "memory");
}

// ---------------- Wp1 prepass: half, transposed [j][k] ----------------
__global__ __launch_bounds__(256) void wp1_prep_kernel(
    const float* __restrict__ Wp1, __half* __restrict__ wp1t)
{
    int idx = blockIdx.x * 256 + threadIdx.x;
    int k = idx >> 7, j = idx & 127;
    wp1t[j * 256 + k] = __float2half_rn(Wp1[idx]);
}

// ---------------- per-layer KV prepass ----------------
__global__ __launch_bounds__(256) void kvprep_kernel(
    const float* __restrict__ qkv, __half* __restrict__ kh, __half* __restrict__ vth)
{
    int gid = blockIdx.x * 256 + threadIdx.x;
    if (gid < 262144) {
        int idx = gid * 4;
        int h   = idx >> 17;
        int rem = idx & 131071;
        int kv  = rem >> 5;
        int d   = rem & 31;
        float4 v = *reinterpret_cast<const float4*>(qkv + (size_t)kv*768 + 256 + h*32 + d);
        __half2* o = reinterpret_cast<__half2*>(kh + idx);
        o[0] = __floats2half2_rn(v.x, v.y);
        o[1] = __floats2half2_rn(v.z, v.w);
    } else {
        int idx = (gid - 262144) * 4;
        int h   = idx >> 17;
        int rem = idx & 131071;
        int d   = rem >> 12;
        int kv  = rem & 4095;
        const float* src = qkv + 512 + h*32 + d;
        __half2* o = reinterpret_cast<__half2*>(vth + idx);
        o[0] = __floats2half2_rn(src[(size_t)kv*768],     src[(size_t)(kv+1)*768]);
        o[1] = __floats2half2_rn(src[(size_t)(kv+2)*768], src[(size_t)(kv+3)*768]);
    }
}

// ---------------- fp16 tensor-core SGEMM, ping-pong + ldmatrix ----------------
__global__ __launch_bounds__(256) void sgemm_tc_kernel(
    int M, int N, int K,
    const float* __restrict__ A, const float* __restrict__ B,
    const float* __restrict__ bias, float* __restrict__ C, int act)
{
    extern __shared__ __align__(16) char smraw[];
    __half* As_ = (__half*)smraw;                   // [2][128][40]
    __half* Bs_ = (__half*)(smraw + 2*128*40*2);    // [2][64][40]

    const int tid  = threadIdx.x;
    const int lane = tid & 31;
    const int wid  = tid >> 5;
    const int wm   = wid >> 1;
    const int wn   = wid & 1;
    const int grp  = lane >> 2;
    const int tig  = lane & 3;

    const int bx = blockIdx.x, by = blockIdx.y;
    A += (size_t)by * 128 * K;
    B += (size_t)bx * 64;
    C += (size_t)by * 128 * N + (size_t)bx * 64;
    bias += (size_t)bx * 64;

    const uint32_t as_b = smem_u32(As_);
    const uint32_t bs_b = smem_u32(Bs_);
    const int a_row = lane & 15;
    const int a_kh  = (lane >> 4) & 1;
    const int b_n   = (lane & 7) + ((lane >> 4) << 3);
    const int b_kh  = (lane >> 3) & 1;
    uint32_t aAddr[2], bAddr[2];
    #pragma unroll
    for (int mt = 0; mt < 2; mt++)
        aAddr[mt] = as_b + (uint32_t)((wm*32 + mt*16 + a_row) * 40) * 2 + a_kh * 16;
    #pragma unroll
    for (int pr = 0; pr < 2; pr++)
        bAddr[pr] = bs_b + (uint32_t)((wn*32 + pr*16 + b_n) * 40) * 2 + b_kh * 16;

    float acc[2][4][4] = {};
    float4 rA[4], rB[2];

    auto ldT = [&](int kt) {
        #pragma unroll
        for (int i = 0; i < 4; i++) {
            int f = tid + i * 256, r = f >> 3, c4 = f & 7;
            rA[i] = *reinterpret_cast<const float4*>(A + (size_t)r * K + kt + c4 * 4);
        }
        #pragma unroll
        for (int i = 0; i < 2; i++) {
            int f = tid + i * 256, r = f >> 4, c4 = f & 15;
            rB[i] = *reinterpret_cast<const float4*>(B + (size_t)(kt + r) * N + c4 * 4);
        }
    };
    auto stT = [&](int bb) {
        #pragma unroll
        for (int i = 0; i < 4; i++) {
            int f = tid + i * 256, r = f >> 3, c4 = f & 7;
            uint2 u;
            u.x = pack_h2(rA[i].x, rA[i].y);
            u.y = pack_h2(rA[i].z, rA[i].w);
            *reinterpret_cast<uint2*>(&As_[bb*(128*40) + r*40 + c4*4]) = u;
        }
        #pragma unroll
        for (int i = 0; i < 2; i++) {
            int f = tid + i * 256, r = f >> 4, c4 = f & 15;
            __half* bp = &Bs_[bb*(64*40)];
            bp[(c4*4+0)*40 + r] = __float2half_rn(rB[i].x);
            bp[(c4*4+1)*40 + r] = __float2half_rn(rB[i].y);
            bp[(c4*4+2)*40 + r] = __float2half_rn(rB[i].z);
            bp[(c4*4+3)*40 + r] = __float2half_rn(rB[i].w);
        }
    };

    const int T = K / 32;
    ldT(0); stT(0); __syncthreads();

    for (int t = 0; t < T; t++) {
        int cur = t & 1;
        uint32_t curA = cur * (128*40*2);
        uint32_t curB = cur * (64*40*2);
        if (t + 1 < T) ldT((t + 1) * 32);
        #pragma unroll
        for (int ks = 0; ks < 2; ks++) {
            uint32_t a[2][4], b[2][4];
            ldsm_x4(a[0], aAddr[0] + curA + ks*32);
            ldsm_x4(a[1], aAddr[1] + curA + ks*32);
            ldsm_x4(b[0], bAddr[0] + curB + ks*32);
            ldsm_x4(b[1], bAddr[1] + curB + ks*32);
            #pragma unroll
            for (int mt = 0; mt < 2; mt++) {
                mma_f16(acc[mt][0], a[mt], b[0]);
                mma_f16(acc[mt][1], a[mt], b[0] + 2);
                mma_f16(acc[mt][2], a[mt], b[1]);
                mma_f16(acc[mt][3], a[mt], b[1] + 2);
            }
        }
        if (t + 1 < T) stT((t + 1) & 1);
        __syncthreads();
    }

    #pragma unroll
    for (int mt = 0; mt < 2; mt++) {
        #pragma unroll
        for (int nt = 0; nt < 4; nt++) {
            int row = wm * 32 + mt * 16 + grp;
            int col = wn * 32 + nt * 8 + tig * 2;
            float b0 = bias[col], b1 = bias[col+1];
            float2 v0, v1;
            v0.x = acc[mt][nt][0] + b0; v0.y = acc[mt][nt][1] + b1;
            v1.x = acc[mt][nt][2] + b0; v1.y = acc[mt][nt][3] + b1;
            if (act == 1) {
                v0.x = fmaxf(v0.x, 0.f); v0.y = fmaxf(v0.y, 0.f);
                v1.x = fmaxf(v1.x, 0.f); v1.y = fmaxf(v1.y, 0.f);
            }
            *reinterpret_cast<float2*>(C + (size_t)row * N + col)     = v0;
            *reinterpret_cast<float2*>(C + (size_t)(row+8) * N + col) = v1;
        }
    }
}

// ---------------- fp16 MMA flash attention, ldmatrix + exp2 ----------------
__global__ __launch_bounds__(256) void attn_tc_kernel(
    const float* __restrict__ qkv,
    const __half* __restrict__ kh, const __half* __restrict__ vth,
    float* __restrict__ out)
{
    extern __shared__ __align__(16) char smraw[];
    __half* Ks_ = (__half*)smraw;                    // [2][64][40]
    __half* Vs_ = (__half*)(smraw + 2*64*40*2);      // [2][32][72]

    const int h  = blockIdx.y;
    const int qb = blockIdx.x * 128;
    const int tid  = threadIdx.x;
    const int lane = tid & 31;
    const int wid  = tid >> 5;
    const int grp  = lane >> 2;
    const int tig  = lane & 3;
    const float scale = 0.17677669529663687f * 1.4426950408889634f;

    const uint32_t ks_u32 = smem_u32(Ks_);
    const uint32_t vs_u32 = smem_u32(Vs_);
    const __half* khh = kh  + (size_t)h * 131072;
    const __half* vhh = vth + (size_t)h * 131072;

    const int b_n  = (lane & 7) + ((lane >> 4) << 3);
    const int b_kh = (lane >> 3) & 1;
    uint32_t kAddr[4], vAddr[2];
    #pragma unroll
    for (int pr = 0; pr < 4; pr++)
        kAddr[pr] = ks_u32 + (uint32_t)((pr*16 + b_n) * 40) * 2 + b_kh * 16;
    #pragma unroll
    for (int pr = 0; pr < 2; pr++)
        vAddr[pr] = vs_u32 + (uint32_t)((pr*16 + b_n) * 72) * 2 + b_kh * 16;

    uint32_t qa[2][4];
    {
        const float* q0 = qkv + (size_t)(qb + wid*16 + grp) * 768 + h * 32;
        const float* q1 = q0 + (size_t)8 * 768;
        #pragma unroll
        for (int ks = 0; ks < 2; ks++) {
            int b = ks * 16 + 2 * tig;
            qa[ks][0] = pack_h2(q0[b]   * scale, q0[b+1] * scale);
            qa[ks][1] = pack_h2(q1[b]   * scale, q1[b+1] * scale);
            qa[ks][2] = pack_h2(q0[b+8] * scale, q0[b+9] * scale);
            qa[ks][3] = pack_h2(q1[b+8] * scale, q1[b+9] * scale);
        }
    }

    float m0 = -1e30f, m1 = -1e30f, l0 = 0.f, l1 = 0.f;
    float o[4][4] = {};

    auto cpKV = [&](int bb, int kb) {
        int r = tid >> 2, c = tid & 3;
        cp_async16(ks_u32 + (uint32_t)(bb*(64*40) + r*40 + c*8) * 2,
                   khh + (size_t)(kb + r) * 32 + c * 8);
        int r2 = tid >> 3, c2 = tid & 7;
        cp_async16(vs_u32 + (uint32_t)(bb*(32*72) + r2*72 + c2*8) * 2,
                   vhh + (size_t)r2 * 4096 + kb + c2 * 8);
        cp_commit();
    };

    cpKV(0, 0);
    cp_wait0();
    __syncthreads();

    for (int t = 0; t < NN/64; t++) {
        int cur = t & 1;
        uint32_t curK = cur * (64*40*2);
        uint32_t curV = cur * (32*72*2);
        if (t < NN/64 - 1) cpKV(cur ^ 1, (t + 1) * 64);

        float sacc[8][4] = {};
        #pragma unroll
        for (int ks = 0; ks < 2; ks++) {
            #pragma unroll
            for (int pr = 0; pr < 4; pr++) {
                uint32_t b[4];
                ldsm_x4(b, kAddr[pr] + curK + ks*32);
                mma_f16(sacc[pr*2    ], qa[ks], b);
                mma_f16(sacc[pr*2 + 1], qa[ks], b + 2);
            }
        }

        float rmax0 = -1e30f, rmax1 = -1e30f;
        #pragma unroll
        for (int nt = 0; nt < 8; nt++) {
            rmax0 = fmaxf(rmax0, fmaxf(sacc[nt][0], sacc[nt][1]));
            rmax1 = fmaxf(rmax1, fmaxf(sacc[nt][2], sacc[nt][3]));
        }
        rmax0 = fmaxf(rmax0, __shfl_xor_sync(0xffffffffu, rmax0, 1));
        rmax0 = fmaxf(rmax0, __shfl_xor_sync(0xffffffffu, rmax0, 2));
        rmax1 = fmaxf(rmax1, __shfl_xor_sync(0xffffffffu, rmax1, 1));
        rmax1 = fmaxf(rmax1, __shfl_xor_sync(0xffffffffu, rmax1, 2));
        float mn0 = fmaxf(m0, rmax0), mn1 = fmaxf(m1, rmax1);
        float a0 = exp2f(m0 - mn0), a1 = exp2f(m1 - mn1);
        float ps0 = 0.f, ps1 = 0.f;
        uint32_t pa[4][4];
        #pragma unroll
        for (int nt = 0; nt < 8; nt++) {
            float p00 = exp2f(sacc[nt][0] - mn0);
            float p01 = exp2f(sacc[nt][1] - mn0);
            float p10 = exp2f(sacc[nt][2] - mn1);
            float p11 = exp2f(sacc[nt][3] - mn1);
            ps0 += p00 + p01; ps1 += p10 + p11;
            int ks2 = nt >> 1, hf = (nt & 1) * 2;
            pa[ks2][hf + 0] = pack_h2(p00, p01);
            pa[ks2][hf + 1] = pack_h2(p10, p11);
        }
        ps0 += __shfl_xor_sync(0xffffffffu, ps0, 1);
        ps0 += __shfl_xor_sync(0xffffffffu, ps0, 2);
        ps1 += __shfl_xor_sync(0xffffffffu, ps1, 1);
        ps1 += __shfl_xor_sync(0xffffffffu, ps1, 2);
        l0 = l0 * a0 + ps0; l1 = l1 * a1 + ps1;
        m0 = mn0; m1 = mn1;
        #pragma unroll
        for (int nt = 0; nt < 4; nt++) {
            o[nt][0] *= a0; o[nt][1] *= a0;
            o[nt][2] *= a1; o[nt][3] *= a1;
        }

        #pragma unroll
        for (int ks = 0; ks < 4; ks++) {
            #pragma unroll
            for (int pr = 0; pr < 2; pr++) {
                uint32_t b[4];
                ldsm_x4(b, vAddr[pr] + curV + ks*32);
                mma_f16(o[pr*2    ], pa[ks], b);
                mma_f16(o[pr*2 + 1], pa[ks], b + 2);
            }
        }

        if (t < NN/64 - 1) cp_wait0();
        __syncthreads();
    }

    float inv0 = 1.f / l0, inv1 = 1.f / l1;
    int r0 = qb + wid*16 + grp;
    #pragma unroll
    for (int nt = 0; nt < 4; nt++) {
        int col = h * 32 + nt * 8 + tig * 2;
        *reinterpret_cast<float2*>(out + (size_t)r0 * 256 + col) =
            make_float2(o[nt][0] * inv0, o[nt][1] * inv0);
        *reinterpret_cast<float2*>(out + (size_t)(r0 + 8) * 256 + col) =
            make_float2(o[nt][2] * inv1, o[nt][3] * inv1);
    }
}

// ---------------- fused residual-add + LayerNorm (warp per row) ----------------
__global__ __launch_bounds__(256) void add_ln_kernel(
    const float* __restrict__ x, const float* __restrict__ y,
    const float* __restrict__ g, const float* __restrict__ b,
    float* __restrict__ out)
{
    int row = blockIdx.x * 8 + (threadIdx.x >> 5);
    int lid = threadIdx.x & 31;
    const float* xr = x + (size_t)row * 256;
    const float* yr = y + (size_t)row * 256;

    float4 v0 = *reinterpret_cast<const float4*>(xr + lid*4);
    float4 w0 = *reinterpret_cast<const float4*>(yr + lid*4);
    float4 v1 = *reinterpret_cast<const float4*>(xr + 128 + lid*4);
    float4 w1 = *reinterpret_cast<const float4*>(yr + 128 + lid*4);
    float a[8] = { v0.x+w0.x, v0.y+w0.y, v0.z+w0.z, v0.w+w0.w,
                   v1.x+w1.x, v1.y+w1.y, v1.z+w1.z, v1.w+w1.w };

    float s = 0.f;
    #pragma unroll
    for (int i = 0; i < 8; i++) s += a[i];
    #pragma unroll
    for (int o2 = 16; o2 > 0; o2 >>= 1) s += __shfl_xor_sync(0xffffffffu, s, o2);
    float mean = s * (1.f/256.f);

    float q = 0.f;
    #pragma unroll
    for (int i = 0; i < 8; i++) { float d = a[i] - mean; q += d*d; }
    #pragma unroll
    for (int o2 = 16; o2 > 0; o2 >>= 1) q += __shfl_xor_sync(0xffffffffu, q, o2);
    float rstd = rsqrtf(q * (1.f/256.f) + 1e-5f);

    float4 g0 = *reinterpret_cast<const float4*>(g + lid*4);
    float4 b0 = *reinterpret_cast<const float4*>(b + lid*4);
    float4 g1 = *reinterpret_cast<const float4*>(g + 128 + lid*4);
    float4 b1 = *reinterpret_cast<const float4*>(b + 128 + lid*4);
    float4 r0, r1;
    r0.x = (a[0]-mean)*rstd*g0.x + b0.x; r0.y = (a[1]-mean)*rstd*g0.y + b0.y;
    r0.z = (a[2]-mean)*rstd*g0.z + b0.z; r0.w = (a[3]-mean)*rstd*g0.w + b0.w;
    r1.x = (a[4]-mean)*rstd*g1.x + b1.x; r1.y = (a[5]-mean)*rstd*g1.y + b1.y;
    r1.z = (a[6]-mean)*rstd*g1.z + b1.z; r1.w = (a[7]-mean)*rstd*g1.w + b1.w;
    *reinterpret_cast<float4*>(out + (size_t)row*256 + lid*4)       = r0;
    *reinterpret_cast<float4*>(out + (size_t)row*256 + 128 + lid*4) = r1;
}

// final layer: h_combined = LN(x+y) + h0, write fp32 tail + fp16 copy
__global__ __launch_bounds__(256) void add_ln_hc_kernel(
    const float* __restrict__ x, const float* __restrict__ y,
    const float* __restrict__ g, const float* __restrict__ b,
    const float* __restrict__ h0,
    float* __restrict__ out_tail, __half* __restrict__ hch)
{
    int row = blockIdx.x * 8 + (threadIdx.x >> 5);
    int lid = threadIdx.x & 31;
    const float* xr = x + (size_t)row * 256;
    const float* yr = y + (size_t)row * 256;
    const float* hr = h0 + (size_t)row * 256;

    float4 v0 = *reinterpret_cast<const float4*>(xr + lid*4);
    float4 w0 = *reinterpret_cast<const float4*>(yr + lid*4);
    float4 v1 = *reinterpret_cast<const float4*>(xr + 128 + lid*4);
    float4 w1 = *reinterpret_cast<const float4*>(yr + 128 + lid*4);
    float a[8] = { v0.x+w0.x, v0.y+w0.y, v0.z+w0.z, v0.w+w0.w,
                   v1.x+w1.x, v1.y+w1.y, v1.z+w1.z, v1.w+w1.w };

    float s = 0.f;
    #pragma unroll
    for (int i = 0; i < 8; i++) s += a[i];
    #pragma unroll
    for (int o2 = 16; o2 > 0; o2 >>= 1) s += __shfl_xor_sync(0xffffffffu, s, o2);
    float mean = s * (1.f/256.f);

    float q = 0.f;
    #pragma unroll
    for (int i = 0; i < 8; i++) { float d = a[i] - mean; q += d*d; }
    #pragma unroll
    for (int o2 = 16; o2 > 0; o2 >>= 1) q += __shfl_xor_sync(0xffffffffu, q, o2);
    float rstd = rsqrtf(q * (1.f/256.f) + 1e-5f);

    float4 g0 = *reinterpret_cast<const float4*>(g + lid*4);
    float4 b0 = *reinterpret_cast<const float4*>(b + lid*4);
    float4 g1 = *reinterpret_cast<const float4*>(g + 128 + lid*4);
    float4 b1 = *reinterpret_cast<const float4*>(b + 128 + lid*4);
    float4 h00 = *reinterpret_cast<const float4*>(hr + lid*4);
    float4 h01 = *reinterpret_cast<const float4*>(hr + 128 + lid*4);

    float4 c0, c1;
    c0.x = (a[0]-mean)*rstd*g0.x + b0.x + h00.x;
    c0.y = (a[1]-mean)*rstd*g0.y + b0.y + h00.y;
    c0.z = (a[2]-mean)*rstd*g0.z + b0.z + h00.z;
    c0.w = (a[3]-mean)*rstd*g0.w + b0.w + h00.w;
    c1.x = (a[4]-mean)*rstd*g1.x + b1.x + h01.x;
    c1.y = (a[5]-mean)*rstd*g1.y + b1.y + h01.y;
    c1.z = (a[6]-mean)*rstd*g1.z + b1.z + h01.z;
    c1.w = (a[7]-mean)*rstd*g1.w + b1.w + h01.w;

    *reinterpret_cast<float4*>(out_tail + (size_t)row*256 + lid*4)       = c0;
    *reinterpret_cast<float4*>(out_tail + (size_t)row*256 + 128 + lid*4) = c1;

    uint2 u0, u1;
    u0.x = pack_h2(c0.x, c0.y); u0.y = pack_h2(c0.z, c0.w);
    u1.x = pack_h2(c1.x, c1.y); u1.y = pack_h2(c1.z, c1.w);
    *reinterpret_cast<uint2*>(hch + (size_t)row*256 + lid*4)       = u0;
    *reinterpret_cast<uint2*>(hch + (size_t)row*256 + 128 + lid*4) = u1;
}

// ---------------- fused edge predictor: pair-local sync, persistent Wp1 ----------------
// 8 warps = 4 independent pairs. Pair pm owns A rows [pm*32, pm*32+32) and the
// corresponding 32 edges/outputs of each unit. All unit-loop syncs are bar.sync(1+pm,64).
__global__ __launch_bounds__(256) void edge_tc_kernel(
    const __half* __restrict__ hch,
    const int* __restrict__ psrc, const int* __restrict__ pdst, const float* __restrict__ pw,
    const int* __restrict__ nsrc, const int* __restrict__ ndst, const float* __restrict__ nw,
    const __half* __restrict__ wp1t, const float* __restrict__ bp1,
    const float* __restrict__ Wp2, const float* __restrict__ bp2,
    float* __restrict__ out, int E, int nblk)
{
    extern __shared__ __align__(16) char smraw[];
    __half* Bs_ = (__half*)smraw;                        // [128][264] persistent
    __half* As_ = (__half*)(smraw + 128*EDGE_BS_H*2);    // [2][128][40]
    __shared__ int      sSrc[128], sDst[128];
    __shared__ uint32_t sWh[128];
    __shared__ float    sWp2[128], sBp1[128];
    __shared__ float    sred[128][2];

    const int tid  = threadIdx.x;
    const int lane = tid & 31;
    const int wid  = tid >> 5;
    const int wm   = wid >> 1;      // pair id pm
    const int wn   = wid & 1;
    const int grp  = lane >> 2;
    const int tig  = lane & 3;
    const int pm   = wm;
    const int bar  = 1 + pm;
    const int ptid = tid & 63;      // thread within pair

    const uint32_t bs_u32 = smem_u32(Bs_);
    const uint32_t as_u32 = smem_u32(As_);

    const int a_row = lane & 15;
    const int a_kh  = (lane >> 4) & 1;
    const int b_n   = (lane & 7) + ((lane >> 4) << 3);
    const int b_kh  = (lane >> 3) & 1;
    uint32_t aAddr[2], bAddr[4];
    #pragma unroll
    for (int mt = 0; mt < 2; mt++)
        aAddr[mt] = as_u32 + (uint32_t)((pm*32 + mt*16 + a_row) * 40) * 2 + a_kh * 16;
    #pragma unroll
    for (int pr = 0; pr < 4; pr++)
        bAddr[pr] = bs_u32 + (uint32_t)((wn*64 + pr*16 + b_n) * EDGE_BS_H) * 2 + b_kh * 16;

    // load full Wp1 once (block-wide) + epilogue params
    #pragma unroll
    for (int i = 0; i < 16; i++) {
        int cid = tid + i * 256;
        int j = cid >> 5, c = cid & 31;
        cp_async16(bs_u32 + (uint32_t)(j * EDGE_BS_H + c * 8) * 2,
                   wp1t + (size_t)j * 256 + c * 8);
    }
    cp_commit();
    if (tid < 128) { sWp2[tid] = Wp2[tid]; sBp1[tid] = bp1[tid]; }
    cp_wait0();
    __syncthreads();

    const float bp2v = bp2[0];
    uint4 gs[2], gd[2];

    // pair-local A tile fill: pair pm covers rows [pm*32, +32), 32 k-halfs per row
    auto ldA = [&](int kt) {
        #pragma unroll
        for (int i = 0; i < 2; i++) {
            int c = ptid + i * 64;              // 0..127 chunk id within pair
            int r = pm*32 + (c >> 2), q = c & 3;
            gs[i] = *reinterpret_cast<const uint4*>(hch + (size_t)sSrc[r]*256 + kt*32 + q*8);
            gd[i] = *reinterpret_cast<const uint4*>(hch + (size_t)sDst[r]*256 + kt*32 + q*8);
        }
    };
    auto stA = [&](int bb) {
        #pragma unroll
        for (int i = 0; i < 2; i++) {
            int c = ptid + i * 64;
            int r = pm*32 + (c >> 2), q = c & 3;
            __half2 w2 = *reinterpret_cast<const __half2*>(&sWh[r]);
            const __half2* sp = reinterpret_cast<const __half2*>(&gs[i]);
            const __half2* dp = reinterpret_cast<const __half2*>(&gd[i]);
            uint4 rr;
            __half2* rp = reinterpret_cast<__half2*>(&rr);
            rp[0] = __hmul2(__hmul2(sp[0], dp[0]), w2);
            rp[1] = __hmul2(__hmul2(sp[1], dp[1]), w2);
            rp[2] = __hmul2(__hmul2(sp[2], dp[2]), w2);
            rp[3] = __hmul2(__hmul2(sp[3], dp[3]), w2);
            *reinterpret_cast<uint4*>(&As_[bb*(128*40) + r*40 + q*8]) = rr;
        }
    };

    for (int uu = 0; uu < EDGE_NU; uu++) {
        int u = blockIdx.x * EDGE_NU + uu;
        if (u >= 2 * nblk) break;
        const int pol = (u >= nblk) ? 1 : 0;
        const int blk = u - pol * nblk;
        const int e0  = blk * 128;
        const int* srcA = pol ? nsrc : psrc;
        const int* dstA = pol ? ndst : pdst;
        const float* wA = pol ? nw   : pw;
        float* op = out + (pol ? (size_t)E : 0);

        // pair loads its own 32 edges' metadata
        if (ptid < 32) {
            int r = pm*32 + ptid;
            int e = e0 + r;
            float wv = (e < E) ? wA[e] : 0.f;
            if (e < E) { sSrc[r] = srcA[e]; sDst[r] = dstA[e]; }
            else       { sSrc[r] = 0;       sDst[r] = 0; }
            sWh[r] = pack_h2(wv, wv);
        }
        bar_pair(bar);

        float acc[2][8][4] = {};

        ldA(0);
        stA(0);
        bar_pair(bar);

        for (int t = 0; t < 8; t++) {
            int cur = t & 1;
            uint32_t curA = cur * (128*40*2);
            if (t < 7) ldA(t + 1);
            #pragma unroll
            for (int ks = 0; ks < 2; ks++) {
                uint32_t kb = t*64 + ks*32;
                uint32_t a[2][4];
                ldsm_x4(a[0], aAddr[0] + curA + ks*32);
                ldsm_x4(a[1], aAddr[1] + curA + ks*32);
                #pragma unroll
                for (int pr = 0; pr < 4; pr++) {
                    uint32_t b[4];
                    ldsm_x4(b, bAddr[pr] + kb);
                    #pragma unroll
                    for (int mt = 0; mt < 2; mt++) {
                        mma_f16(acc[mt][pr*2    ], a[mt], b);
                        mma_f16(acc[mt][pr*2 + 1], a[mt], b + 2);
                    }
                }
            }
            if (t < 7) stA((t + 1) & 1);
            bar_pair(bar);
        }

        // epilogue: leaky(acc + bp1) . Wp2, pair-local
        #pragma unroll
        for (int mt = 0; mt < 2; mt++) {
            float p0 = 0.f, p1 = 0.f;
            #pragma unroll
            for (int nt = 0; nt < 8; nt++) {
                int col = wn * 64 + nt * 8 + tig * 2;
                float bb0 = sBp1[col], bb1 = sBp1[col+1];
                float w0  = sWp2[col], w1  = sWp2[col+1];
                float y;
                y = acc[mt][nt][0] + bb0; y = (y > 0.f) ? y : 0.2f*y; p0 += y * w0;
                y = acc[mt][nt][1] + bb1; y = (y > 0.f) ? y : 0.2f*y; p0 += y * w1;
                y = acc[mt][nt][2] + bb0; y = (y > 0.f) ? y : 0.2f*y; p1 += y * w0;
                y = acc[mt][nt][3] + bb1; y = (y > 0.f) ? y : 0.2f*y; p1 += y * w1;
            }
            p0 += __shfl_xor_sync(0xffffffffu, p0, 1);
            p0 += __shfl_xor_sync(0xffffffffu, p0, 2);
            p1 += __shfl_xor_sync(0xffffffffu, p1, 1);
            p1 += __shfl_xor_sync(0xffffffffu, p1, 2);
            if (tig == 0) {
                int r0 = pm*32 + mt*16 + grp;
                sred[r0    ][wn] = p0;
                sred[r0 + 8][wn] = p1;
            }
        }
        bar_pair(bar);

        // warp wn==0 of the pair writes the pair's 32 outputs
        if (wn == 0) {
            int r = pm*32 + lane;
            int e = e0 + r;
            if (e < E) op[e] = sred[r][0] + sred[r][1] + bp2v;
        }
        bar_pair(bar);
    }
}

// ---------------- host orchestration ----------------
extern "C" void kernel_launch(void* const* d_in, const int* in_sizes, int n_in,
                              void* d_out, int out_size)
{
    const float* x        = (const float*)d_in[0];
    const int*   pos_src  = (const int*)  d_in[1];
    const int*   pos_dst  = (const int*)  d_in[2];
    const float* pos_w    = (const float*)d_in[3];
    const int*   neg_src  = (const int*)  d_in[4];
    const int*   neg_dst  = (const int*)  d_in[5];
    const float* neg_w    = (const float*)d_in[6];
    const float* Wi       = (const float*)d_in[7];
    const float* bi       = (const float*)d_in[8];
    const float* Wqkv     = (const float*)d_in[9];
    const float* bqkv     = (const float*)d_in[10];
    const float* Wo       = (const float*)d_in[11];
    const float* bo       = (const float*)d_in[12];
    const float* g1       = (const float*)d_in[13];
    const float* be1      = (const float*)d_in[14];
    const float* g2       = (const float*)d_in[15];
    const float* be2      = (const float*)d_in[16];
    const float* W1       = (const float*)d_in[17];
    const float* b1       = (const float*)d_in[18];
    const float* W2       = (const float*)d_in[19];
    const float* b2       = (const float*)d_in[20];
    const float* Wp1      = (const float*)d_in[21];
    const float* bp1      = (const float*)d_in[22];
    const float* Wp2      = (const float*)d_in[23];
    const float* bp2      = (const float*)d_in[24];

    const int E = in_sizes[1];   // 500000

    cudaFuncSetAttribute(sgemm_tc_kernel, cudaFuncAttributeMaxDynamicSharedMemorySize, SGEMM_SMEM);
    cudaFuncSetAttribute(attn_tc_kernel,  cudaFuncAttributeMaxDynamicSharedMemorySize, ATTN_SMEM);
    cudaFuncSetAttribute(edge_tc_kernel,  cudaFuncAttributeMaxDynamicSharedMemorySize, EDGE_SMEM);

    float* S = nullptr;
    cudaGetSymbolAddress((void**)&S, g_scratch);
    float* h0    = S + OFF_H0;
    float* h     = S + OFF_H;
    float* qkv   = S + OFF_QKV;
    float* attn  = S + OFF_ATTN;
    float* tmp   = S + OFF_TMP;
    float* ff    = S + OFF_FF;
    __half* wp1t = (__half*)(S + OFF_WP1T);
    __half* kh   = (__half*)(S + OFF_KH);
    __half* vth  = (__half*)(S + OFF_VTH);
    __half* hch  = (__half*)(S + OFF_HCH);
    float* out   = (float*)d_out;

    wp1_prep_kernel<<<128, 256>>>(Wp1, wp1t);

    sgemm_tc_kernel<<<dim3(DD/64, NN/128), 256, SGEMM_SMEM>>>(NN, DD, INF_, x, Wi, bi, h0, 0);

    for (int l = 0; l < LL; l++) {
        const float* hin = (l == 0) ? h0 : h;
        sgemm_tc_kernel<<<dim3(768/64, NN/128), 256, SGEMM_SMEM>>>(NN, 768, DD,
            hin, Wqkv + (size_t)l*DD*768, bqkv + (size_t)l*768, qkv, 0);
        kvprep_kernel<<<2048, 256>>>(qkv, kh, vth);
        attn_tc_kernel<<<dim3(NN/128, HH), 256, ATTN_SMEM>>>(qkv, kh, vth, attn);
        sgemm_tc_kernel<<<dim3(DD/64, NN/128), 256, SGEMM_SMEM>>>(NN, DD, DD,
            attn, Wo + (size_t)l*DD*DD, bo + (size_t)l*DD, tmp, 0);
        add_ln_kernel<<<NN/8, 256>>>(hin, tmp, g1 + (size_t)l*DD, be1 + (size_t)l*DD, h);
        sgemm_tc_kernel<<<dim3(FF_/64, NN/128), 256, SGEMM_SMEM>>>(NN, FF_, DD,
            h, W1 + (size_t)l*DD*FF_, b1 + (size_t)l*FF_, ff, 1);
        sgemm_tc_kernel<<<dim3(DD/64, NN/128), 256, SGEMM_SMEM>>>(NN, DD, FF_,
            ff, W2 + (size_t)l*FF_*DD, b2 + (size_t)l*DD, tmp, 0);
        if (l == LL - 1) {
            add_ln_hc_kernel<<<NN/8, 256>>>(h, tmp, g2 + (size_t)l*DD, be2 + (size_t)l*DD,
                                            h0, out + 2*(size_t)E, hch);
        } else {
            add_ln_kernel<<<NN/8, 256>>>(h, tmp, g2 + (size_t)l*DD, be2 + (size_t)l*DD, h);
        }
    }

    const int nblk = (E + 127) / 128;
    const int units = 2 * nblk;
    const int egrid = (units + EDGE_NU - 1) / EDGE_NU;
    edge_tc_kernel<<<egrid, 256, EDGE_SMEM>>>(
        hch, pos_src, pos_dst, pos_w, neg_src, neg_dst, neg_w,
        wp1t, bp1, Wp2, bp2, out, E, nblk);
}